// round 1
// baseline (speedup 1.0000x reference)
#include <cuda_runtime.h>
#include <math.h>

// Problem constants
constexpr int B_ = 4;
constexpr int S_ = 2048;
constexpr int E_ = 1024;
constexpr int H_ = 16;
constexpr int D_ = 64;

// Scratch (allocation-free rule: __device__ globals)
__device__ float g_qkv[(long long)B_ * S_ * 3 * E_];  // [B*S, 3E]
__device__ float g_y[(long long)B_ * S_ * E_];        // [B*S, E]

// ---------------------------------------------------------------------------
// Tiled fp32 GEMM: C[M,N] = A[M,K] @ B[K,N], all row-major.
// 64x64 block tile, BK=16, 256 threads, 4x4 per thread.
// M % 64 == 0, N % 64 == 0, K % 16 == 0 (true for all our shapes).
// ---------------------------------------------------------------------------
__global__ void __launch_bounds__(256) gemm64_kernel(
    const float* __restrict__ A, const float* __restrict__ Bm,
    float* __restrict__ C, int M, int N, int K) {
    __shared__ float As[16][64];   // K-major A tile
    __shared__ float Bs[16][64];

    const int tid = threadIdx.x;
    const int tx = tid & 15;
    const int ty = tid >> 4;
    const int row0 = blockIdx.y * 64;
    const int col0 = blockIdx.x * 64;

    // A load mapping: 1024 elems = 256 float4. Each thread: row am, 4 k's.
    const int am  = tid >> 2;
    const int ak4 = (tid & 3) * 4;
    // B load mapping: row bk (0..15), 4 contiguous cols.
    const int bk  = tid >> 4;
    const int bn4 = (tid & 15) * 4;

    const float* Aptr = A + (long long)(row0 + am) * K + ak4;
    const float* Bptr = Bm + (long long)bk * N + col0 + bn4;

    float acc[4][4] = {};

    for (int k0 = 0; k0 < K; k0 += 16) {
        float4 a = *(const float4*)(Aptr + k0);
        As[ak4 + 0][am] = a.x;
        As[ak4 + 1][am] = a.y;
        As[ak4 + 2][am] = a.z;
        As[ak4 + 3][am] = a.w;
        *(float4*)&Bs[bk][bn4] = *(const float4*)(Bptr + (long long)k0 * N);
        __syncthreads();

#pragma unroll
        for (int kk = 0; kk < 16; kk++) {
            float4 ra = *(const float4*)&As[kk][ty * 4];
            float4 rb = *(const float4*)&Bs[kk][tx * 4];
            float a4[4] = {ra.x, ra.y, ra.z, ra.w};
            float b4[4] = {rb.x, rb.y, rb.z, rb.w};
#pragma unroll
            for (int i = 0; i < 4; i++)
#pragma unroll
                for (int j = 0; j < 4; j++)
                    acc[i][j] += a4[i] * b4[j];
        }
        __syncthreads();
    }

#pragma unroll
    for (int i = 0; i < 4; i++) {
        float4 v = make_float4(acc[i][0], acc[i][1], acc[i][2], acc[i][3]);
        *(float4*)&C[(long long)(row0 + ty * 4 + i) * N + col0 + tx * 4] = v;
    }
}

// ---------------------------------------------------------------------------
// Causal flash attention, fp32.
// Grid: (S/64, H, B). Block: 256 threads (16x16), each thread owns a 4x4
// patch of both the score tile (64 q x 64 k) and the output tile (64 q x 64 d).
// qkv layout: [B*S, 3E] with Q at col h*64, K at E + h*64, V at 2E + h*64.
// Output y layout: [B*S, E] (already transposed back to [b, s, h*d]).
// ---------------------------------------------------------------------------
constexpr int PS_PAD = 68;  // P-tile row stride (floats) to break bank degeneracy
constexpr int ATTN_SMEM_FLOATS = 3 * 64 * 64 + 64 * PS_PAD;
constexpr int ATTN_SMEM_BYTES  = ATTN_SMEM_FLOATS * 4;  // 66560 B

__global__ void __launch_bounds__(256) attn_kernel(
    const float* __restrict__ qkv, float* __restrict__ y) {
    extern __shared__ float sm[];
    float* Qt = sm;                 // [d][r] d-major Q tile
    float* Kt = Qt + 64 * 64;       // [d][c] d-major K tile
    float* Vs = Kt + 64 * 64;       // [k][d] V tile
    float* Ps = Vs + 64 * 64;       // [r][PS_PAD] probability tile

    const int tid = threadIdx.x;
    const int tx = tid & 15;
    const int ty = tid >> 4;
    const int qt = blockIdx.x;
    const int h  = blockIdx.y;
    const int b  = blockIdx.z;
    const int q0 = qt * 64;

    const float* base = qkv + (long long)b * S_ * 3 * E_;

    // Load Q tile transposed: Qt[d][r]
    for (int i = tid; i < 64 * 16; i += 256) {
        int r  = i >> 4;
        int d4 = (i & 15) * 4;
        float4 v = *(const float4*)(base + (long long)(q0 + r) * 3 * E_ + h * 64 + d4);
        Qt[(d4 + 0) * 64 + r] = v.x;
        Qt[(d4 + 1) * 64 + r] = v.y;
        Qt[(d4 + 2) * 64 + r] = v.z;
        Qt[(d4 + 3) * 64 + r] = v.w;
    }

    float m_run[4], l_run[4];
    float acc[4][4] = {};
#pragma unroll
    for (int i = 0; i < 4; i++) { m_run[i] = -INFINITY; l_run[i] = 0.0f; }

    const int ntiles = qt + 1;
    for (int t = 0; t < ntiles; t++) {
        const int k0 = t * 64;
        // Load K (transposed) and V tiles
        for (int i = tid; i < 64 * 16; i += 256) {
            int r  = i >> 4;
            int d4 = (i & 15) * 4;
            const float* rowp = base + (long long)(k0 + r) * 3 * E_ + h * 64 + d4;
            float4 kv = *(const float4*)(rowp + E_);
            Kt[(d4 + 0) * 64 + r] = kv.x;
            Kt[(d4 + 1) * 64 + r] = kv.y;
            Kt[(d4 + 2) * 64 + r] = kv.z;
            Kt[(d4 + 3) * 64 + r] = kv.w;
            *(float4*)&Vs[r * 64 + d4] = *(const float4*)(rowp + 2 * E_);
        }
        __syncthreads();

        // S = Q K^T (own 4x4 patch)
        float s[4][4] = {};
#pragma unroll 8
        for (int kk = 0; kk < 64; kk++) {
            float4 ra = *(const float4*)&Qt[kk * 64 + ty * 4];
            float4 rb = *(const float4*)&Kt[kk * 64 + tx * 4];
            float a4[4] = {ra.x, ra.y, ra.z, ra.w};
            float b4[4] = {rb.x, rb.y, rb.z, rb.w};
#pragma unroll
            for (int i = 0; i < 4; i++)
#pragma unroll
                for (int j = 0; j < 4; j++)
                    s[i][j] += a4[i] * b4[j];
        }

        const float scale = 0.125f;  // 1/sqrt(64)
#pragma unroll
        for (int i = 0; i < 4; i++)
#pragma unroll
            for (int j = 0; j < 4; j++)
                s[i][j] *= scale;

        if (t == qt) {  // diagonal tile: causal mask
#pragma unroll
            for (int i = 0; i < 4; i++)
#pragma unroll
                for (int j = 0; j < 4; j++)
                    if (k0 + tx * 4 + j > q0 + ty * 4 + i) s[i][j] = -INFINITY;
        }

        // Online softmax per row (16 tx-threads per row group, same half-warp)
#pragma unroll
        for (int i = 0; i < 4; i++) {
            float mloc = fmaxf(fmaxf(s[i][0], s[i][1]), fmaxf(s[i][2], s[i][3]));
#pragma unroll
            for (int off = 8; off; off >>= 1)
                mloc = fmaxf(mloc, __shfl_xor_sync(0xffffffffu, mloc, off));
            float mnew = fmaxf(m_run[i], mloc);
            float corr = __expf(m_run[i] - mnew);
            l_run[i] *= corr;
#pragma unroll
            for (int j = 0; j < 4; j++) acc[i][j] *= corr;
            float p[4], rsum = 0.0f;
#pragma unroll
            for (int j = 0; j < 4; j++) {
                p[j] = __expf(s[i][j] - mnew);
                rsum += p[j];
            }
#pragma unroll
            for (int off = 8; off; off >>= 1)
                rsum += __shfl_xor_sync(0xffffffffu, rsum, off);
            l_run[i] += rsum;
            m_run[i] = mnew;
            *(float4*)&Ps[(ty * 4 + i) * PS_PAD + tx * 4] =
                make_float4(p[0], p[1], p[2], p[3]);
        }
        __syncthreads();

        // O += P @ V
#pragma unroll 8
        for (int kk = 0; kk < 64; kk++) {
            float rp[4];
#pragma unroll
            for (int i = 0; i < 4; i++) rp[i] = Ps[(ty * 4 + i) * PS_PAD + kk];
            float4 rv = *(const float4*)&Vs[kk * 64 + tx * 4];
#pragma unroll
            for (int i = 0; i < 4; i++) {
                acc[i][0] += rp[i] * rv.x;
                acc[i][1] += rp[i] * rv.y;
                acc[i][2] += rp[i] * rv.z;
                acc[i][3] += rp[i] * rv.w;
            }
        }
        __syncthreads();
    }

    // Epilogue: normalize and write to y in [b, s, h*d] layout
#pragma unroll
    for (int i = 0; i < 4; i++) {
        float inv = 1.0f / l_run[i];
        float4 o = make_float4(acc[i][0] * inv, acc[i][1] * inv,
                               acc[i][2] * inv, acc[i][3] * inv);
        *(float4*)&y[(long long)((b * S_ + q0 + ty * 4 + i)) * E_ + h * 64 + tx * 4] = o;
    }
}

// ---------------------------------------------------------------------------
extern "C" void kernel_launch(void* const* d_in, const int* in_sizes, int n_in,
                              void* d_out, int out_size) {
    const float* x      = (const float*)d_in[0];   // [B, S, E]
    const float* w_att  = (const float*)d_in[1];   // [E, 3E]
    const float* w_proj = (const float*)d_in[2];   // [E, E]
    float* out = (float*)d_out;                    // [B, S, E]

    float* qkv = nullptr;
    float* yb  = nullptr;
    cudaGetSymbolAddress((void**)&qkv, g_qkv);
    cudaGetSymbolAddress((void**)&yb, g_y);

    cudaFuncSetAttribute(attn_kernel,
                         cudaFuncAttributeMaxDynamicSharedMemorySize,
                         ATTN_SMEM_BYTES);

    const int M = B_ * S_;  // 8192

    // 1) QKV projection: [8192,1024] @ [1024,3072]
    {
        dim3 grid(3 * E_ / 64, M / 64);
        gemm64_kernel<<<grid, 256>>>(x, w_att, qkv, M, 3 * E_, E_);
    }
    // 2) Causal flash attention
    {
        dim3 grid(S_ / 64, H_, B_);
        attn_kernel<<<grid, 256, ATTN_SMEM_BYTES>>>(qkv, yb);
    }
    // 3) Output projection: [8192,1024] @ [1024,1024]
    {
        dim3 grid(E_ / 64, M / 64);
        gemm64_kernel<<<grid, 256>>>(yb, w_proj, out, M, E_, E_);
    }
}

// round 3
// speedup vs baseline: 2.9519x; 2.9519x over previous
#include <cuda_runtime.h>
#include <math.h>
#include <stdint.h>

// Problem constants
constexpr int B_ = 4;
constexpr int S_ = 2048;
constexpr int E_ = 1024;
constexpr int H_ = 16;
constexpr int D_ = 64;

// Scratch (allocation-free rule: __device__ globals)
__device__ float g_qkv[(long long)B_ * S_ * 3 * E_];      // [B*S, 3E]
__device__ float g_y[(long long)B_ * S_ * E_];            // [B*S, E]
__device__ float g_wT[(long long)3 * E_ * E_ + (long long)E_ * E_]; // w_att^T, w_proj^T

__device__ __forceinline__ float rna_tf32(float x) {
    float r; asm("cvt.rna.tf32.f32 %0, %1;" : "=f"(r) : "f"(x)); return r;
}
__device__ __forceinline__ uint32_t fau(float x) { return __float_as_uint(x); }

// m16n8k8 tf32 MMA (sm_80+ portable PTX; runs on the Blackwell tensor pipe)
__device__ __forceinline__ void mma_tf32(float d[4], const uint32_t a[4],
                                         const uint32_t b[2]) {
    asm volatile(
        "mma.sync.aligned.m16n8k8.row.col.f32.tf32.tf32.f32 "
        "{%0,%1,%2,%3}, {%4,%5,%6,%7}, {%8,%9}, {%0,%1,%2,%3};\n"
        : "+f"(d[0]), "+f"(d[1]), "+f"(d[2]), "+f"(d[3])
        : "r"(a[0]), "r"(a[1]), "r"(a[2]), "r"(a[3]), "r"(b[0]), "r"(b[1]));
}

// ===========================================================================
// Weight transpose: WT[n, k] = W[k, n]   (W is [K, N] row-major)
// ===========================================================================
__global__ void __launch_bounds__(256) transpose_kernel(
    const float* __restrict__ W, float* __restrict__ WT, int K, int N) {
    __shared__ float t[32][33];
    const int n0 = blockIdx.x * 32, k0 = blockIdx.y * 32;
    const int tx = threadIdx.x & 31, ty = threadIdx.x >> 5;  // 32x8
    for (int r = ty; r < 32; r += 8)
        t[r][tx] = W[(long long)(k0 + r) * N + n0 + tx];
    __syncthreads();
    for (int r = ty; r < 32; r += 8)
        WT[(long long)(n0 + r) * K + k0 + tx] = t[tx][r];
}

// ===========================================================================
// tf32 mma.sync GEMM: C[M,N] = A[M,K] @ BT[N,K]^T   (both operands K-major)
// 128x128x32 tile, 8 warps (2x4), warp tile 64x32 = 4x4 m16n8k8 frags.
// Register-prefetch double-buffered smem.
// ===========================================================================
constexpr int BM = 128, BN = 128, BK = 32, BKP = 36;
constexpr int GEMM_STAGE_F = 2 * 128 * BKP;              // A + B one stage
constexpr int GEMM_SMEM_BYTES = 2 * GEMM_STAGE_F * 4;    // 73728

__global__ void __launch_bounds__(256) gemm_mma_kernel(
    const float* __restrict__ A, const float* __restrict__ BT,
    float* __restrict__ C, int M, int N, int K) {
    extern __shared__ float sm[];

    const int tid  = threadIdx.x;
    const int wid  = tid >> 5;
    const int lane = tid & 31;
    const int gid  = lane >> 2;
    const int tig  = lane & 3;
    const int wm   = (wid & 1) * 64;
    const int wn   = (wid >> 1) * 32;
    const int m0   = blockIdx.y * BM;
    const int n0   = blockIdx.x * BN;

    float acc[4][4][4] = {};
    float4 ra[4], rb[4];

    // prologue: load chunk 0 -> regs -> smem stage 0
#pragma unroll
    for (int it = 0; it < 4; it++) {
        int idx = tid + it * 256;
        int row = idx >> 3;
        int kc  = (idx & 7) * 4;
        ra[it] = *(const float4*)(A  + (long long)(m0 + row) * K + kc);
        rb[it] = *(const float4*)(BT + (long long)(n0 + row) * K + kc);
    }
    {
        float* as = sm;
        float* bs = sm + 128 * BKP;
#pragma unroll
        for (int it = 0; it < 4; it++) {
            int idx = tid + it * 256;
            int row = idx >> 3;
            int kc  = (idx & 7) * 4;
            float* da = as + row * BKP + kc;
            da[0] = rna_tf32(ra[it].x); da[1] = rna_tf32(ra[it].y);
            da[2] = rna_tf32(ra[it].z); da[3] = rna_tf32(ra[it].w);
            float* db = bs + row * BKP + kc;
            db[0] = rna_tf32(rb[it].x); db[1] = rna_tf32(rb[it].y);
            db[2] = rna_tf32(rb[it].z); db[3] = rna_tf32(rb[it].w);
        }
    }
    __syncthreads();

    const int NIT = K / BK;
    for (int i = 0; i < NIT; i++) {
        const int cur = i & 1;
        // prefetch next chunk into registers (latency overlaps compute)
        if (i + 1 < NIT) {
            const int k0 = (i + 1) * BK;
#pragma unroll
            for (int it = 0; it < 4; it++) {
                int idx = tid + it * 256;
                int row = idx >> 3;
                int kc  = (idx & 7) * 4;
                ra[it] = *(const float4*)(A  + (long long)(m0 + row) * K + k0 + kc);
                rb[it] = *(const float4*)(BT + (long long)(n0 + row) * K + k0 + kc);
            }
        }
        // compute on stage cur
        const float* as = sm + cur * GEMM_STAGE_F;
        const float* bs = as + 128 * BKP;
#pragma unroll
        for (int ks = 0; ks < 4; ks++) {
            const int k = ks * 8;
            uint32_t af[4][4], bf[4][2];
#pragma unroll
            for (int mf = 0; mf < 4; mf++) {
                const float* p = as + (wm + mf * 16 + gid) * BKP + k + tig;
                af[mf][0] = fau(p[0]);
                af[mf][1] = fau(p[8 * BKP]);
                af[mf][2] = fau(p[4]);
                af[mf][3] = fau(p[8 * BKP + 4]);
            }
#pragma unroll
            for (int nf = 0; nf < 4; nf++) {
                const float* p = bs + (wn + nf * 8 + gid) * BKP + k + tig;
                bf[nf][0] = fau(p[0]);
                bf[nf][1] = fau(p[4]);
            }
#pragma unroll
            for (int mf = 0; mf < 4; mf++)
#pragma unroll
                for (int nf = 0; nf < 4; nf++)
                    mma_tf32(acc[mf][nf], af[mf], bf[nf]);
        }
        // store prefetched regs into the other stage
        if (i + 1 < NIT) {
            float* as2 = sm + (cur ^ 1) * GEMM_STAGE_F;
            float* bs2 = as2 + 128 * BKP;
#pragma unroll
            for (int it = 0; it < 4; it++) {
                int idx = tid + it * 256;
                int row = idx >> 3;
                int kc  = (idx & 7) * 4;
                float* da = as2 + row * BKP + kc;
                da[0] = rna_tf32(ra[it].x); da[1] = rna_tf32(ra[it].y);
                da[2] = rna_tf32(ra[it].z); da[3] = rna_tf32(ra[it].w);
                float* db = bs2 + row * BKP + kc;
                db[0] = rna_tf32(rb[it].x); db[1] = rna_tf32(rb[it].y);
                db[2] = rna_tf32(rb[it].z); db[3] = rna_tf32(rb[it].w);
            }
        }
        __syncthreads();
    }

    // epilogue
#pragma unroll
    for (int mf = 0; mf < 4; mf++) {
        const int r0 = m0 + wm + mf * 16 + gid;
#pragma unroll
        for (int nf = 0; nf < 4; nf++) {
            const int c = n0 + wn + nf * 8 + 2 * tig;
            *(float2*)&C[(long long)r0 * N + c] =
                make_float2(acc[mf][nf][0], acc[mf][nf][1]);
            *(float2*)&C[(long long)(r0 + 8) * N + c] =
                make_float2(acc[mf][nf][2], acc[mf][nf][3]);
        }
    }
}

// ===========================================================================
// Causal flash attention with tf32 mma.sync.
// Block 256 threads (8 warps). Q tile 128 rows; each warp owns a 16-row strip.
// K tiles of 64. Grid: (S/128, H, B).
// ===========================================================================
constexpr int AP = 68;  // smem row pad (floats)
constexpr int ATT_SMEM_F = 128 * AP + 64 * AP + 64 * AP + 128 * AP;
constexpr int ATT_SMEM_BYTES = ATT_SMEM_F * 4;  // 104448

__global__ void __launch_bounds__(256) attn_mma_kernel(
    const float* __restrict__ qkv, float* __restrict__ y) {
    extern __shared__ float sm[];
    float* Qs = sm;                   // [128][AP] tf32
    float* Ks = Qs + 128 * AP;        // [64][AP]  tf32 (row=key, col=d)
    float* Vs = Ks + 64 * AP;         // [64][AP]  tf32 (row=key, col=d)
    float* Ps = Vs + 64 * AP;         // [128][AP] tf32 (warp-private strips)

    const int tid  = threadIdx.x;
    const int w    = tid >> 5;
    const int lane = tid & 31;
    const int gid  = lane >> 2;
    const int tig  = lane & 3;
    const int qt   = blockIdx.x;
    const int h    = blockIdx.y;
    const int b    = blockIdx.z;
    const int q0   = qt * 128;

    const float* base = qkv + (long long)b * S_ * 3 * E_;

    // Load Q tile (convert to tf32)
#pragma unroll
    for (int it = 0; it < 8; it++) {
        int idx = tid + it * 256;
        int row = idx >> 4;
        int c4  = (idx & 15) * 4;
        float4 v = *(const float4*)(base + (long long)(q0 + row) * 3 * E_ + h * 64 + c4);
        float* d = Qs + row * AP + c4;
        d[0] = rna_tf32(v.x); d[1] = rna_tf32(v.y);
        d[2] = rna_tf32(v.z); d[3] = rna_tf32(v.w);
    }

    float m0r = -INFINITY, m1r = -INFINITY, l0 = 0.0f, l1 = 0.0f;
    float ofr[8][4] = {};

    const int r0g = q0 + w * 16 + gid;
    const int r1g = r0g + 8;
    const int nt = 2 * qt + 2;

    for (int t = 0; t < nt; t++) {
        const int k0 = t * 64;
        // Load K and V tiles (convert to tf32)
#pragma unroll
        for (int it = 0; it < 4; it++) {
            int idx = tid + it * 256;
            int row = idx >> 4;
            int c4  = (idx & 15) * 4;
            const float* p = base + (long long)(k0 + row) * 3 * E_ + E_ + h * 64 + c4;
            float4 kv = *(const float4*)p;
            float4 vv = *(const float4*)(p + E_);
            float* dk = Ks + row * AP + c4;
            dk[0] = rna_tf32(kv.x); dk[1] = rna_tf32(kv.y);
            dk[2] = rna_tf32(kv.z); dk[3] = rna_tf32(kv.w);
            float* dv = Vs + row * AP + c4;
            dv[0] = rna_tf32(vv.x); dv[1] = rna_tf32(vv.y);
            dv[2] = rna_tf32(vv.z); dv[3] = rna_tf32(vv.w);
        }
        __syncthreads();

        // S = Q K^T for this warp's 16-row strip
        float sfr[8][4] = {};
#pragma unroll
        for (int ks = 0; ks < 8; ks++) {
            const int d = ks * 8;
            uint32_t a[4];
            const float* qp = Qs + (w * 16 + gid) * AP + d + tig;
            a[0] = fau(qp[0]);
            a[1] = fau(qp[8 * AP]);
            a[2] = fau(qp[4]);
            a[3] = fau(qp[8 * AP + 4]);
#pragma unroll
            for (int nf = 0; nf < 8; nf++) {
                uint32_t bf[2];
                const float* kp = Ks + (nf * 8 + gid) * AP + d + tig;
                bf[0] = fau(kp[0]);
                bf[1] = fau(kp[4]);
                mma_tf32(sfr[nf], a, bf);
            }
        }

        // scale + causal mask
        const float scale = 0.125f;
        const bool domask = (k0 + 63 > q0 + w * 16);
#pragma unroll
        for (int nf = 0; nf < 8; nf++) {
            sfr[nf][0] *= scale; sfr[nf][1] *= scale;
            sfr[nf][2] *= scale; sfr[nf][3] *= scale;
            if (domask) {
                const int c0 = k0 + nf * 8 + 2 * tig;
                if (c0     > r0g) sfr[nf][0] = -INFINITY;
                if (c0 + 1 > r0g) sfr[nf][1] = -INFINITY;
                if (c0     > r1g) sfr[nf][2] = -INFINITY;
                if (c0 + 1 > r1g) sfr[nf][3] = -INFINITY;
            }
        }

        // online softmax (row reductions across the 4-lane tig group)
        float mx0 = -INFINITY, mx1 = -INFINITY;
#pragma unroll
        for (int nf = 0; nf < 8; nf++) {
            mx0 = fmaxf(mx0, fmaxf(sfr[nf][0], sfr[nf][1]));
            mx1 = fmaxf(mx1, fmaxf(sfr[nf][2], sfr[nf][3]));
        }
#pragma unroll
        for (int off = 1; off <= 2; off <<= 1) {
            mx0 = fmaxf(mx0, __shfl_xor_sync(0xffffffffu, mx0, off));
            mx1 = fmaxf(mx1, __shfl_xor_sync(0xffffffffu, mx1, off));
        }
        const float mn0 = fmaxf(m0r, mx0);
        const float mn1 = fmaxf(m1r, mx1);
        const float cr0 = __expf(m0r - mn0);
        const float cr1 = __expf(m1r - mn1);
        m0r = mn0; m1r = mn1;
        l0 *= cr0;  l1 *= cr1;
#pragma unroll
        for (int nf = 0; nf < 8; nf++) {
            ofr[nf][0] *= cr0; ofr[nf][1] *= cr0;
            ofr[nf][2] *= cr1; ofr[nf][3] *= cr1;
        }
        float rs0 = 0.0f, rs1 = 0.0f;
#pragma unroll
        for (int nf = 0; nf < 8; nf++) {
            float p0 = __expf(sfr[nf][0] - mn0);
            float p1 = __expf(sfr[nf][1] - mn0);
            float p2 = __expf(sfr[nf][2] - mn1);
            float p3 = __expf(sfr[nf][3] - mn1);
            rs0 += p0 + p1;
            rs1 += p2 + p3;
            float* pp = Ps + (w * 16 + gid) * AP + nf * 8 + 2 * tig;
            pp[0] = rna_tf32(p0);
            pp[1] = rna_tf32(p1);
            pp[8 * AP] = rna_tf32(p2);
            pp[8 * AP + 1] = rna_tf32(p3);
        }
#pragma unroll
        for (int off = 1; off <= 2; off <<= 1) {
            rs0 += __shfl_xor_sync(0xffffffffu, rs0, off);
            rs1 += __shfl_xor_sync(0xffffffffu, rs1, off);
        }
        l0 += rs0; l1 += rs1;
        __syncwarp();

        // O += P @ V
#pragma unroll
        for (int ks = 0; ks < 8; ks++) {
            const int kk = ks * 8;
            uint32_t a[4];
            const float* pp = Ps + (w * 16 + gid) * AP + kk + tig;
            a[0] = fau(pp[0]);
            a[1] = fau(pp[8 * AP]);
            a[2] = fau(pp[4]);
            a[3] = fau(pp[8 * AP + 4]);
#pragma unroll
            for (int nf = 0; nf < 8; nf++) {
                uint32_t bf[2];
                const float* vp = Vs + (kk + tig) * AP + nf * 8 + gid;
                bf[0] = fau(vp[0]);
                bf[1] = fau(vp[4 * AP]);
                mma_tf32(ofr[nf], a, bf);
            }
        }
        __syncthreads();
    }

    // epilogue: normalize + write y[b*S + q, h*64 + d]
    const float inv0 = 1.0f / l0;
    const float inv1 = 1.0f / l1;
#pragma unroll
    for (int nf = 0; nf < 8; nf++) {
        const int c = h * 64 + nf * 8 + 2 * tig;
        *(float2*)&y[(long long)(b * S_ + r0g) * E_ + c] =
            make_float2(ofr[nf][0] * inv0, ofr[nf][1] * inv0);
        *(float2*)&y[(long long)(b * S_ + r1g) * E_ + c] =
            make_float2(ofr[nf][2] * inv1, ofr[nf][3] * inv1);
    }
}

// ===========================================================================
extern "C" void kernel_launch(void* const* d_in, const int* in_sizes, int n_in,
                              void* d_out, int out_size) {
    const float* x      = (const float*)d_in[0];   // [B, S, E]
    const float* w_att  = (const float*)d_in[1];   // [E, 3E]
    const float* w_proj = (const float*)d_in[2];   // [E, E]
    float* out = (float*)d_out;                    // [B, S, E]

    float* qkv = nullptr;
    float* yb  = nullptr;
    float* wT  = nullptr;
    cudaGetSymbolAddress((void**)&qkv, g_qkv);
    cudaGetSymbolAddress((void**)&yb, g_y);
    cudaGetSymbolAddress((void**)&wT, g_wT);
    float* wattT  = wT;                            // [3E, E]
    float* wprojT = wT + (long long)3 * E_ * E_;   // [E, E]

    cudaFuncSetAttribute(gemm_mma_kernel,
                         cudaFuncAttributeMaxDynamicSharedMemorySize,
                         GEMM_SMEM_BYTES);
    cudaFuncSetAttribute(attn_mma_kernel,
                         cudaFuncAttributeMaxDynamicSharedMemorySize,
                         ATT_SMEM_BYTES);

    const int M = B_ * S_;  // 8192

    // 0) Transpose weights to [N, K] K-major
    {
        dim3 g1(3 * E_ / 32, E_ / 32);
        transpose_kernel<<<g1, 256>>>(w_att, wattT, E_, 3 * E_);
        dim3 g2(E_ / 32, E_ / 32);
        transpose_kernel<<<g2, 256>>>(w_proj, wprojT, E_, E_);
    }
    // 1) QKV projection: [8192,1024] @ [1024,3072]
    {
        dim3 grid(3 * E_ / BN, M / BM);
        gemm_mma_kernel<<<grid, 256, GEMM_SMEM_BYTES>>>(x, wattT, qkv, M, 3 * E_, E_);
    }
    // 2) Causal flash attention (tf32 mma)
    {
        dim3 grid(S_ / 128, H_, B_);
        attn_mma_kernel<<<grid, 256, ATT_SMEM_BYTES>>>(qkv, yb);
    }
    // 3) Output projection: [8192,1024] @ [1024,1024]
    {
        dim3 grid(E_ / BN, M / BM);
        gemm_mma_kernel<<<grid, 256, GEMM_SMEM_BYTES>>>(yb, wprojT, out, M, E_, E_);
    }
}

// round 4
// speedup vs baseline: 3.9703x; 1.3450x over previous
#include <cuda_runtime.h>
#include <math.h>
#include <stdint.h>

// Problem constants
constexpr int B_ = 4;
constexpr int S_ = 2048;
constexpr int E_ = 1024;
constexpr int H_ = 16;
constexpr int D_ = 64;

// Scratch (allocation-free rule: __device__ globals)
__device__ float g_qkv[(long long)B_ * S_ * 3 * E_];      // [B*S, 3E] (tf32-rounded)
__device__ float g_y[(long long)B_ * S_ * E_];            // [B*S, E]  (tf32-rounded)
__device__ float g_wT[(long long)3 * E_ * E_ + (long long)E_ * E_]; // rounded W^T
__device__ float g_xr[(long long)B_ * S_ * E_];           // tf32-rounded x

__device__ __forceinline__ float rna_tf32(float x) {
    float r; asm("cvt.rna.tf32.f32 %0, %1;" : "=f"(r) : "f"(x)); return r;
}
__device__ __forceinline__ uint32_t fau(float x) { return __float_as_uint(x); }
__device__ __forceinline__ uint32_t smem_u32(const void* p) {
    uint32_t a;
    asm("{ .reg .u64 t; cvta.to.shared.u64 t, %1; cvt.u32.u64 %0, t; }"
        : "=r"(a) : "l"(p));
    return a;
}

#define CP_ASYNC16(dst, src) \
    asm volatile("cp.async.cg.shared.global [%0], [%1], 16;" \
        :: "r"(dst), "l"(src))
#define CP_COMMIT() asm volatile("cp.async.commit_group;" ::: "memory")
#define CP_WAIT0()  asm volatile("cp.async.wait_group 0;" ::: "memory")
#define CP_WAIT1()  asm volatile("cp.async.wait_group 1;" ::: "memory")

// m16n8k8 tf32 MMA (sm_80+ portable; Blackwell tensor pipe)
__device__ __forceinline__ void mma_tf32(float d[4], const uint32_t a[4],
                                         const uint32_t b[2]) {
    asm volatile(
        "mma.sync.aligned.m16n8k8.row.col.f32.tf32.tf32.f32 "
        "{%0,%1,%2,%3}, {%4,%5,%6,%7}, {%8,%9}, {%0,%1,%2,%3};\n"
        : "+f"(d[0]), "+f"(d[1]), "+f"(d[2]), "+f"(d[3])
        : "r"(a[0]), "r"(a[1]), "r"(a[2]), "r"(a[3]), "r"(b[0]), "r"(b[1]));
}

// ===========================================================================
// x pre-round: xr = rna_tf32(x)
// ===========================================================================
__global__ void __launch_bounds__(256) round_kernel(
    const float* __restrict__ X, float* __restrict__ XR, long long n4) {
    long long i = blockIdx.x * 256 + threadIdx.x;
    long long stride = (long long)gridDim.x * 256;
    for (; i < n4; i += stride) {
        float4 v = ((const float4*)X)[i];
        v.x = rna_tf32(v.x); v.y = rna_tf32(v.y);
        v.z = rna_tf32(v.z); v.w = rna_tf32(v.w);
        ((float4*)XR)[i] = v;
    }
}

// ===========================================================================
// Weight transpose + tf32 round: WT[n, k] = rna(W[k, n])
// ===========================================================================
__global__ void __launch_bounds__(256) transpose_kernel(
    const float* __restrict__ W, float* __restrict__ WT, int K, int N) {
    __shared__ float t[32][33];
    const int n0 = blockIdx.x * 32, k0 = blockIdx.y * 32;
    const int tx = threadIdx.x & 31, ty = threadIdx.x >> 5;
    for (int r = ty; r < 32; r += 8)
        t[r][tx] = W[(long long)(k0 + r) * N + n0 + tx];
    __syncthreads();
    for (int r = ty; r < 32; r += 8)
        WT[(long long)(n0 + r) * K + k0 + tx] = rna_tf32(t[tx][r]);
}

// ===========================================================================
// tf32 mma.sync GEMM with 3-stage cp.async pipeline.
// C[M,N] = A[M,K] @ BT[N,K]^T (both operands K-major, PRE-ROUNDED to tf32).
// 128x128x32 tile, 8 warps (2x4), warp tile 64x32. XOR-swizzled smem (no pad).
// ===========================================================================
constexpr int BM = 128, BN = 128, BK = 32;
constexpr int GSTAGE_F = 2 * 128 * 32;                   // A + B, floats
constexpr int GEMM_SMEM_BYTES = 3 * GSTAGE_F * 4;        // 98304

__device__ __forceinline__ void gemm_issue(
    const float* __restrict__ A, const float* __restrict__ BT,
    uint32_t sbase, int stage, int m0, int n0, int k0, int K, int tid) {
    uint32_t st = sbase + stage * (GSTAGE_F * 4);
#pragma unroll
    for (int it = 0; it < 4; it++) {
        int idx = tid + it * 256;
        int row = idx >> 3;
        int c4  = idx & 7;
        uint32_t off = (uint32_t)(row * 8 + (c4 ^ (row & 7))) * 16;
        CP_ASYNC16(st + off, A + (long long)(m0 + row) * K + k0 + c4 * 4);
        CP_ASYNC16(st + 16384 + off, BT + (long long)(n0 + row) * K + k0 + c4 * 4);
    }
    CP_COMMIT();
}

__global__ void __launch_bounds__(256, 2) gemm_mma_kernel(
    const float* __restrict__ A, const float* __restrict__ BT,
    float* __restrict__ C, int M, int N, int K, int roundC) {
    extern __shared__ float sm[];
    const uint32_t sbase = smem_u32(sm);

    const int tid  = threadIdx.x;
    const int wid  = tid >> 5;
    const int lane = tid & 31;
    const int gid  = lane >> 2;
    const int tig  = lane & 3;
    const int wm   = (wid & 1) * 64;
    const int wn   = (wid >> 1) * 32;
    const int m0   = blockIdx.y * BM;
    const int n0   = blockIdx.x * BN;

    float acc[4][4][4] = {};

    const int NIT = K / BK;
    gemm_issue(A, BT, sbase, 0, m0, n0, 0, K, tid);
    gemm_issue(A, BT, sbase, 1, m0, n0, BK, K, tid);

    for (int i = 0; i < NIT; i++) {
        if (i + 1 < NIT) { CP_WAIT1(); } else { CP_WAIT0(); }
        __syncthreads();
        if (i + 2 < NIT)
            gemm_issue(A, BT, sbase, (i + 2) % 3, m0, n0, (i + 2) * BK, K, tid);

        const float* as = sm + (i % 3) * GSTAGE_F;
        const float* bs = as + 128 * 32;
#pragma unroll
        for (int ks = 0; ks < 4; ks++) {
            uint32_t af[4][4], bf[4][2];
#pragma unroll
            for (int mf = 0; mf < 4; mf++) {
                const int r = wm + mf * 16 + gid;           // r&7 == gid
                const float* p = as + r * 32 + tig;
                const int x0 = ((2 * ks) ^ gid) * 4;
                const int x1 = ((2 * ks + 1) ^ gid) * 4;
                af[mf][0] = fau(p[x0]);
                af[mf][1] = fau(p[256 + x0]);
                af[mf][2] = fau(p[x1]);
                af[mf][3] = fau(p[256 + x1]);
            }
#pragma unroll
            for (int nf = 0; nf < 4; nf++) {
                const int r = wn + nf * 8 + gid;            // r&7 == gid
                const float* p = bs + r * 32 + tig;
                bf[nf][0] = fau(p[((2 * ks) ^ gid) * 4]);
                bf[nf][1] = fau(p[((2 * ks + 1) ^ gid) * 4]);
            }
#pragma unroll
            for (int mf = 0; mf < 4; mf++)
#pragma unroll
                for (int nf = 0; nf < 4; nf++)
                    mma_tf32(acc[mf][nf], af[mf], bf[nf]);
        }
        __syncthreads();
    }

    // epilogue (optionally tf32-rounded for downstream consumers)
#pragma unroll
    for (int mf = 0; mf < 4; mf++) {
        const int r0 = m0 + wm + mf * 16 + gid;
#pragma unroll
        for (int nf = 0; nf < 4; nf++) {
            const int c = n0 + wn + nf * 8 + 2 * tig;
            float v0 = acc[mf][nf][0], v1 = acc[mf][nf][1];
            float v2 = acc[mf][nf][2], v3 = acc[mf][nf][3];
            if (roundC) {
                v0 = rna_tf32(v0); v1 = rna_tf32(v1);
                v2 = rna_tf32(v2); v3 = rna_tf32(v3);
            }
            *(float2*)&C[(long long)r0 * N + c] = make_float2(v0, v1);
            *(float2*)&C[(long long)(r0 + 8) * N + c] = make_float2(v2, v3);
        }
    }
}

// ===========================================================================
// Causal flash attention, tf32 mma.sync, cp.async double-buffered K/V,
// shfl-based P (C-frag -> A-frag) conversion (no P smem tile).
// Block 256 (8 warps), Q tile 128 rows, K tiles of 64. Grid (S/128, H, B).
// qkv is already tf32-rounded. y written tf32-rounded.
// ===========================================================================
constexpr int AP = 68;  // padded row stride (floats)
constexpr int ATT_Q_F  = 128 * AP;
constexpr int ATT_KV_F = 2 * 64 * AP;    // K + V one stage
constexpr int ATT_SMEM_F = ATT_Q_F + 2 * ATT_KV_F;
constexpr int ATT_SMEM_BYTES = ATT_SMEM_F * 4;   // 104448

__device__ __forceinline__ void attn_issue_kv(
    const float* __restrict__ base, uint32_t sbase, int stage,
    int k0, int h, int tid) {
    uint32_t kst = sbase + (ATT_Q_F + stage * ATT_KV_F) * 4;
    uint32_t vst = kst + 64 * AP * 4;
#pragma unroll
    for (int it = 0; it < 4; it++) {
        int idx = tid + it * 256;
        int row = idx >> 4;
        int c4  = idx & 15;
        const float* p = base + (long long)(k0 + row) * 3 * E_ + E_ + h * 64 + c4 * 4;
        uint32_t off = (uint32_t)row * (AP * 4) + c4 * 16;
        CP_ASYNC16(kst + off, p);
        CP_ASYNC16(vst + off, p + E_);
    }
    CP_COMMIT();
}

__global__ void __launch_bounds__(256, 2) attn_mma_kernel(
    const float* __restrict__ qkv, float* __restrict__ y) {
    extern __shared__ float sm[];
    float* Qs = sm;                                  // [128][AP]
    const uint32_t sbase = smem_u32(sm);

    const int tid  = threadIdx.x;
    const int w    = tid >> 5;
    const int lane = tid & 31;
    const int gid  = lane >> 2;
    const int tig  = lane & 3;
    const int qt   = blockIdx.x;
    const int h    = blockIdx.y;
    const int b    = blockIdx.z;
    const int q0   = qt * 128;

    const float* base = qkv + (long long)b * S_ * 3 * E_;
    const int nt = 2 * qt + 2;

    // Prologue: start K/V pipeline, then load Q (plain; values pre-rounded)
    attn_issue_kv(base, sbase, 0, 0, h, tid);
    if (nt > 1) attn_issue_kv(base, sbase, 1, 64, h, tid);

#pragma unroll
    for (int it = 0; it < 8; it++) {
        int idx = tid + it * 256;
        int row = idx >> 4;
        int c4  = (idx & 15) * 4;
        float4 v = *(const float4*)(base + (long long)(q0 + row) * 3 * E_ + h * 64 + c4);
        *(float4*)&Qs[row * AP + c4] = v;
    }

    float m0r = -INFINITY, m1r = -INFINITY, l0 = 0.0f, l1 = 0.0f;
    float ofr[8][4] = {};

    const int r0g = q0 + w * 16 + gid;
    const int r1g = r0g + 8;
    const int shsrc = (gid << 2) + (tig >> 1);
    const bool odd = (tig & 1);

    for (int t = 0; t < nt; t++) {
        const int k0 = t * 64;
        if (t + 1 < nt) { CP_WAIT1(); } else { CP_WAIT0(); }
        __syncthreads();
        const float* Ks = sm + ATT_Q_F + (t & 1) * ATT_KV_F;
        const float* Vs = Ks + 64 * AP;

        // S = Q K^T for this warp's 16-row strip
        float sfr[8][4] = {};
#pragma unroll
        for (int ks = 0; ks < 8; ks++) {
            const int d = ks * 8;
            uint32_t a[4];
            const float* qp = Qs + (w * 16 + gid) * AP + d + tig;
            a[0] = fau(qp[0]);
            a[1] = fau(qp[8 * AP]);
            a[2] = fau(qp[4]);
            a[3] = fau(qp[8 * AP + 4]);
#pragma unroll
            for (int nf = 0; nf < 8; nf++) {
                uint32_t bf[2];
                const float* kp = Ks + (nf * 8 + gid) * AP + d + tig;
                bf[0] = fau(kp[0]);
                bf[1] = fau(kp[4]);
                mma_tf32(sfr[nf], a, bf);
            }
        }

        // scale + causal mask
        const float scale = 0.125f;
        const bool domask = (k0 + 63 > q0 + w * 16);
#pragma unroll
        for (int nf = 0; nf < 8; nf++) {
            sfr[nf][0] *= scale; sfr[nf][1] *= scale;
            sfr[nf][2] *= scale; sfr[nf][3] *= scale;
            if (domask) {
                const int c0 = k0 + nf * 8 + 2 * tig;
                if (c0     > r0g) sfr[nf][0] = -INFINITY;
                if (c0 + 1 > r0g) sfr[nf][1] = -INFINITY;
                if (c0     > r1g) sfr[nf][2] = -INFINITY;
                if (c0 + 1 > r1g) sfr[nf][3] = -INFINITY;
            }
        }

        // online softmax
        float mx0 = -INFINITY, mx1 = -INFINITY;
#pragma unroll
        for (int nf = 0; nf < 8; nf++) {
            mx0 = fmaxf(mx0, fmaxf(sfr[nf][0], sfr[nf][1]));
            mx1 = fmaxf(mx1, fmaxf(sfr[nf][2], sfr[nf][3]));
        }
#pragma unroll
        for (int off = 1; off <= 2; off <<= 1) {
            mx0 = fmaxf(mx0, __shfl_xor_sync(0xffffffffu, mx0, off));
            mx1 = fmaxf(mx1, __shfl_xor_sync(0xffffffffu, mx1, off));
        }
        const float mn0 = fmaxf(m0r, mx0);
        const float mn1 = fmaxf(m1r, mx1);
        const float cr0 = __expf(m0r - mn0);
        const float cr1 = __expf(m1r - mn1);
        m0r = mn0; m1r = mn1;
        l0 *= cr0;  l1 *= cr1;
#pragma unroll
        for (int nf = 0; nf < 8; nf++) {
            ofr[nf][0] *= cr0; ofr[nf][1] *= cr0;
            ofr[nf][2] *= cr1; ofr[nf][3] *= cr1;
        }
        float rs0 = 0.0f, rs1 = 0.0f;
#pragma unroll
        for (int nf = 0; nf < 8; nf++) {
            sfr[nf][0] = rna_tf32(__expf(sfr[nf][0] - mn0));
            sfr[nf][1] = rna_tf32(__expf(sfr[nf][1] - mn0));
            sfr[nf][2] = rna_tf32(__expf(sfr[nf][2] - mn1));
            sfr[nf][3] = rna_tf32(__expf(sfr[nf][3] - mn1));
            rs0 += sfr[nf][0] + sfr[nf][1];
            rs1 += sfr[nf][2] + sfr[nf][3];
        }
#pragma unroll
        for (int off = 1; off <= 2; off <<= 1) {
            rs0 += __shfl_xor_sync(0xffffffffu, rs0, off);
            rs1 += __shfl_xor_sync(0xffffffffu, rs1, off);
        }
        l0 += rs0; l1 += rs1;

        // O += P @ V   (A-frags of P built from C-frags via shfl)
#pragma unroll
        for (int ks = 0; ks < 8; ks++) {
            const int kk = ks * 8;
            float e0 = __shfl_sync(0xffffffffu, sfr[ks][0], shsrc);
            float o0 = __shfl_sync(0xffffffffu, sfr[ks][1], shsrc);
            float e2 = __shfl_sync(0xffffffffu, sfr[ks][0], shsrc + 2);
            float o2 = __shfl_sync(0xffffffffu, sfr[ks][1], shsrc + 2);
            float e1 = __shfl_sync(0xffffffffu, sfr[ks][2], shsrc);
            float o1 = __shfl_sync(0xffffffffu, sfr[ks][3], shsrc);
            float e3 = __shfl_sync(0xffffffffu, sfr[ks][2], shsrc + 2);
            float o3 = __shfl_sync(0xffffffffu, sfr[ks][3], shsrc + 2);
            uint32_t a[4];
            a[0] = fau(odd ? o0 : e0);
            a[1] = fau(odd ? o1 : e1);
            a[2] = fau(odd ? o2 : e2);
            a[3] = fau(odd ? o3 : e3);
#pragma unroll
            for (int nf = 0; nf < 8; nf++) {
                uint32_t bf[2];
                const float* vp = Vs + (kk + tig) * AP + nf * 8 + gid;
                bf[0] = fau(vp[0]);
                bf[1] = fau(vp[4 * AP]);
                mma_tf32(ofr[nf], a, bf);
            }
        }
        __syncthreads();
        if (t + 2 < nt)
            attn_issue_kv(base, sbase, t & 1, (t + 2) * 64, h, tid);
    }

    // epilogue: normalize, round to tf32 (consumed by tf32 proj GEMM), write
    const float inv0 = 1.0f / l0;
    const float inv1 = 1.0f / l1;
#pragma unroll
    for (int nf = 0; nf < 8; nf++) {
        const int c = h * 64 + nf * 8 + 2 * tig;
        *(float2*)&y[(long long)(b * S_ + r0g) * E_ + c] =
            make_float2(rna_tf32(ofr[nf][0] * inv0), rna_tf32(ofr[nf][1] * inv0));
        *(float2*)&y[(long long)(b * S_ + r1g) * E_ + c] =
            make_float2(rna_tf32(ofr[nf][2] * inv1), rna_tf32(ofr[nf][3] * inv1));
    }
}

// ===========================================================================
extern "C" void kernel_launch(void* const* d_in, const int* in_sizes, int n_in,
                              void* d_out, int out_size) {
    const float* x      = (const float*)d_in[0];   // [B, S, E]
    const float* w_att  = (const float*)d_in[1];   // [E, 3E]
    const float* w_proj = (const float*)d_in[2];   // [E, E]
    float* out = (float*)d_out;                    // [B, S, E]

    float* qkv = nullptr; float* yb = nullptr; float* wT = nullptr; float* xr = nullptr;
    cudaGetSymbolAddress((void**)&qkv, g_qkv);
    cudaGetSymbolAddress((void**)&yb, g_y);
    cudaGetSymbolAddress((void**)&wT, g_wT);
    cudaGetSymbolAddress((void**)&xr, g_xr);
    float* wattT  = wT;                            // [3E, E]
    float* wprojT = wT + (long long)3 * E_ * E_;   // [E, E]

    cudaFuncSetAttribute(gemm_mma_kernel,
                         cudaFuncAttributeMaxDynamicSharedMemorySize,
                         GEMM_SMEM_BYTES);
    cudaFuncSetAttribute(attn_mma_kernel,
                         cudaFuncAttributeMaxDynamicSharedMemorySize,
                         ATT_SMEM_BYTES);

    const int M = B_ * S_;  // 8192

    // 0) Pre-round x; transpose+round weights
    round_kernel<<<2048, 256>>>(x, xr, (long long)M * E_ / 4);
    {
        dim3 g1(3 * E_ / 32, E_ / 32);
        transpose_kernel<<<g1, 256>>>(w_att, wattT, E_, 3 * E_);
        dim3 g2(E_ / 32, E_ / 32);
        transpose_kernel<<<g2, 256>>>(w_proj, wprojT, E_, E_);
    }
    // 1) QKV projection (writes tf32-rounded qkv)
    {
        dim3 grid(3 * E_ / BN, M / BM);
        gemm_mma_kernel<<<grid, 256, GEMM_SMEM_BYTES>>>(xr, wattT, qkv, M, 3 * E_, E_, 1);
    }
    // 2) Causal flash attention (writes tf32-rounded y)
    {
        dim3 grid(S_ / 128, H_, B_);
        attn_mma_kernel<<<grid, 256, ATT_SMEM_BYTES>>>(qkv, yb);
    }
    // 3) Output projection (full fp32 output)
    {
        dim3 grid(E_ / BN, M / BM);
        gemm_mma_kernel<<<grid, 256, GEMM_SMEM_BYTES>>>(yb, wprojT, out, M, E_, E_, 0);
    }
}

// round 5
// speedup vs baseline: 4.2521x; 1.0710x over previous
#include <cuda_runtime.h>
#include <math.h>
#include <stdint.h>

// Problem constants
constexpr int B_ = 4;
constexpr int S_ = 2048;
constexpr int E_ = 1024;
constexpr int H_ = 16;
constexpr int D_ = 64;

// Scratch (allocation-free rule: __device__ globals)
__device__ float g_qkv[(long long)B_ * S_ * 3 * E_];      // [B*S, 3E] (tf32-rounded)
__device__ float g_y[(long long)B_ * S_ * E_];            // [B*S, E]  (tf32-rounded)
__device__ float g_wT[(long long)3 * E_ * E_ + (long long)E_ * E_]; // rounded W^T
__device__ float g_xr[(long long)B_ * S_ * E_];           // tf32-rounded x

__device__ __forceinline__ float rna_tf32(float x) {
    float r; asm("cvt.rna.tf32.f32 %0, %1;" : "=f"(r) : "f"(x)); return r;
}
__device__ __forceinline__ float ex2f(float x) {
    float r; asm("ex2.approx.f32 %0, %1;" : "=f"(r) : "f"(x)); return r;
}
__device__ __forceinline__ uint32_t fau(float x) { return __float_as_uint(x); }
__device__ __forceinline__ uint32_t smem_u32(const void* p) {
    uint32_t a;
    asm("{ .reg .u64 t; cvta.to.shared.u64 t, %1; cvt.u32.u64 %0, t; }"
        : "=r"(a) : "l"(p));
    return a;
}

#define CP_ASYNC16(dst, src) \
    asm volatile("cp.async.cg.shared.global [%0], [%1], 16;" \
        :: "r"(dst), "l"(src))
#define CP_COMMIT() asm volatile("cp.async.commit_group;" ::: "memory")
#define CP_WAIT0()  asm volatile("cp.async.wait_group 0;" ::: "memory")
#define CP_WAIT1()  asm volatile("cp.async.wait_group 1;" ::: "memory")

// m16n8k8 tf32 MMA (sm_80+ portable; Blackwell tensor pipe)
__device__ __forceinline__ void mma_tf32(float d[4], const uint32_t a[4],
                                         const uint32_t b[2]) {
    asm volatile(
        "mma.sync.aligned.m16n8k8.row.col.f32.tf32.tf32.f32 "
        "{%0,%1,%2,%3}, {%4,%5,%6,%7}, {%8,%9}, {%0,%1,%2,%3};\n"
        : "+f"(d[0]), "+f"(d[1]), "+f"(d[2]), "+f"(d[3])
        : "r"(a[0]), "r"(a[1]), "r"(a[2]), "r"(a[3]), "r"(b[0]), "r"(b[1]));
}

// ===========================================================================
// x pre-round: xr = rna_tf32(x)
// ===========================================================================
__global__ void __launch_bounds__(256) round_kernel(
    const float* __restrict__ X, float* __restrict__ XR, long long n4) {
    long long i = blockIdx.x * 256 + threadIdx.x;
    long long stride = (long long)gridDim.x * 256;
    for (; i < n4; i += stride) {
        float4 v = ((const float4*)X)[i];
        v.x = rna_tf32(v.x); v.y = rna_tf32(v.y);
        v.z = rna_tf32(v.z); v.w = rna_tf32(v.w);
        ((float4*)XR)[i] = v;
    }
}

// ===========================================================================
// Weight transpose + tf32 round: WT[n, k] = rna(W[k, n])
// ===========================================================================
__global__ void __launch_bounds__(256) transpose_kernel(
    const float* __restrict__ W, float* __restrict__ WT, int K, int N) {
    __shared__ float t[32][33];
    const int n0 = blockIdx.x * 32, k0 = blockIdx.y * 32;
    const int tx = threadIdx.x & 31, ty = threadIdx.x >> 5;
    for (int r = ty; r < 32; r += 8)
        t[r][tx] = W[(long long)(k0 + r) * N + n0 + tx];
    __syncthreads();
    for (int r = ty; r < 32; r += 8)
        WT[(long long)(n0 + r) * K + k0 + tx] = rna_tf32(t[tx][r]);
}

// ===========================================================================
// tf32 mma.sync GEMM with 3-stage cp.async pipeline, ONE barrier per chunk.
// C[M,N] = A[M,K] @ BT[N,K]^T (both operands K-major, PRE-ROUNDED to tf32).
// 128x128x32 tile, 8 warps (2x4), warp tile 64x32. XOR-swizzled smem.
// ===========================================================================
constexpr int BM = 128, BN = 128, BK = 32;
constexpr int GSTAGE_F = 2 * 128 * 32;                   // A + B, floats
constexpr int GEMM_SMEM_BYTES = 3 * GSTAGE_F * 4;        // 98304

__device__ __forceinline__ void gemm_issue(
    const float* __restrict__ A, const float* __restrict__ BT,
    uint32_t sbase, int stage, int m0, int n0, int k0, int K, int tid) {
    uint32_t st = sbase + stage * (GSTAGE_F * 4);
#pragma unroll
    for (int it = 0; it < 4; it++) {
        int idx = tid + it * 256;
        int row = idx >> 3;
        int c4  = idx & 7;
        uint32_t off = (uint32_t)(row * 8 + (c4 ^ (row & 7))) * 16;
        CP_ASYNC16(st + off, A + (long long)(m0 + row) * K + k0 + c4 * 4);
        CP_ASYNC16(st + 16384 + off, BT + (long long)(n0 + row) * K + k0 + c4 * 4);
    }
    CP_COMMIT();
}

__global__ void __launch_bounds__(256, 2) gemm_mma_kernel(
    const float* __restrict__ A, const float* __restrict__ BT,
    float* __restrict__ C, int M, int N, int K, int roundC) {
    extern __shared__ float sm[];
    const uint32_t sbase = smem_u32(sm);

    const int tid  = threadIdx.x;
    const int wid  = tid >> 5;
    const int lane = tid & 31;
    const int gid  = lane >> 2;
    const int tig  = lane & 3;
    const int wm   = (wid & 1) * 64;
    const int wn   = (wid >> 1) * 32;
    const int m0   = blockIdx.y * BM;
    const int n0   = blockIdx.x * BN;

    float acc[4][4][4] = {};

    const int NIT = K / BK;
    gemm_issue(A, BT, sbase, 0, m0, n0, 0, K, tid);
    gemm_issue(A, BT, sbase, 1, m0, n0, BK, K, tid);

    for (int i = 0; i < NIT; i++) {
        if (i + 1 < NIT) { CP_WAIT1(); } else { CP_WAIT0(); }
        __syncthreads();   // single barrier: stage i data visible AND
                           // stage (i+2)%3 == (i-1)%3 readers all finished
        if (i + 2 < NIT)
            gemm_issue(A, BT, sbase, (i + 2) % 3, m0, n0, (i + 2) * BK, K, tid);

        const float* as = sm + (i % 3) * GSTAGE_F;
        const float* bs = as + 128 * 32;
#pragma unroll
        for (int ks = 0; ks < 4; ks++) {
            uint32_t af[4][4], bf[4][2];
#pragma unroll
            for (int mf = 0; mf < 4; mf++) {
                const int r = wm + mf * 16 + gid;           // r&7 == gid
                const float* p = as + r * 32 + tig;
                const int x0 = ((2 * ks) ^ gid) * 4;
                const int x1 = ((2 * ks + 1) ^ gid) * 4;
                af[mf][0] = fau(p[x0]);
                af[mf][1] = fau(p[256 + x0]);
                af[mf][2] = fau(p[x1]);
                af[mf][3] = fau(p[256 + x1]);
            }
#pragma unroll
            for (int nf = 0; nf < 4; nf++) {
                const int r = wn + nf * 8 + gid;            // r&7 == gid
                const float* p = bs + r * 32 + tig;
                bf[nf][0] = fau(p[((2 * ks) ^ gid) * 4]);
                bf[nf][1] = fau(p[((2 * ks + 1) ^ gid) * 4]);
            }
#pragma unroll
            for (int mf = 0; mf < 4; mf++)
#pragma unroll
                for (int nf = 0; nf < 4; nf++)
                    mma_tf32(acc[mf][nf], af[mf], bf[nf]);
        }
    }

    // epilogue (optionally tf32-rounded for downstream consumers)
#pragma unroll
    for (int mf = 0; mf < 4; mf++) {
        const int r0 = m0 + wm + mf * 16 + gid;
#pragma unroll
        for (int nf = 0; nf < 4; nf++) {
            const int c = n0 + wn + nf * 8 + 2 * tig;
            float v0 = acc[mf][nf][0], v1 = acc[mf][nf][1];
            float v2 = acc[mf][nf][2], v3 = acc[mf][nf][3];
            if (roundC) {
                v0 = rna_tf32(v0); v1 = rna_tf32(v1);
                v2 = rna_tf32(v2); v3 = rna_tf32(v3);
            }
            *(float2*)&C[(long long)r0 * N + c] = make_float2(v0, v1);
            *(float2*)&C[(long long)(r0 + 8) * N + c] = make_float2(v2, v3);
        }
    }
}

// ===========================================================================
// Causal flash attention, tf32 mma.sync.
// - K stored with per-8-group column permutation sigma(r) = (r>>1)+(r&1)*4
//   so S's C-frags double as P's A-frags (zero shuffles, V unpermuted).
// - cp.async double-buffered K/V; softmax in log2 domain (raw ex2).
// - Heavy q-tiles scheduled first (qt reversed vs blockIdx.x).
// Block 256 (8 warps), Q tile 128 rows, K tiles of 64. Grid (S/128, H, B).
// ===========================================================================
constexpr int AP = 68;  // padded row stride (floats)
constexpr int ATT_Q_F  = 128 * AP;
constexpr int ATT_KV_F = 2 * 64 * AP;    // K + V one stage
constexpr int ATT_SMEM_F = ATT_Q_F + 2 * ATT_KV_F;
constexpr int ATT_SMEM_BYTES = ATT_SMEM_F * 4;   // 104448

__device__ __forceinline__ void attn_issue_kv(
    const float* __restrict__ base, uint32_t sbase, int stage,
    int k0, int h, int tid) {
    uint32_t kst = sbase + (ATT_Q_F + stage * ATT_KV_F) * 4;
    uint32_t vst = kst + 64 * AP * 4;
#pragma unroll
    for (int it = 0; it < 4; it++) {
        int idx = tid + it * 256;
        int row = idx >> 4;                        // physical smem row
        int c4  = idx & 15;
        // K: physical row stores key sigma(row) within its 8-group
        int r7 = row & 7;
        int krow = (row & ~7) | ((r7 >> 1) + ((r7 & 1) << 2));
        const float* pk = base + (long long)(k0 + krow) * 3 * E_ + E_ + h * 64 + c4 * 4;
        const float* pv = base + (long long)(k0 + row) * 3 * E_ + 2 * E_ + h * 64 + c4 * 4;
        uint32_t off = (uint32_t)row * (AP * 4) + c4 * 16;
        CP_ASYNC16(kst + off, pk);
        CP_ASYNC16(vst + off, pv);
    }
    CP_COMMIT();
}

__global__ void __launch_bounds__(256, 2) attn_mma_kernel(
    const float* __restrict__ qkv, float* __restrict__ y) {
    extern __shared__ float sm[];
    float* Qs = sm;                                  // [128][AP]
    const uint32_t sbase = smem_u32(sm);

    const int tid  = threadIdx.x;
    const int w    = tid >> 5;
    const int lane = tid & 31;
    const int gid  = lane >> 2;
    const int tig  = lane & 3;
    const int qt   = gridDim.x - 1 - blockIdx.x;     // heavy tiles first
    const int h    = blockIdx.y;
    const int b    = blockIdx.z;
    const int q0   = qt * 128;

    const float* base = qkv + (long long)b * S_ * 3 * E_;
    const int nt = 2 * qt + 2;

    // Prologue: start K/V pipeline, then load Q (plain; values pre-rounded)
    attn_issue_kv(base, sbase, 0, 0, h, tid);
    if (nt > 1) attn_issue_kv(base, sbase, 1, 64, h, tid);

#pragma unroll
    for (int it = 0; it < 8; it++) {
        int idx = tid + it * 256;
        int row = idx >> 4;
        int c4  = (idx & 15) * 4;
        float4 v = *(const float4*)(base + (long long)(q0 + row) * 3 * E_ + h * 64 + c4);
        *(float4*)&Qs[row * AP + c4] = v;
    }

    float m0r = -INFINITY, m1r = -INFINITY, l0 = 0.0f, l1 = 0.0f;
    float ofr[8][4] = {};

    const int r0g = q0 + w * 16 + gid;
    const int r1g = r0g + 8;
    // scale folded with log2(e): softmax runs in log2 domain
    const float scale2 = 0.125f * 1.4426950408889634f;

    for (int t = 0; t < nt; t++) {
        const int k0 = t * 64;
        if (t + 1 < nt) { CP_WAIT1(); } else { CP_WAIT0(); }
        __syncthreads();
        const float* Ks = sm + ATT_Q_F + (t & 1) * ATT_KV_F;
        const float* Vs = Ks + 64 * AP;

        // S = Q K^T (K columns sigma-permuted in smem)
        float sfr[8][4] = {};
#pragma unroll
        for (int ks = 0; ks < 8; ks++) {
            const int d = ks * 8;
            uint32_t a[4];
            const float* qp = Qs + (w * 16 + gid) * AP + d + tig;
            a[0] = fau(qp[0]);
            a[1] = fau(qp[8 * AP]);
            a[2] = fau(qp[4]);
            a[3] = fau(qp[8 * AP + 4]);
#pragma unroll
            for (int nf = 0; nf < 8; nf++) {
                uint32_t bf[2];
                const float* kp = Ks + (nf * 8 + gid) * AP + d + tig;
                bf[0] = fau(kp[0]);
                bf[1] = fau(kp[4]);
                mma_tf32(sfr[nf], a, bf);
            }
        }

        // scale (log2 domain) + causal mask.
        // C-frag cols map to keys: val{0,2} -> key tig, val{1,3} -> key tig+4.
        const bool domask = (k0 + 63 > q0 + w * 16);
#pragma unroll
        for (int nf = 0; nf < 8; nf++) {
            sfr[nf][0] *= scale2; sfr[nf][1] *= scale2;
            sfr[nf][2] *= scale2; sfr[nf][3] *= scale2;
            if (domask) {
                const int ca = k0 + nf * 8 + tig;       // key for vals 0,2
                const int cb = ca + 4;                  // key for vals 1,3
                if (ca > r0g) sfr[nf][0] = -INFINITY;
                if (cb > r0g) sfr[nf][1] = -INFINITY;
                if (ca > r1g) sfr[nf][2] = -INFINITY;
                if (cb > r1g) sfr[nf][3] = -INFINITY;
            }
        }

        // online softmax (base-2)
        float mx0 = -INFINITY, mx1 = -INFINITY;
#pragma unroll
        for (int nf = 0; nf < 8; nf++) {
            mx0 = fmaxf(mx0, fmaxf(sfr[nf][0], sfr[nf][1]));
            mx1 = fmaxf(mx1, fmaxf(sfr[nf][2], sfr[nf][3]));
        }
#pragma unroll
        for (int off = 1; off <= 2; off <<= 1) {
            mx0 = fmaxf(mx0, __shfl_xor_sync(0xffffffffu, mx0, off));
            mx1 = fmaxf(mx1, __shfl_xor_sync(0xffffffffu, mx1, off));
        }
        const float mn0 = fmaxf(m0r, mx0);
        const float mn1 = fmaxf(m1r, mx1);
        const float cr0 = ex2f(m0r - mn0);
        const float cr1 = ex2f(m1r - mn1);
        m0r = mn0; m1r = mn1;
        l0 *= cr0;  l1 *= cr1;
#pragma unroll
        for (int nf = 0; nf < 8; nf++) {
            ofr[nf][0] *= cr0; ofr[nf][1] *= cr0;
            ofr[nf][2] *= cr1; ofr[nf][3] *= cr1;
        }
        float rs0 = 0.0f, rs1 = 0.0f;
#pragma unroll
        for (int nf = 0; nf < 8; nf++) {
            sfr[nf][0] = rna_tf32(ex2f(sfr[nf][0] - mn0));
            sfr[nf][1] = rna_tf32(ex2f(sfr[nf][1] - mn0));
            sfr[nf][2] = rna_tf32(ex2f(sfr[nf][2] - mn1));
            sfr[nf][3] = rna_tf32(ex2f(sfr[nf][3] - mn1));
            rs0 += sfr[nf][0] + sfr[nf][1];
            rs1 += sfr[nf][2] + sfr[nf][3];
        }
#pragma unroll
        for (int off = 1; off <= 2; off <<= 1) {
            rs0 += __shfl_xor_sync(0xffffffffu, rs0, off);
            rs1 += __shfl_xor_sync(0xffffffffu, rs1, off);
        }
        l0 += rs0; l1 += rs1;

        // O += P @ V : C-frags ARE A-frags under the sigma permutation.
        // a = {c0, c2, c1, c3}; V rows are unpermuted.
#pragma unroll
        for (int ks = 0; ks < 8; ks++) {
            const int kk = ks * 8;
            uint32_t a[4];
            a[0] = fau(sfr[ks][0]);
            a[1] = fau(sfr[ks][2]);
            a[2] = fau(sfr[ks][1]);
            a[3] = fau(sfr[ks][3]);
#pragma unroll
            for (int nf = 0; nf < 8; nf++) {
                uint32_t bf[2];
                const float* vp = Vs + (kk + tig) * AP + nf * 8 + gid;
                bf[0] = fau(vp[0]);
                bf[1] = fau(vp[4 * AP]);
                mma_tf32(ofr[nf], a, bf);
            }
        }
        __syncthreads();
        if (t + 2 < nt)
            attn_issue_kv(base, sbase, t & 1, (t + 2) * 64, h, tid);
    }

    // epilogue: normalize, round to tf32 (consumed by tf32 proj GEMM), write
    const float inv0 = 1.0f / l0;
    const float inv1 = 1.0f / l1;
#pragma unroll
    for (int nf = 0; nf < 8; nf++) {
        const int c = h * 64 + nf * 8 + 2 * tig;
        *(float2*)&y[(long long)(b * S_ + r0g) * E_ + c] =
            make_float2(rna_tf32(ofr[nf][0] * inv0), rna_tf32(ofr[nf][1] * inv0));
        *(float2*)&y[(long long)(b * S_ + r1g) * E_ + c] =
            make_float2(rna_tf32(ofr[nf][2] * inv1), rna_tf32(ofr[nf][3] * inv1));
    }
}

// ===========================================================================
extern "C" void kernel_launch(void* const* d_in, const int* in_sizes, int n_in,
                              void* d_out, int out_size) {
    const float* x      = (const float*)d_in[0];   // [B, S, E]
    const float* w_att  = (const float*)d_in[1];   // [E, 3E]
    const float* w_proj = (const float*)d_in[2];   // [E, E]
    float* out = (float*)d_out;                    // [B, S, E]

    float* qkv = nullptr; float* yb = nullptr; float* wT = nullptr; float* xr = nullptr;
    cudaGetSymbolAddress((void**)&qkv, g_qkv);
    cudaGetSymbolAddress((void**)&yb, g_y);
    cudaGetSymbolAddress((void**)&wT, g_wT);
    cudaGetSymbolAddress((void**)&xr, g_xr);
    float* wattT  = wT;                            // [3E, E]
    float* wprojT = wT + (long long)3 * E_ * E_;   // [E, E]

    cudaFuncSetAttribute(gemm_mma_kernel,
                         cudaFuncAttributeMaxDynamicSharedMemorySize,
                         GEMM_SMEM_BYTES);
    cudaFuncSetAttribute(attn_mma_kernel,
                         cudaFuncAttributeMaxDynamicSharedMemorySize,
                         ATT_SMEM_BYTES);

    const int M = B_ * S_;  // 8192

    // 0) Pre-round x; transpose+round weights
    round_kernel<<<2048, 256>>>(x, xr, (long long)M * E_ / 4);
    {
        dim3 g1(3 * E_ / 32, E_ / 32);
        transpose_kernel<<<g1, 256>>>(w_att, wattT, E_, 3 * E_);
        dim3 g2(E_ / 32, E_ / 32);
        transpose_kernel<<<g2, 256>>>(w_proj, wprojT, E_, E_);
    }
    // 1) QKV projection (writes tf32-rounded qkv)
    {
        dim3 grid(3 * E_ / BN, M / BM);
        gemm_mma_kernel<<<grid, 256, GEMM_SMEM_BYTES>>>(xr, wattT, qkv, M, 3 * E_, E_, 1);
    }
    // 2) Causal flash attention (writes tf32-rounded y)
    {
        dim3 grid(S_ / 128, H_, B_);
        attn_mma_kernel<<<grid, 256, ATT_SMEM_BYTES>>>(qkv, yb);
    }
    // 3) Output projection (full fp32 output)
    {
        dim3 grid(E_ / BN, M / BM);
        gemm_mma_kernel<<<grid, 256, GEMM_SMEM_BYTES>>>(yb, wprojT, out, M, E_, E_, 0);
    }
}

// round 6
// speedup vs baseline: 4.5954x; 1.0807x over previous
#include <cuda_runtime.h>
#include <math.h>
#include <stdint.h>

// Problem constants
constexpr int B_ = 4;
constexpr int S_ = 2048;
constexpr int E_ = 1024;
constexpr int H_ = 16;
constexpr int D_ = 64;

// Scratch (allocation-free rule: __device__ globals)
__device__ float g_qkv[(long long)B_ * S_ * 3 * E_];      // [B*S, 3E] (tf32-rounded)
__device__ float g_y[(long long)B_ * S_ * E_];            // [B*S, E]  (tf32-rounded)
__device__ float g_wT[(long long)3 * E_ * E_ + (long long)E_ * E_]; // rounded W^T
__device__ float g_xr[(long long)B_ * S_ * E_];           // tf32-rounded x

__device__ __forceinline__ float rna_tf32(float x) {
    float r; asm("cvt.rna.tf32.f32 %0, %1;" : "=f"(r) : "f"(x)); return r;
}
__device__ __forceinline__ float ex2f(float x) {
    float r; asm("ex2.approx.f32 %0, %1;" : "=f"(r) : "f"(x)); return r;
}
__device__ __forceinline__ uint32_t fau(float x) { return __float_as_uint(x); }
__device__ __forceinline__ uint32_t smem_u32(const void* p) {
    uint32_t a;
    asm("{ .reg .u64 t; cvta.to.shared.u64 t, %1; cvt.u32.u64 %0, t; }"
        : "=r"(a) : "l"(p));
    return a;
}

#define CP_ASYNC16(dst, src) \
    asm volatile("cp.async.cg.shared.global [%0], [%1], 16;" \
        :: "r"(dst), "l"(src))
#define CP_COMMIT() asm volatile("cp.async.commit_group;" ::: "memory")
#define CP_WAIT0()  asm volatile("cp.async.wait_group 0;" ::: "memory")
#define CP_WAIT1()  asm volatile("cp.async.wait_group 1;" ::: "memory")

// ldmatrix x4: loads four 8x8 b16 matrices; for b32 data each lane gets
// element (l%8? no: l/4, l%4) of its matrix -> exactly tf32 frag layout.
#define LDSM_X4(r0, r1, r2, r3, addr) \
    asm volatile("ldmatrix.sync.aligned.m8n8.x4.shared.b16 {%0,%1,%2,%3}, [%4];" \
        : "=r"(r0), "=r"(r1), "=r"(r2), "=r"(r3) : "r"(addr))

// m16n8k8 tf32 MMA (sm_80+ portable; Blackwell tensor pipe)
__device__ __forceinline__ void mma_tf32(float d[4], const uint32_t a[4],
                                         const uint32_t b[2]) {
    asm volatile(
        "mma.sync.aligned.m16n8k8.row.col.f32.tf32.tf32.f32 "
        "{%0,%1,%2,%3}, {%4,%5,%6,%7}, {%8,%9}, {%0,%1,%2,%3};\n"
        : "+f"(d[0]), "+f"(d[1]), "+f"(d[2]), "+f"(d[3])
        : "r"(a[0]), "r"(a[1]), "r"(a[2]), "r"(a[3]), "r"(b[0]), "r"(b[1]));
}

// ===========================================================================
// x pre-round: xr = rna_tf32(x)
// ===========================================================================
__global__ void __launch_bounds__(256) round_kernel(
    const float* __restrict__ X, float* __restrict__ XR, long long n4) {
    long long i = blockIdx.x * 256 + threadIdx.x;
    long long stride = (long long)gridDim.x * 256;
    for (; i < n4; i += stride) {
        float4 v = ((const float4*)X)[i];
        v.x = rna_tf32(v.x); v.y = rna_tf32(v.y);
        v.z = rna_tf32(v.z); v.w = rna_tf32(v.w);
        ((float4*)XR)[i] = v;
    }
}

// ===========================================================================
// Weight transpose + tf32 round: WT[n, k] = rna(W[k, n])
// ===========================================================================
__global__ void __launch_bounds__(256) transpose_kernel(
    const float* __restrict__ W, float* __restrict__ WT, int K, int N) {
    __shared__ float t[32][33];
    const int n0 = blockIdx.x * 32, k0 = blockIdx.y * 32;
    const int tx = threadIdx.x & 31, ty = threadIdx.x >> 5;
    for (int r = ty; r < 32; r += 8)
        t[r][tx] = W[(long long)(k0 + r) * N + n0 + tx];
    __syncthreads();
    for (int r = ty; r < 32; r += 8)
        WT[(long long)(n0 + r) * K + k0 + tx] = rna_tf32(t[tx][r]);
}

// ===========================================================================
// tf32 mma.sync GEMM, 3-stage cp.async pipeline, ldmatrix fragment loads.
// C[M,N] = A[M,K] @ BT[N,K]^T (operands K-major, PRE-ROUNDED to tf32).
// 128x128x32 tile, 8 warps (2x4), warp tile 64x32. XOR-swizzled smem.
// ===========================================================================
constexpr int BM = 128, BN = 128, BK = 32;
constexpr int GSTAGE_F = 2 * 128 * 32;                   // A + B, floats
constexpr int GEMM_SMEM_BYTES = 3 * GSTAGE_F * 4;        // 98304

__device__ __forceinline__ void gemm_issue(
    const float* __restrict__ A, const float* __restrict__ BT,
    uint32_t sbase, int stage, int m0, int n0, int k0, int K, int tid) {
    uint32_t st = sbase + stage * (GSTAGE_F * 4);
#pragma unroll
    for (int it = 0; it < 4; it++) {
        int idx = tid + it * 256;
        int row = idx >> 3;
        int c4  = idx & 7;
        uint32_t off = (uint32_t)(row * 8 + (c4 ^ (row & 7))) * 16;
        CP_ASYNC16(st + off, A + (long long)(m0 + row) * K + k0 + c4 * 4);
        CP_ASYNC16(st + 16384 + off, BT + (long long)(n0 + row) * K + k0 + c4 * 4);
    }
    CP_COMMIT();
}

__global__ void __launch_bounds__(256, 2) gemm_mma_kernel(
    const float* __restrict__ A, const float* __restrict__ BT,
    float* __restrict__ C, int M, int N, int K, int roundC) {
    extern __shared__ float sm[];
    const uint32_t sbase = smem_u32(sm);

    const int tid  = threadIdx.x;
    const int wid  = tid >> 5;
    const int lane = tid & 31;
    const int gid  = lane >> 2;
    const int tig  = lane & 3;
    const int wm   = (wid & 1) * 64;
    const int wn   = (wid >> 1) * 32;
    const int m0   = blockIdx.y * BM;
    const int n0   = blockIdx.x * BN;

    // ldmatrix per-lane bases (bytes). row&7 == rl for all frag rows.
    const int rl   = lane & 7;
    const uint32_t a_lane = (uint32_t)((wm + ((lane >> 3) & 1) * 8 + rl) * 32) * 4;
    const int a_cb = lane >> 4;                   // A chunk half
    const uint32_t b_lane = 16384u + (uint32_t)((wn + ((lane >> 4) & 1) * 8 + rl) * 32) * 4;
    const int b_cb = (lane >> 3) & 1;             // B chunk half

    float acc[4][4][4] = {};

    const int NIT = K / BK;
    gemm_issue(A, BT, sbase, 0, m0, n0, 0, K, tid);
    gemm_issue(A, BT, sbase, 1, m0, n0, BK, K, tid);

    for (int i = 0; i < NIT; i++) {
        if (i + 1 < NIT) { CP_WAIT1(); } else { CP_WAIT0(); }
        __syncthreads();   // stage i visible AND stage (i+2)%3 readers done
        if (i + 2 < NIT)
            gemm_issue(A, BT, sbase, (i + 2) % 3, m0, n0, (i + 2) * BK, K, tid);

        const uint32_t stb = sbase + (uint32_t)(i % 3) * (GSTAGE_F * 4);
#pragma unroll
        for (int ks = 0; ks < 4; ks++) {
            uint32_t af[4][4], bf[4][2];
#pragma unroll
            for (int mf = 0; mf < 4; mf++) {
                uint32_t ad = stb + a_lane + mf * 2048 +
                              ((uint32_t)((2 * ks + a_cb) ^ rl) << 4);
                LDSM_X4(af[mf][0], af[mf][1], af[mf][2], af[mf][3], ad);
            }
#pragma unroll
            for (int j = 0; j < 2; j++) {
                uint32_t bd = stb + b_lane + j * 2048 +
                              ((uint32_t)((2 * ks + b_cb) ^ rl) << 4);
                LDSM_X4(bf[2 * j][0], bf[2 * j][1], bf[2 * j + 1][0], bf[2 * j + 1][1], bd);
            }
#pragma unroll
            for (int mf = 0; mf < 4; mf++)
#pragma unroll
                for (int nf = 0; nf < 4; nf++)
                    mma_tf32(acc[mf][nf], af[mf], bf[nf]);
        }
    }

    // epilogue (optionally tf32-rounded for downstream consumers)
#pragma unroll
    for (int mf = 0; mf < 4; mf++) {
        const int r0 = m0 + wm + mf * 16 + gid;
#pragma unroll
        for (int nf = 0; nf < 4; nf++) {
            const int c = n0 + wn + nf * 8 + 2 * tig;
            float v0 = acc[mf][nf][0], v1 = acc[mf][nf][1];
            float v2 = acc[mf][nf][2], v3 = acc[mf][nf][3];
            if (roundC) {
                v0 = rna_tf32(v0); v1 = rna_tf32(v1);
                v2 = rna_tf32(v2); v3 = rna_tf32(v3);
            }
            *(float2*)&C[(long long)r0 * N + c] = make_float2(v0, v1);
            *(float2*)&C[(long long)(r0 + 8) * N + c] = make_float2(v2, v3);
        }
    }
}

// ===========================================================================
// Causal flash attention, tf32 mma.sync, ldmatrix Q/K fragment loads.
// - K stored with per-8-group column permutation sigma(r) = (r>>1)+(r&1)*4
//   so S's C-frags double as P's A-frags (zero shuffles, V unpermuted).
// - cp.async double-buffered K/V; softmax in log2 domain (raw ex2).
// - Heavy q-tiles scheduled first (qt reversed vs blockIdx.x).
// Block 256 (8 warps), Q tile 128 rows, K tiles of 64. Grid (S/128, H, B).
// ===========================================================================
constexpr int AP = 68;  // padded row stride (floats); 68*4=272B, 16B aligned
constexpr int ATT_Q_F  = 128 * AP;
constexpr int ATT_KV_F = 2 * 64 * AP;    // K + V one stage
constexpr int ATT_SMEM_F = ATT_Q_F + 2 * ATT_KV_F;
constexpr int ATT_SMEM_BYTES = ATT_SMEM_F * 4;   // 104448

__device__ __forceinline__ void attn_issue_kv(
    const float* __restrict__ base, uint32_t sbase, int stage,
    int k0, int h, int tid) {
    uint32_t kst = sbase + (ATT_Q_F + stage * ATT_KV_F) * 4;
    uint32_t vst = kst + 64 * AP * 4;
#pragma unroll
    for (int it = 0; it < 4; it++) {
        int idx = tid + it * 256;
        int row = idx >> 4;                        // physical smem row
        int c4  = idx & 15;
        // K: physical row stores key sigma(row) within its 8-group
        int r7 = row & 7;
        int krow = (row & ~7) | ((r7 >> 1) + ((r7 & 1) << 2));
        const float* pk = base + (long long)(k0 + krow) * 3 * E_ + E_ + h * 64 + c4 * 4;
        const float* pv = base + (long long)(k0 + row) * 3 * E_ + 2 * E_ + h * 64 + c4 * 4;
        uint32_t off = (uint32_t)row * (AP * 4) + c4 * 16;
        CP_ASYNC16(kst + off, pk);
        CP_ASYNC16(vst + off, pv);
    }
    CP_COMMIT();
}

__global__ void __launch_bounds__(256, 2) attn_mma_kernel(
    const float* __restrict__ qkv, float* __restrict__ y) {
    extern __shared__ float sm[];
    float* Qs = sm;                                  // [128][AP]
    const uint32_t sbase = smem_u32(sm);

    const int tid  = threadIdx.x;
    const int w    = tid >> 5;
    const int lane = tid & 31;
    const int gid  = lane >> 2;
    const int tig  = lane & 3;
    const int qt   = gridDim.x - 1 - blockIdx.x;     // heavy tiles first
    const int h    = blockIdx.y;
    const int b    = blockIdx.z;
    const int q0   = qt * 128;

    const float* base = qkv + (long long)b * S_ * 3 * E_;
    const int nt = 2 * qt + 2;

    // ldmatrix per-lane bases (bytes)
    const int rl = lane & 7;
    const uint32_t q_lane = (uint32_t)((w * 16 + ((lane >> 3) & 1) * 8 + rl) * AP +
                                       (lane >> 4) * 4) * 4;
    const uint32_t k_lane = (uint32_t)((((lane >> 4) & 1) * 8 + rl) * AP +
                                       ((lane >> 3) & 1) * 4) * 4;

    // Prologue: start K/V pipeline, then load Q (plain; values pre-rounded)
    attn_issue_kv(base, sbase, 0, 0, h, tid);
    if (nt > 1) attn_issue_kv(base, sbase, 1, 64, h, tid);

#pragma unroll
    for (int it = 0; it < 8; it++) {
        int idx = tid + it * 256;
        int row = idx >> 4;
        int c4  = (idx & 15) * 4;
        float4 v = *(const float4*)(base + (long long)(q0 + row) * 3 * E_ + h * 64 + c4);
        *(float4*)&Qs[row * AP + c4] = v;
    }

    float m0r = -INFINITY, m1r = -INFINITY, l0 = 0.0f, l1 = 0.0f;
    float ofr[8][4] = {};

    const int r0g = q0 + w * 16 + gid;
    const int r1g = r0g + 8;
    const float scale2 = 0.125f * 1.4426950408889634f;  // log2-domain softmax

    for (int t = 0; t < nt; t++) {
        const int k0 = t * 64;
        if (t + 1 < nt) { CP_WAIT1(); } else { CP_WAIT0(); }
        __syncthreads();
        const uint32_t ksb = sbase + (ATT_Q_F + (t & 1) * ATT_KV_F) * 4;
        const float* Vs = sm + ATT_Q_F + (t & 1) * ATT_KV_F + 64 * AP;

        // S = Q K^T (K columns sigma-permuted in smem); ldmatrix frags
        float sfr[8][4] = {};
#pragma unroll
        for (int ks = 0; ks < 8; ks++) {
            uint32_t a[4];
            LDSM_X4(a[0], a[1], a[2], a[3], sbase + q_lane + ks * 32);
            uint32_t bf[8][2];
#pragma unroll
            for (int j = 0; j < 4; j++) {
                uint32_t bd = ksb + k_lane + j * (16 * AP * 4) + ks * 32;
                LDSM_X4(bf[2 * j][0], bf[2 * j][1], bf[2 * j + 1][0], bf[2 * j + 1][1], bd);
            }
#pragma unroll
            for (int nf = 0; nf < 8; nf++)
                mma_tf32(sfr[nf], a, bf[nf]);
        }

        // scale (log2 domain) + causal mask.
        // C-frag cols map to keys: val{0,2} -> key tig, val{1,3} -> key tig+4.
        const bool domask = (k0 + 63 > q0 + w * 16);
#pragma unroll
        for (int nf = 0; nf < 8; nf++) {
            sfr[nf][0] *= scale2; sfr[nf][1] *= scale2;
            sfr[nf][2] *= scale2; sfr[nf][3] *= scale2;
            if (domask) {
                const int ca = k0 + nf * 8 + tig;       // key for vals 0,2
                const int cb = ca + 4;                  // key for vals 1,3
                if (ca > r0g) sfr[nf][0] = -INFINITY;
                if (cb > r0g) sfr[nf][1] = -INFINITY;
                if (ca > r1g) sfr[nf][2] = -INFINITY;
                if (cb > r1g) sfr[nf][3] = -INFINITY;
            }
        }

        // online softmax (base-2)
        float mx0 = -INFINITY, mx1 = -INFINITY;
#pragma unroll
        for (int nf = 0; nf < 8; nf++) {
            mx0 = fmaxf(mx0, fmaxf(sfr[nf][0], sfr[nf][1]));
            mx1 = fmaxf(mx1, fmaxf(sfr[nf][2], sfr[nf][3]));
        }
#pragma unroll
        for (int off = 1; off <= 2; off <<= 1) {
            mx0 = fmaxf(mx0, __shfl_xor_sync(0xffffffffu, mx0, off));
            mx1 = fmaxf(mx1, __shfl_xor_sync(0xffffffffu, mx1, off));
        }
        const float mn0 = fmaxf(m0r, mx0);
        const float mn1 = fmaxf(m1r, mx1);
        const float cr0 = ex2f(m0r - mn0);
        const float cr1 = ex2f(m1r - mn1);
        m0r = mn0; m1r = mn1;
        l0 *= cr0;  l1 *= cr1;
#pragma unroll
        for (int nf = 0; nf < 8; nf++) {
            ofr[nf][0] *= cr0; ofr[nf][1] *= cr0;
            ofr[nf][2] *= cr1; ofr[nf][3] *= cr1;
        }
        float rs0 = 0.0f, rs1 = 0.0f;
#pragma unroll
        for (int nf = 0; nf < 8; nf++) {
            sfr[nf][0] = rna_tf32(ex2f(sfr[nf][0] - mn0));
            sfr[nf][1] = rna_tf32(ex2f(sfr[nf][1] - mn0));
            sfr[nf][2] = rna_tf32(ex2f(sfr[nf][2] - mn1));
            sfr[nf][3] = rna_tf32(ex2f(sfr[nf][3] - mn1));
            rs0 += sfr[nf][0] + sfr[nf][1];
            rs1 += sfr[nf][2] + sfr[nf][3];
        }
#pragma unroll
        for (int off = 1; off <= 2; off <<= 1) {
            rs0 += __shfl_xor_sync(0xffffffffu, rs0, off);
            rs1 += __shfl_xor_sync(0xffffffffu, rs1, off);
        }
        l0 += rs0; l1 += rs1;

        // O += P @ V : C-frags ARE A-frags under the sigma permutation.
#pragma unroll
        for (int ks = 0; ks < 8; ks++) {
            const int kk = ks * 8;
            uint32_t a[4];
            a[0] = fau(sfr[ks][0]);
            a[1] = fau(sfr[ks][2]);
            a[2] = fau(sfr[ks][1]);
            a[3] = fau(sfr[ks][3]);
#pragma unroll
            for (int nf = 0; nf < 8; nf++) {
                uint32_t bf[2];
                const float* vp = Vs + (kk + tig) * AP + nf * 8 + gid;
                bf[0] = fau(vp[0]);
                bf[1] = fau(vp[4 * AP]);
                mma_tf32(ofr[nf], a, bf);
            }
        }
        __syncthreads();
        if (t + 2 < nt)
            attn_issue_kv(base, sbase, t & 1, (t + 2) * 64, h, tid);
    }

    // epilogue: normalize, round to tf32 (consumed by tf32 proj GEMM), write
    const float inv0 = 1.0f / l0;
    const float inv1 = 1.0f / l1;
#pragma unroll
    for (int nf = 0; nf < 8; nf++) {
        const int c = h * 64 + nf * 8 + 2 * tig;
        *(float2*)&y[(long long)(b * S_ + r0g) * E_ + c] =
            make_float2(rna_tf32(ofr[nf][0] * inv0), rna_tf32(ofr[nf][1] * inv0));
        *(float2*)&y[(long long)(b * S_ + r1g) * E_ + c] =
            make_float2(rna_tf32(ofr[nf][2] * inv1), rna_tf32(ofr[nf][3] * inv1));
    }
}

// ===========================================================================
extern "C" void kernel_launch(void* const* d_in, const int* in_sizes, int n_in,
                              void* d_out, int out_size) {
    const float* x      = (const float*)d_in[0];   // [B, S, E]
    const float* w_att  = (const float*)d_in[1];   // [E, 3E]
    const float* w_proj = (const float*)d_in[2];   // [E, E]
    float* out = (float*)d_out;                    // [B, S, E]

    float* qkv = nullptr; float* yb = nullptr; float* wT = nullptr; float* xr = nullptr;
    cudaGetSymbolAddress((void**)&qkv, g_qkv);
    cudaGetSymbolAddress((void**)&yb, g_y);
    cudaGetSymbolAddress((void**)&wT, g_wT);
    cudaGetSymbolAddress((void**)&xr, g_xr);
    float* wattT  = wT;                            // [3E, E]
    float* wprojT = wT + (long long)3 * E_ * E_;   // [E, E]

    cudaFuncSetAttribute(gemm_mma_kernel,
                         cudaFuncAttributeMaxDynamicSharedMemorySize,
                         GEMM_SMEM_BYTES);
    cudaFuncSetAttribute(attn_mma_kernel,
                         cudaFuncAttributeMaxDynamicSharedMemorySize,
                         ATT_SMEM_BYTES);

    const int M = B_ * S_;  // 8192

    // 0) Pre-round x; transpose+round weights
    round_kernel<<<2048, 256>>>(x, xr, (long long)M * E_ / 4);
    {
        dim3 g1(3 * E_ / 32, E_ / 32);
        transpose_kernel<<<g1, 256>>>(w_att, wattT, E_, 3 * E_);
        dim3 g2(E_ / 32, E_ / 32);
        transpose_kernel<<<g2, 256>>>(w_proj, wprojT, E_, E_);
    }
    // 1) QKV projection (writes tf32-rounded qkv)
    {
        dim3 grid(3 * E_ / BN, M / BM);
        gemm_mma_kernel<<<grid, 256, GEMM_SMEM_BYTES>>>(xr, wattT, qkv, M, 3 * E_, E_, 1);
    }
    // 2) Causal flash attention (writes tf32-rounded y)
    {
        dim3 grid(S_ / 128, H_, B_);
        attn_mma_kernel<<<grid, 256, ATT_SMEM_BYTES>>>(qkv, yb);
    }
    // 3) Output projection (full fp32 output)
    {
        dim3 grid(E_ / BN, M / BM);
        gemm_mma_kernel<<<grid, 256, GEMM_SMEM_BYTES>>>(yb, wprojT, out, M, E_, E_, 0);
    }
}

// round 7
// speedup vs baseline: 4.7986x; 1.0442x over previous
#include <cuda_runtime.h>
#include <math.h>
#include <stdint.h>

// Problem constants
constexpr int B_ = 4;
constexpr int S_ = 2048;
constexpr int E_ = 1024;
constexpr int H_ = 16;
constexpr int D_ = 64;
constexpr int M_ = B_ * S_;   // 8192 tokens

// Scratch (allocation-free rule: __device__ globals)
__device__ float g_qkv[(long long)B_ * S_ * 3 * E_];      // [B*S, 3E] (Q,K used; V unused)
__device__ float g_vt[(long long)E_ * M_];                // V transposed: [h*64+d][token]
__device__ float g_y[(long long)B_ * S_ * E_];            // [B*S, E]  (tf32-rounded)
__device__ float g_wT[(long long)3 * E_ * E_ + (long long)E_ * E_]; // rounded W^T
__device__ float g_xr[(long long)B_ * S_ * E_];           // tf32-rounded x

__device__ __forceinline__ float rna_tf32(float x) {
    float r; asm("cvt.rna.tf32.f32 %0, %1;" : "=f"(r) : "f"(x)); return r;
}
__device__ __forceinline__ float ex2f(float x) {
    float r; asm("ex2.approx.f32 %0, %1;" : "=f"(r) : "f"(x)); return r;
}
__device__ __forceinline__ uint32_t fau(float x) { return __float_as_uint(x); }
__device__ __forceinline__ uint32_t smem_u32(const void* p) {
    uint32_t a;
    asm("{ .reg .u64 t; cvta.to.shared.u64 t, %1; cvt.u32.u64 %0, t; }"
        : "=r"(a) : "l"(p));
    return a;
}

#define CP_ASYNC16(dst, src) \
    asm volatile("cp.async.cg.shared.global [%0], [%1], 16;" \
        :: "r"(dst), "l"(src))
#define CP_COMMIT() asm volatile("cp.async.commit_group;" ::: "memory")
#define CP_WAIT0()  asm volatile("cp.async.wait_group 0;" ::: "memory")
#define CP_WAIT1()  asm volatile("cp.async.wait_group 1;" ::: "memory")

// ldmatrix x4 on b32 data: four 8x8 b16 matrices; lane l of each matrix gets
// the (l%4)-th b32 of row (l/4) -> exactly the tf32 fragment layout.
#define LDSM_X4(r0, r1, r2, r3, addr) \
    asm volatile("ldmatrix.sync.aligned.m8n8.x4.shared.b16 {%0,%1,%2,%3}, [%4];" \
        : "=r"(r0), "=r"(r1), "=r"(r2), "=r"(r3) : "r"(addr))

// m16n8k8 tf32 MMA (sm_80+ portable; Blackwell tensor pipe)
__device__ __forceinline__ void mma_tf32(float d[4], const uint32_t a[4],
                                         const uint32_t b[2]) {
    asm volatile(
        "mma.sync.aligned.m16n8k8.row.col.f32.tf32.tf32.f32 "
        "{%0,%1,%2,%3}, {%4,%5,%6,%7}, {%8,%9}, {%0,%1,%2,%3};\n"
        : "+f"(d[0]), "+f"(d[1]), "+f"(d[2]), "+f"(d[3])
        : "r"(a[0]), "r"(a[1]), "r"(a[2]), "r"(a[3]), "r"(b[0]), "r"(b[1]));
}

// ===========================================================================
// x pre-round: xr = rna_tf32(x)
// ===========================================================================
__global__ void __launch_bounds__(256) round_kernel(
    const float* __restrict__ X, float* __restrict__ XR, long long n4) {
    long long i = blockIdx.x * 256 + threadIdx.x;
    long long stride = (long long)gridDim.x * 256;
    for (; i < n4; i += stride) {
        float4 v = ((const float4*)X)[i];
        v.x = rna_tf32(v.x); v.y = rna_tf32(v.y);
        v.z = rna_tf32(v.z); v.w = rna_tf32(v.w);
        ((float4*)XR)[i] = v;
    }
}

// ===========================================================================
// Weight transpose + tf32 round: WT[n, k] = rna(W[k, n])
// ===========================================================================
__global__ void __launch_bounds__(256) transpose_kernel(
    const float* __restrict__ W, float* __restrict__ WT, int K, int N) {
    __shared__ float t[32][33];
    const int n0 = blockIdx.x * 32, k0 = blockIdx.y * 32;
    const int tx = threadIdx.x & 31, ty = threadIdx.x >> 5;
    for (int r = ty; r < 32; r += 8)
        t[r][tx] = W[(long long)(k0 + r) * N + n0 + tx];
    __syncthreads();
    for (int r = ty; r < 32; r += 8)
        WT[(long long)(n0 + r) * K + k0 + tx] = rna_tf32(t[tx][r]);
}

// ===========================================================================
// tf32 mma.sync GEMM, 3-stage cp.async pipeline, ldmatrix fragment loads.
// C[M,N] = A[M,K] @ BT[N,K]^T (operands K-major, PRE-ROUNDED to tf32).
// 128x128x32 tile, 8 warps (2x4), warp tile 64x32. XOR-swizzled smem.
// If VT != null, columns c >= 2048 are written TRANSPOSED to VT[c-2048][row]
// (used by the QKV projection to produce Vt for the attention kernel).
// ===========================================================================
constexpr int BM = 128, BN = 128, BK = 32;
constexpr int GSTAGE_F = 2 * 128 * 32;                   // A + B, floats
constexpr int GEMM_SMEM_BYTES = 3 * GSTAGE_F * 4;        // 98304

__device__ __forceinline__ void gemm_issue(
    const float* __restrict__ A, const float* __restrict__ BT,
    uint32_t sbase, int stage, int m0, int n0, int k0, int K, int tid) {
    uint32_t st = sbase + stage * (GSTAGE_F * 4);
#pragma unroll
    for (int it = 0; it < 4; it++) {
        int idx = tid + it * 256;
        int row = idx >> 3;
        int c4  = idx & 7;
        uint32_t off = (uint32_t)(row * 8 + (c4 ^ (row & 7))) * 16;
        CP_ASYNC16(st + off, A + (long long)(m0 + row) * K + k0 + c4 * 4);
        CP_ASYNC16(st + 16384 + off, BT + (long long)(n0 + row) * K + k0 + c4 * 4);
    }
    CP_COMMIT();
}

__global__ void __launch_bounds__(256, 2) gemm_mma_kernel(
    const float* __restrict__ A, const float* __restrict__ BT,
    float* __restrict__ C, float* __restrict__ VT,
    int M, int N, int K, int roundC) {
    extern __shared__ float sm[];
    const uint32_t sbase = smem_u32(sm);

    const int tid  = threadIdx.x;
    const int wid  = tid >> 5;
    const int lane = tid & 31;
    const int gid  = lane >> 2;
    const int tig  = lane & 3;
    const int wm   = (wid & 1) * 64;
    const int wn   = (wid >> 1) * 32;
    const int m0   = blockIdx.y * BM;
    const int n0   = blockIdx.x * BN;

    // ldmatrix per-lane bases (bytes). row&7 == rl for all frag rows.
    const int rl   = lane & 7;
    const uint32_t a_lane = (uint32_t)((wm + ((lane >> 3) & 1) * 8 + rl) * 32) * 4;
    const int a_cb = lane >> 4;                   // A chunk half
    const uint32_t b_lane = 16384u + (uint32_t)((wn + ((lane >> 4) & 1) * 8 + rl) * 32) * 4;
    const int b_cb = (lane >> 3) & 1;             // B chunk half

    float acc[4][4][4] = {};

    const int NIT = K / BK;
    gemm_issue(A, BT, sbase, 0, m0, n0, 0, K, tid);
    gemm_issue(A, BT, sbase, 1, m0, n0, BK, K, tid);

    for (int i = 0; i < NIT; i++) {
        if (i + 1 < NIT) { CP_WAIT1(); } else { CP_WAIT0(); }
        __syncthreads();   // stage i visible AND stage (i+2)%3 readers done
        if (i + 2 < NIT)
            gemm_issue(A, BT, sbase, (i + 2) % 3, m0, n0, (i + 2) * BK, K, tid);

        const uint32_t stb = sbase + (uint32_t)(i % 3) * (GSTAGE_F * 4);
#pragma unroll
        for (int ks = 0; ks < 4; ks++) {
            uint32_t af[4][4], bf[4][2];
#pragma unroll
            for (int mf = 0; mf < 4; mf++) {
                uint32_t ad = stb + a_lane + mf * 2048 +
                              ((uint32_t)((2 * ks + a_cb) ^ rl) << 4);
                LDSM_X4(af[mf][0], af[mf][1], af[mf][2], af[mf][3], ad);
            }
#pragma unroll
            for (int j = 0; j < 2; j++) {
                uint32_t bd = stb + b_lane + j * 2048 +
                              ((uint32_t)((2 * ks + b_cb) ^ rl) << 4);
                LDSM_X4(bf[2 * j][0], bf[2 * j][1], bf[2 * j + 1][0], bf[2 * j + 1][1], bd);
            }
#pragma unroll
            for (int mf = 0; mf < 4; mf++)
#pragma unroll
                for (int nf = 0; nf < 4; nf++)
                    mma_tf32(acc[mf][nf], af[mf], bf[nf]);
        }
    }

    // epilogue (tf32-rounded for downstream consumers when requested).
    // V-region blocks (n0 >= 2048 with VT set) are written transposed.
    const bool isv = (VT != nullptr) && (n0 >= 2 * E_);
#pragma unroll
    for (int mf = 0; mf < 4; mf++) {
        const int r0 = m0 + wm + mf * 16 + gid;
#pragma unroll
        for (int nf = 0; nf < 4; nf++) {
            const int c = n0 + wn + nf * 8 + 2 * tig;
            float v0 = acc[mf][nf][0], v1 = acc[mf][nf][1];
            float v2 = acc[mf][nf][2], v3 = acc[mf][nf][3];
            if (roundC) {
                v0 = rna_tf32(v0); v1 = rna_tf32(v1);
                v2 = rna_tf32(v2); v3 = rna_tf32(v3);
            }
            if (isv) {
                const long long cv = c - 2 * E_;
                VT[cv * M_ + r0]           = v0;
                VT[(cv + 1) * M_ + r0]     = v1;
                VT[cv * M_ + r0 + 8]       = v2;
                VT[(cv + 1) * M_ + r0 + 8] = v3;
            } else {
                *(float2*)&C[(long long)r0 * N + c] = make_float2(v0, v1);
                *(float2*)&C[(long long)(r0 + 8) * N + c] = make_float2(v2, v3);
            }
        }
    }
}

// ===========================================================================
// Causal flash attention, tf32 mma.sync, ldmatrix for Q, K AND V fragments.
// - K stored with per-8-group column permutation sigma(r) = (r>>1)+(r&1)*4
//   so S's C-frags double as P's A-frags (zero shuffles).
// - V comes pre-transposed from the QKV GEMM (Vt[d][token]); smem tile
//   Vt[d][key] -> PV B-frags load with the same LDSM pattern as K-frags.
// - cp.async double-buffered K/V; softmax in log2 domain (raw ex2).
// - Heavy q-tiles scheduled first (qt reversed vs blockIdx.x).
// Block 256 (8 warps), Q tile 128 rows, K tiles of 64. Grid (S/128, H, B).
// ===========================================================================
constexpr int AP = 68;  // padded row stride (floats); 68*4=272B, 16B aligned
constexpr int ATT_Q_F  = 128 * AP;
constexpr int ATT_KV_F = 2 * 64 * AP;    // K + Vt one stage
constexpr int ATT_SMEM_F = ATT_Q_F + 2 * ATT_KV_F;
constexpr int ATT_SMEM_BYTES = ATT_SMEM_F * 4;   // 104448

__device__ __forceinline__ void attn_issue_kv(
    const float* __restrict__ base, const float* __restrict__ vt,
    uint32_t sbase, int stage, int k0, int h, int b, int tid) {
    uint32_t kst = sbase + (ATT_Q_F + stage * ATT_KV_F) * 4;
    uint32_t vst = kst + 64 * AP * 4;
#pragma unroll
    for (int it = 0; it < 4; it++) {
        int idx = tid + it * 256;
        int row = idx >> 4;                        // physical smem row
        int c4  = idx & 15;
        // K: physical row stores key sigma(row) within its 8-group
        int r7 = row & 7;
        int krow = (row & ~7) | ((r7 >> 1) + ((r7 & 1) << 2));
        const float* pk = base + (long long)(k0 + krow) * 3 * E_ + E_ + h * 64 + c4 * 4;
        // Vt: row = d, keys contiguous
        const float* pv = vt + (long long)(h * 64 + row) * M_ + b * S_ + k0 + c4 * 4;
        uint32_t off = (uint32_t)row * (AP * 4) + c4 * 16;
        CP_ASYNC16(kst + off, pk);
        CP_ASYNC16(vst + off, pv);
    }
    CP_COMMIT();
}

__global__ void __launch_bounds__(256, 2) attn_mma_kernel(
    const float* __restrict__ qkv, const float* __restrict__ vt,
    float* __restrict__ y) {
    extern __shared__ float sm[];
    float* Qs = sm;                                  // [128][AP]
    const uint32_t sbase = smem_u32(sm);

    const int tid  = threadIdx.x;
    const int w    = tid >> 5;
    const int lane = tid & 31;
    const int gid  = lane >> 2;
    const int tig  = lane & 3;
    const int qt   = gridDim.x - 1 - blockIdx.x;     // heavy tiles first
    const int h    = blockIdx.y;
    const int b    = blockIdx.z;
    const int q0   = qt * 128;

    const float* base = qkv + (long long)b * S_ * 3 * E_;
    const int nt = 2 * qt + 2;

    // ldmatrix per-lane bases (bytes)
    const int rl = lane & 7;
    const uint32_t q_lane = (uint32_t)((w * 16 + ((lane >> 3) & 1) * 8 + rl) * AP +
                                       (lane >> 4) * 4) * 4;
    const uint32_t kv_lane = (uint32_t)((((lane >> 4) & 1) * 8 + rl) * AP +
                                        ((lane >> 3) & 1) * 4) * 4;

    // Prologue: start K/V pipeline, then load Q (plain; values pre-rounded)
    attn_issue_kv(base, vt, sbase, 0, 0, h, b, tid);
    if (nt > 1) attn_issue_kv(base, vt, sbase, 1, 64, h, b, tid);

#pragma unroll
    for (int it = 0; it < 8; it++) {
        int idx = tid + it * 256;
        int row = idx >> 4;
        int c4  = (idx & 15) * 4;
        float4 v = *(const float4*)(base + (long long)(q0 + row) * 3 * E_ + h * 64 + c4);
        *(float4*)&Qs[row * AP + c4] = v;
    }

    float m0r = -INFINITY, m1r = -INFINITY, l0 = 0.0f, l1 = 0.0f;
    float ofr[8][4] = {};

    const int r0g = q0 + w * 16 + gid;
    const int r1g = r0g + 8;
    const float scale2 = 0.125f * 1.4426950408889634f;  // log2-domain softmax

    for (int t = 0; t < nt; t++) {
        const int k0 = t * 64;
        if (t + 1 < nt) { CP_WAIT1(); } else { CP_WAIT0(); }
        __syncthreads();
        const uint32_t ksb = sbase + (ATT_Q_F + (t & 1) * ATT_KV_F) * 4;
        const uint32_t vsb = ksb + 64 * AP * 4;

        // S = Q K^T (K columns sigma-permuted in smem); ldmatrix frags
        float sfr[8][4] = {};
#pragma unroll
        for (int ks = 0; ks < 8; ks++) {
            uint32_t a[4];
            LDSM_X4(a[0], a[1], a[2], a[3], sbase + q_lane + ks * 32);
            uint32_t bf[8][2];
#pragma unroll
            for (int j = 0; j < 4; j++) {
                uint32_t bd = ksb + kv_lane + j * (16 * AP * 4) + ks * 32;
                LDSM_X4(bf[2 * j][0], bf[2 * j][1], bf[2 * j + 1][0], bf[2 * j + 1][1], bd);
            }
#pragma unroll
            for (int nf = 0; nf < 8; nf++)
                mma_tf32(sfr[nf], a, bf[nf]);
        }

        // scale (log2 domain) + causal mask.
        // C-frag cols map to keys: val{0,2} -> key tig, val{1,3} -> key tig+4.
        const bool domask = (k0 + 63 > q0 + w * 16);
#pragma unroll
        for (int nf = 0; nf < 8; nf++) {
            sfr[nf][0] *= scale2; sfr[nf][1] *= scale2;
            sfr[nf][2] *= scale2; sfr[nf][3] *= scale2;
            if (domask) {
                const int ca = k0 + nf * 8 + tig;       // key for vals 0,2
                const int cb = ca + 4;                  // key for vals 1,3
                if (ca > r0g) sfr[nf][0] = -INFINITY;
                if (cb > r0g) sfr[nf][1] = -INFINITY;
                if (ca > r1g) sfr[nf][2] = -INFINITY;
                if (cb > r1g) sfr[nf][3] = -INFINITY;
            }
        }

        // online softmax (base-2)
        float mx0 = -INFINITY, mx1 = -INFINITY;
#pragma unroll
        for (int nf = 0; nf < 8; nf++) {
            mx0 = fmaxf(mx0, fmaxf(sfr[nf][0], sfr[nf][1]));
            mx1 = fmaxf(mx1, fmaxf(sfr[nf][2], sfr[nf][3]));
        }
#pragma unroll
        for (int off = 1; off <= 2; off <<= 1) {
            mx0 = fmaxf(mx0, __shfl_xor_sync(0xffffffffu, mx0, off));
            mx1 = fmaxf(mx1, __shfl_xor_sync(0xffffffffu, mx1, off));
        }
        const float mn0 = fmaxf(m0r, mx0);
        const float mn1 = fmaxf(m1r, mx1);
        const float cr0 = ex2f(m0r - mn0);
        const float cr1 = ex2f(m1r - mn1);
        m0r = mn0; m1r = mn1;
        l0 *= cr0;  l1 *= cr1;
#pragma unroll
        for (int nf = 0; nf < 8; nf++) {
            ofr[nf][0] *= cr0; ofr[nf][1] *= cr0;
            ofr[nf][2] *= cr1; ofr[nf][3] *= cr1;
        }
        float rs0 = 0.0f, rs1 = 0.0f;
#pragma unroll
        for (int nf = 0; nf < 8; nf++) {
            sfr[nf][0] = rna_tf32(ex2f(sfr[nf][0] - mn0));
            sfr[nf][1] = rna_tf32(ex2f(sfr[nf][1] - mn0));
            sfr[nf][2] = rna_tf32(ex2f(sfr[nf][2] - mn1));
            sfr[nf][3] = rna_tf32(ex2f(sfr[nf][3] - mn1));
            rs0 += sfr[nf][0] + sfr[nf][1];
            rs1 += sfr[nf][2] + sfr[nf][3];
        }
#pragma unroll
        for (int off = 1; off <= 2; off <<= 1) {
            rs0 += __shfl_xor_sync(0xffffffffu, rs0, off);
            rs1 += __shfl_xor_sync(0xffffffffu, rs1, off);
        }
        l0 += rs0; l1 += rs1;

        // O += P @ V : C-frags ARE A-frags under the sigma permutation;
        // V B-frags via ldmatrix from Vt[d][key] tile.
#pragma unroll
        for (int ks = 0; ks < 8; ks++) {
            uint32_t a[4];
            a[0] = fau(sfr[ks][0]);
            a[1] = fau(sfr[ks][2]);
            a[2] = fau(sfr[ks][1]);
            a[3] = fau(sfr[ks][3]);
            uint32_t bf[8][2];
#pragma unroll
            for (int j = 0; j < 4; j++) {
                uint32_t bd = vsb + kv_lane + j * (16 * AP * 4) + ks * 32;
                LDSM_X4(bf[2 * j][0], bf[2 * j][1], bf[2 * j + 1][0], bf[2 * j + 1][1], bd);
            }
#pragma unroll
            for (int nf = 0; nf < 8; nf++)
                mma_tf32(ofr[nf], a, bf[nf]);
        }
        __syncthreads();
        if (t + 2 < nt)
            attn_issue_kv(base, vt, sbase, t & 1, (t + 2) * 64, h, b, tid);
    }

    // epilogue: normalize, round to tf32 (consumed by tf32 proj GEMM), write
    const float inv0 = 1.0f / l0;
    const float inv1 = 1.0f / l1;
#pragma unroll
    for (int nf = 0; nf < 8; nf++) {
        const int c = h * 64 + nf * 8 + 2 * tig;
        *(float2*)&y[(long long)(b * S_ + r0g) * E_ + c] =
            make_float2(rna_tf32(ofr[nf][0] * inv0), rna_tf32(ofr[nf][1] * inv0));
        *(float2*)&y[(long long)(b * S_ + r1g) * E_ + c] =
            make_float2(rna_tf32(ofr[nf][2] * inv1), rna_tf32(ofr[nf][3] * inv1));
    }
}

// ===========================================================================
extern "C" void kernel_launch(void* const* d_in, const int* in_sizes, int n_in,
                              void* d_out, int out_size) {
    const float* x      = (const float*)d_in[0];   // [B, S, E]
    const float* w_att  = (const float*)d_in[1];   // [E, 3E]
    const float* w_proj = (const float*)d_in[2];   // [E, E]
    float* out = (float*)d_out;                    // [B, S, E]

    float *qkv = nullptr, *vt = nullptr, *yb = nullptr, *wT = nullptr, *xr = nullptr;
    cudaGetSymbolAddress((void**)&qkv, g_qkv);
    cudaGetSymbolAddress((void**)&vt, g_vt);
    cudaGetSymbolAddress((void**)&yb, g_y);
    cudaGetSymbolAddress((void**)&wT, g_wT);
    cudaGetSymbolAddress((void**)&xr, g_xr);
    float* wattT  = wT;                            // [3E, E]
    float* wprojT = wT + (long long)3 * E_ * E_;   // [E, E]

    cudaFuncSetAttribute(gemm_mma_kernel,
                         cudaFuncAttributeMaxDynamicSharedMemorySize,
                         GEMM_SMEM_BYTES);
    cudaFuncSetAttribute(attn_mma_kernel,
                         cudaFuncAttributeMaxDynamicSharedMemorySize,
                         ATT_SMEM_BYTES);

    // 0) Pre-round x; transpose+round weights
    round_kernel<<<2048, 256>>>(x, xr, (long long)M_ * E_ / 4);
    {
        dim3 g1(3 * E_ / 32, E_ / 32);
        transpose_kernel<<<g1, 256>>>(w_att, wattT, E_, 3 * E_);
        dim3 g2(E_ / 32, E_ / 32);
        transpose_kernel<<<g2, 256>>>(w_proj, wprojT, E_, E_);
    }
    // 1) QKV projection (Q,K -> qkv rounded; V -> vt transposed + rounded)
    {
        dim3 grid(3 * E_ / BN, M_ / BM);
        gemm_mma_kernel<<<grid, 256, GEMM_SMEM_BYTES>>>(
            xr, wattT, qkv, vt, M_, 3 * E_, E_, 1);
    }
    // 2) Causal flash attention (writes tf32-rounded y)
    {
        dim3 grid(S_ / 128, H_, B_);
        attn_mma_kernel<<<grid, 256, ATT_SMEM_BYTES>>>(qkv, vt, yb);
    }
    // 3) Output projection (full fp32 output)
    {
        dim3 grid(E_ / BN, M_ / BM);
        gemm_mma_kernel<<<grid, 256, GEMM_SMEM_BYTES>>>(
            yb, wprojT, out, nullptr, M_, E_, E_, 0);
    }
}

// round 10
// speedup vs baseline: 9.0167x; 1.8790x over previous
#include <cuda_runtime.h>
#include <cuda_fp16.h>
#include <math.h>
#include <stdint.h>

// Problem constants
constexpr int B_ = 4;
constexpr int S_ = 2048;
constexpr int E_ = 1024;
constexpr int H_ = 16;
constexpr int D_ = 64;
constexpr int M_ = B_ * S_;   // 8192 tokens

// Q pre-scale: 1/sqrt(64) * log2(e)  (softmax runs in base-2)
#define QSCALE 0.180336880f

// Scratch (allocation-free rule: __device__ globals)
__device__ __half g_xh[(long long)M_ * E_];          // x in fp16
__device__ __half g_qkvh[(long long)M_ * 2 * E_];    // Q(pre-scaled)|K, fp16
__device__ __half g_vth[(long long)E_ * M_];         // V transposed [h*64+d][token]
__device__ __half g_yh[(long long)M_ * E_];          // attention out, fp16
__device__ __half g_wTh[(long long)3 * E_ * E_ + (long long)E_ * E_]; // W^T fp16

__device__ __forceinline__ float ex2f(float x) {
    float r; asm("ex2.approx.f32 %0, %1;" : "=f"(r) : "f"(x)); return r;
}
__device__ __forceinline__ uint32_t pack_half2(float lo, float hi) {
    uint32_t r;
    asm("cvt.rn.f16x2.f32 %0, %1, %2;" : "=r"(r) : "f"(hi), "f"(lo));
    return r;
}
__device__ __forceinline__ uint32_t smem_u32(const void* p) {
    uint32_t a;
    asm("{ .reg .u64 t; cvta.to.shared.u64 t, %1; cvt.u32.u64 %0, t; }"
        : "=r"(a) : "l"(p));
    return a;
}

#define CP_ASYNC16(dst, src) \
    asm volatile("cp.async.cg.shared.global [%0], [%1], 16;" \
        :: "r"(dst), "l"(src))
#define CP_COMMIT() asm volatile("cp.async.commit_group;" ::: "memory")
#define CP_WAIT0()  asm volatile("cp.async.wait_group 0;" ::: "memory")
#define CP_WAIT1()  asm volatile("cp.async.wait_group 1;" ::: "memory")

#define LDSM_X4(r0, r1, r2, r3, addr) \
    asm volatile("ldmatrix.sync.aligned.m8n8.x4.shared.b16 {%0,%1,%2,%3}, [%4];" \
        : "=r"(r0), "=r"(r1), "=r"(r2), "=r"(r3) : "r"(addr))

// m16n8k16 fp16 MMA, fp32 accumulate (sm_80+; Blackwell tensor pipe, 2x tf32 rate)
__device__ __forceinline__ void mma_f16(float d[4], const uint32_t a[4],
                                        const uint32_t b[2]) {
    asm volatile(
        "mma.sync.aligned.m16n8k16.row.col.f32.f16.f16.f32 "
        "{%0,%1,%2,%3}, {%4,%5,%6,%7}, {%8,%9}, {%0,%1,%2,%3};\n"
        : "+f"(d[0]), "+f"(d[1]), "+f"(d[2]), "+f"(d[3])
        : "r"(a[0]), "r"(a[1]), "r"(a[2]), "r"(a[3]), "r"(b[0]), "r"(b[1]));
}

// ===========================================================================
// x -> fp16
// ===========================================================================
__global__ void __launch_bounds__(256) cvt_kernel(
    const float* __restrict__ X, __half* __restrict__ XH, long long n4) {
    long long i = blockIdx.x * 256 + threadIdx.x;
    long long stride = (long long)gridDim.x * 256;
    for (; i < n4; i += stride) {
        float4 v = ((const float4*)X)[i];
        ((uint2*)XH)[i] = make_uint2(pack_half2(v.x, v.y), pack_half2(v.z, v.w));
    }
}

// ===========================================================================
// Weight transpose + fp16: WT[n, k] = h(W[k, n])
// ===========================================================================
__global__ void __launch_bounds__(256) transpose_kernel(
    const float* __restrict__ W, __half* __restrict__ WT, int K, int N) {
    __shared__ float t[32][33];
    const int n0 = blockIdx.x * 32, k0 = blockIdx.y * 32;
    const int tx = threadIdx.x & 31, ty = threadIdx.x >> 5;
    for (int r = ty; r < 32; r += 8)
        t[r][tx] = W[(long long)(k0 + r) * N + n0 + tx];
    __syncthreads();
    for (int r = ty; r < 32; r += 8)
        WT[(long long)(n0 + r) * K + k0 + tx] = __float2half_rn(t[tx][r]);
}

// ===========================================================================
// fp16 mma.sync GEMM, 3-stage cp.async pipeline, ldmatrix fragment loads.
// C = A[M,K] @ BT[N,K]^T, fp16 operands, fp32 accum.
// 128x128x64 tile (BK=64 halves = 128B rows), 8 warps (2x4), warp 64x32.
// mode 0: fp32 out to Cf.
// mode 1 (QKV): n0<1024 -> Q (scale by QSCALE, half -> Ch);
//               n0<2048 -> K (half -> Ch); else V -> VT transposed.
// ===========================================================================
constexpr int BK = 64;                          // halves per chunk (128B)
constexpr int GSTAGE_B = 2 * 128 * 128;         // A + B tile bytes = 32768
constexpr int GEMM_SMEM_BYTES = 3 * GSTAGE_B;   // 98304

__device__ __forceinline__ void gemm_issue(
    const __half* __restrict__ A, const __half* __restrict__ BT,
    uint32_t sbase, int stage, int m0, int n0, int k0, int K, int tid) {
    uint32_t st = sbase + stage * GSTAGE_B;
#pragma unroll
    for (int it = 0; it < 4; it++) {
        int idx = tid + it * 256;          // 0..1023
        int row = idx >> 3;                // 0..127
        int c   = idx & 7;                 // 16B chunk
        uint32_t off = (uint32_t)(row * 8 + (c ^ (row & 7))) * 16;
        CP_ASYNC16(st + off, A + (long long)(m0 + row) * K + k0 + c * 8);
        CP_ASYNC16(st + 16384 + off, BT + (long long)(n0 + row) * K + k0 + c * 8);
    }
    CP_COMMIT();
}

__global__ void __launch_bounds__(256, 2) gemm_h_kernel(
    const __half* __restrict__ A, const __half* __restrict__ BT,
    float* __restrict__ Cf, __half* __restrict__ Ch, __half* __restrict__ VT,
    int M, int N, int K, int mode) {
    extern __shared__ char smc[];
    const uint32_t sbase = smem_u32(smc);

    const int tid  = threadIdx.x;
    const int wid  = tid >> 5;
    const int lane = tid & 31;
    const int gid  = lane >> 2;
    const int tig  = lane & 3;
    const int wm   = (wid & 1) * 64;
    const int wn   = (wid >> 1) * 32;
    const int m0   = blockIdx.y * 128;
    const int n0   = blockIdx.x * 128;

    const int rl = lane & 7;
    const uint32_t a_lane = (uint32_t)((wm + ((lane >> 3) & 1) * 8 + rl) * 128);
    const int a_cb = lane >> 4;
    const uint32_t b_lane = 16384u + (uint32_t)((wn + ((lane >> 4) & 1) * 8 + rl) * 128);
    const int b_cb = (lane >> 3) & 1;

    float acc[4][4][4] = {};

    const int NIT = K / BK;
    gemm_issue(A, BT, sbase, 0, m0, n0, 0, K, tid);
    gemm_issue(A, BT, sbase, 1, m0, n0, BK, K, tid);

    for (int i = 0; i < NIT; i++) {
        if (i + 1 < NIT) { CP_WAIT1(); } else { CP_WAIT0(); }
        __syncthreads();
        if (i + 2 < NIT)
            gemm_issue(A, BT, sbase, (i + 2) % 3, m0, n0, (i + 2) * BK, K, tid);

        const uint32_t stb = sbase + (uint32_t)(i % 3) * GSTAGE_B;
#pragma unroll
        for (int ks = 0; ks < 4; ks++) {       // 4 k16 steps per BK=64
            uint32_t af[4][4], bf[4][2];
#pragma unroll
            for (int mf = 0; mf < 4; mf++) {
                uint32_t ad = stb + a_lane + mf * 2048 +
                              ((uint32_t)((2 * ks + a_cb) ^ rl) << 4);
                LDSM_X4(af[mf][0], af[mf][1], af[mf][2], af[mf][3], ad);
            }
#pragma unroll
            for (int j = 0; j < 2; j++) {
                uint32_t bd = stb + b_lane + j * 2048 +
                              ((uint32_t)((2 * ks + b_cb) ^ rl) << 4);
                LDSM_X4(bf[2 * j][0], bf[2 * j][1], bf[2 * j + 1][0], bf[2 * j + 1][1], bd);
            }
#pragma unroll
            for (int mf = 0; mf < 4; mf++)
#pragma unroll
                for (int nf = 0; nf < 4; nf++)
                    mma_f16(acc[mf][nf], af[mf], bf[nf]);
        }
    }

    // epilogue
    if (mode == 0) {
#pragma unroll
        for (int mf = 0; mf < 4; mf++) {
            const int r0 = m0 + wm + mf * 16 + gid;
#pragma unroll
            for (int nf = 0; nf < 4; nf++) {
                const int c = n0 + wn + nf * 8 + 2 * tig;
                *(float2*)&Cf[(long long)r0 * N + c] =
                    make_float2(acc[mf][nf][0], acc[mf][nf][1]);
                *(float2*)&Cf[(long long)(r0 + 8) * N + c] =
                    make_float2(acc[mf][nf][2], acc[mf][nf][3]);
            }
        }
    } else {
        const int region = n0 >> 10;   // 0:Q 1:K 2:V
        if (region < 2) {
            const float s = (region == 0) ? QSCALE : 1.0f;
#pragma unroll
            for (int mf = 0; mf < 4; mf++) {
                const int r0 = m0 + wm + mf * 16 + gid;
#pragma unroll
                for (int nf = 0; nf < 4; nf++) {
                    const int c = n0 + wn + nf * 8 + 2 * tig;
                    *(uint32_t*)&Ch[(long long)r0 * 2048 + c] =
                        pack_half2(acc[mf][nf][0] * s, acc[mf][nf][1] * s);
                    *(uint32_t*)&Ch[(long long)(r0 + 8) * 2048 + c] =
                        pack_half2(acc[mf][nf][2] * s, acc[mf][nf][3] * s);
                }
            }
        } else {
#pragma unroll
            for (int mf = 0; mf < 4; mf++) {
                const int r0 = m0 + wm + mf * 16 + gid;
#pragma unroll
                for (int nf = 0; nf < 4; nf++) {
                    const long long cv = n0 + wn + nf * 8 + 2 * tig - 2048;
                    VT[cv * M_ + r0]           = __float2half_rn(acc[mf][nf][0]);
                    VT[(cv + 1) * M_ + r0]     = __float2half_rn(acc[mf][nf][1]);
                    VT[cv * M_ + r0 + 8]       = __float2half_rn(acc[mf][nf][2]);
                    VT[(cv + 1) * M_ + r0 + 8] = __float2half_rn(acc[mf][nf][3]);
                }
            }
        }
    }
}

// ===========================================================================
// Causal flash attention, fp16 m16n8k16.
// FIX vs R9: causal-mask gate is k0+63 > q0+w*16 (FIRST row of the warp
// strip, as in the passing tf32 version), not rmax — the rmax gate let
// warps 3/7 skip masking their diagonal tile.
// Q pre-scaled by QSCALE (base-2 softmax). All tiles 128B swizzled rows.
// P C-frags pack directly into A-frags. cp.async double-buffered K/V;
// heavy q-tiles first; per-warp future-tile skip; deferred l reduction.
// Block 256 (8 warps), Q 128 rows, K tiles 64. Grid (S/128, H, B).
// ===========================================================================
constexpr int ATT_Q_B  = 128 * 128;             // 16384
constexpr int ATT_KV_B = 2 * 64 * 128;          // K + V one stage = 16384
constexpr int ATT_SMEM_BYTES = ATT_Q_B + 2 * ATT_KV_B;  // 49152

__device__ __forceinline__ void attn_issue_kv(
    const __half* __restrict__ qkvh, const __half* __restrict__ vth,
    uint32_t sbase, int stage, int k0, int h, int b, int tid) {
    uint32_t kst = sbase + ATT_Q_B + stage * ATT_KV_B;
    uint32_t vst = kst + 64 * 128;
    const long long bS = (long long)b * S_;
#pragma unroll
    for (int it = 0; it < 4; it++) {
        int idx = tid + (it & 1) * 256;    // 0..511
        int row = idx >> 3;                // 0..63
        int c   = idx & 7;
        uint32_t off = (uint32_t)(row * 8 + (c ^ (row & 7))) * 16;
        if (it < 2) {
            CP_ASYNC16(kst + off,
                       qkvh + (bS + k0 + row) * 2048 + 1024 + h * 64 + c * 8);
        } else {
            CP_ASYNC16(vst + off,
                       vth + (long long)(h * 64 + row) * M_ + bS + k0 + c * 8);
        }
    }
    CP_COMMIT();
}

__global__ void __launch_bounds__(256, 2) attn_h_kernel(
    const __half* __restrict__ qkvh, const __half* __restrict__ vth,
    __half* __restrict__ yh) {
    extern __shared__ char smc[];
    const uint32_t sbase = smem_u32(smc);

    const int tid  = threadIdx.x;
    const int w    = tid >> 5;
    const int lane = tid & 31;
    const int gid  = lane >> 2;
    const int tig  = lane & 3;
    const int qt   = gridDim.x - 1 - blockIdx.x;     // heavy tiles first
    const int h    = blockIdx.y;
    const int b    = blockIdx.z;
    const int q0   = qt * 128;
    const int nt   = 2 * qt + 2;
    const long long bS = (long long)b * S_;

    const int rl = lane & 7;
    const uint32_t q_lane  = (uint32_t)((w * 16 + ((lane >> 3) & 1) * 8 + rl) * 128);
    const int      q_cb    = lane >> 4;
    const uint32_t kv_lane = (uint32_t)((((lane >> 4) & 1) * 8 + rl) * 128);
    const int      kv_cb   = (lane >> 3) & 1;

    // pipeline: [KV s0][Q][KV s1] -> WAIT1 leaves only s1 outstanding
    attn_issue_kv(qkvh, vth, sbase, 0, 0, h, b, tid);
#pragma unroll
    for (int it = 0; it < 4; it++) {
        int idx = tid + it * 256;          // 0..1023
        int row = idx >> 3;                // 0..127
        int c   = idx & 7;
        uint32_t off = (uint32_t)(row * 8 + (c ^ (row & 7))) * 16;
        CP_ASYNC16(sbase + off,
                   qkvh + (bS + q0 + row) * 2048 + h * 64 + c * 8);
    }
    CP_COMMIT();
    attn_issue_kv(qkvh, vth, sbase, 1, 64, h, b, tid);

    float m0r = -INFINITY, m1r = -INFINITY, l0 = 0.0f, l1 = 0.0f;
    float ofr[8][4] = {};

    const int r0g = q0 + w * 16 + gid;
    const int r1g = r0g + 8;
    const int rfirst = q0 + w * 16;
    const int rmax   = rfirst + 15;

    for (int t = 0; t < nt; t++) {
        const int k0 = t * 64;
        if (t + 1 < nt) { CP_WAIT1(); } else { CP_WAIT0(); }
        __syncthreads();

        if (k0 <= rmax) {   // skip tiles entirely in this warp's future
            const uint32_t ksb = sbase + ATT_Q_B + (t & 1) * ATT_KV_B;
            const uint32_t vsb = ksb + 64 * 128;

            // S = Q K^T  (Q pre-scaled; 4 k16 steps over d=64)
            float sfr[8][4] = {};
#pragma unroll
            for (int ks = 0; ks < 4; ks++) {
                uint32_t a[4];
                LDSM_X4(a[0], a[1], a[2], a[3],
                        sbase + q_lane + ((uint32_t)((2 * ks + q_cb) ^ rl) << 4));
                uint32_t bf[8][2];
#pragma unroll
                for (int j = 0; j < 4; j++) {
                    uint32_t bd = ksb + kv_lane + j * 2048 +
                                  ((uint32_t)((2 * ks + kv_cb) ^ rl) << 4);
                    LDSM_X4(bf[2 * j][0], bf[2 * j][1],
                            bf[2 * j + 1][0], bf[2 * j + 1][1], bd);
                }
#pragma unroll
                for (int nf = 0; nf < 8; nf++)
                    mma_f16(sfr[nf], a, bf[nf]);
            }

            // causal mask (keys natural: c0,c1 -> 2tig, 2tig+1).
            // Gate on the FIRST row of the strip (R9 bug was rmax here).
            if (k0 + 63 > rfirst) {
#pragma unroll
                for (int nf = 0; nf < 8; nf++) {
                    const int ca = k0 + nf * 8 + 2 * tig;
                    if (ca     > r0g) sfr[nf][0] = -INFINITY;
                    if (ca + 1 > r0g) sfr[nf][1] = -INFINITY;
                    if (ca     > r1g) sfr[nf][2] = -INFINITY;
                    if (ca + 1 > r1g) sfr[nf][3] = -INFINITY;
                }
            }

            // online softmax (base-2), deferred l reduction
            float mx0 = -INFINITY, mx1 = -INFINITY;
#pragma unroll
            for (int nf = 0; nf < 8; nf++) {
                mx0 = fmaxf(mx0, fmaxf(sfr[nf][0], sfr[nf][1]));
                mx1 = fmaxf(mx1, fmaxf(sfr[nf][2], sfr[nf][3]));
            }
#pragma unroll
            for (int off = 1; off <= 2; off <<= 1) {
                mx0 = fmaxf(mx0, __shfl_xor_sync(0xffffffffu, mx0, off));
                mx1 = fmaxf(mx1, __shfl_xor_sync(0xffffffffu, mx1, off));
            }
            const float mn0 = fmaxf(m0r, mx0);
            const float mn1 = fmaxf(m1r, mx1);
            const float cr0 = ex2f(m0r - mn0);
            const float cr1 = ex2f(m1r - mn1);
            m0r = mn0; m1r = mn1;
            l0 *= cr0;  l1 *= cr1;
#pragma unroll
            for (int nf = 0; nf < 8; nf++) {
                ofr[nf][0] *= cr0; ofr[nf][1] *= cr0;
                ofr[nf][2] *= cr1; ofr[nf][3] *= cr1;
            }
            uint32_t pa[4][4];   // P A-frags for the 4 k16 steps
#pragma unroll
            for (int j = 0; j < 4; j++) {
                float p00 = ex2f(sfr[2 * j][0] - mn0);
                float p01 = ex2f(sfr[2 * j][1] - mn0);
                float p02 = ex2f(sfr[2 * j][2] - mn1);
                float p03 = ex2f(sfr[2 * j][3] - mn1);
                float p10 = ex2f(sfr[2 * j + 1][0] - mn0);
                float p11 = ex2f(sfr[2 * j + 1][1] - mn0);
                float p12 = ex2f(sfr[2 * j + 1][2] - mn1);
                float p13 = ex2f(sfr[2 * j + 1][3] - mn1);
                l0 += p00 + p01 + p10 + p11;
                l1 += p02 + p03 + p12 + p13;
                pa[j][0] = pack_half2(p00, p01);
                pa[j][1] = pack_half2(p02, p03);
                pa[j][2] = pack_half2(p10, p11);
                pa[j][3] = pack_half2(p12, p13);
            }

            // O += P @ V  (V B-frags from Vt[d][key] tile)
#pragma unroll
            for (int j = 0; j < 4; j++) {
                uint32_t bf[8][2];
#pragma unroll
                for (int jb = 0; jb < 4; jb++) {
                    uint32_t bd = vsb + kv_lane + jb * 2048 +
                                  ((uint32_t)((2 * j + kv_cb) ^ rl) << 4);
                    LDSM_X4(bf[2 * jb][0], bf[2 * jb][1],
                            bf[2 * jb + 1][0], bf[2 * jb + 1][1], bd);
                }
#pragma unroll
                for (int nf = 0; nf < 8; nf++)
                    mma_f16(ofr[nf], pa[j], bf[nf]);
            }
        }

        __syncthreads();
        if (t + 2 < nt)
            attn_issue_kv(qkvh, vth, sbase, t & 1, (t + 2) * 64, h, b, tid);
    }

    // deferred l reduction + epilogue (fp16 y)
#pragma unroll
    for (int off = 1; off <= 2; off <<= 1) {
        l0 += __shfl_xor_sync(0xffffffffu, l0, off);
        l1 += __shfl_xor_sync(0xffffffffu, l1, off);
    }
    const float inv0 = 1.0f / l0;
    const float inv1 = 1.0f / l1;
#pragma unroll
    for (int nf = 0; nf < 8; nf++) {
        const int c = h * 64 + nf * 8 + 2 * tig;
        *(uint32_t*)&yh[(bS + r0g) * E_ + c] =
            pack_half2(ofr[nf][0] * inv0, ofr[nf][1] * inv0);
        *(uint32_t*)&yh[(bS + r1g) * E_ + c] =
            pack_half2(ofr[nf][2] * inv1, ofr[nf][3] * inv1);
    }
}

// ===========================================================================
extern "C" void kernel_launch(void* const* d_in, const int* in_sizes, int n_in,
                              void* d_out, int out_size) {
    const float* x      = (const float*)d_in[0];   // [B, S, E]
    const float* w_att  = (const float*)d_in[1];   // [E, 3E]
    const float* w_proj = (const float*)d_in[2];   // [E, E]
    float* out = (float*)d_out;                    // [B, S, E]

    __half *xh, *qkvh, *vth, *yh, *wTh;
    cudaGetSymbolAddress((void**)&xh, g_xh);
    cudaGetSymbolAddress((void**)&qkvh, g_qkvh);
    cudaGetSymbolAddress((void**)&vth, g_vth);
    cudaGetSymbolAddress((void**)&yh, g_yh);
    cudaGetSymbolAddress((void**)&wTh, g_wTh);
    __half* wattTh  = wTh;                          // [3E, E]
    __half* wprojTh = wTh + (long long)3 * E_ * E_; // [E, E]

    cudaFuncSetAttribute(gemm_h_kernel,
                         cudaFuncAttributeMaxDynamicSharedMemorySize,
                         GEMM_SMEM_BYTES);
    cudaFuncSetAttribute(attn_h_kernel,
                         cudaFuncAttributeMaxDynamicSharedMemorySize,
                         ATT_SMEM_BYTES);

    // 0) Convert x; transpose+convert weights
    cvt_kernel<<<2048, 256>>>(x, xh, (long long)M_ * E_ / 4);
    {
        dim3 g1(3 * E_ / 32, E_ / 32);
        transpose_kernel<<<g1, 256>>>(w_att, wattTh, E_, 3 * E_);
        dim3 g2(E_ / 32, E_ / 32);
        transpose_kernel<<<g2, 256>>>(w_proj, wprojTh, E_, E_);
    }
    // 1) QKV projection: Q (scaled) + K -> qkvh; V -> vth transposed
    {
        dim3 grid(3 * E_ / 128, M_ / 128);
        gemm_h_kernel<<<grid, 256, GEMM_SMEM_BYTES>>>(
            xh, wattTh, nullptr, qkvh, vth, M_, 3 * E_, E_, 1);
    }
    // 2) Causal flash attention -> yh (fp16)
    {
        dim3 grid(S_ / 128, H_, B_);
        attn_h_kernel<<<grid, 256, ATT_SMEM_BYTES>>>(qkvh, vth, yh);
    }
    // 3) Output projection -> fp32 out
    {
        dim3 grid(E_ / 128, M_ / 128);
        gemm_h_kernel<<<grid, 256, GEMM_SMEM_BYTES>>>(
            yh, wprojTh, out, nullptr, nullptr, M_, E_, E_, 0);
    }
}

// round 11
// speedup vs baseline: 9.1021x; 1.0095x over previous
#include <cuda_runtime.h>
#include <cuda_fp16.h>
#include <math.h>
#include <stdint.h>

// Problem constants
constexpr int B_ = 4;
constexpr int S_ = 2048;
constexpr int E_ = 1024;
constexpr int H_ = 16;
constexpr int D_ = 64;
constexpr int M_ = B_ * S_;   // 8192 tokens

// Q pre-scale: 1/sqrt(64) * log2(e)  (softmax runs in base-2)
#define QSCALE 0.180336880f

// Scratch (allocation-free rule: __device__ globals)
__device__ __half g_xh[(long long)M_ * E_];          // x in fp16
__device__ __half g_qkvh[(long long)M_ * 2 * E_];    // Q(pre-scaled)|K, fp16
__device__ __half g_vth[(long long)E_ * M_];         // V transposed [h*64+d][token]
__device__ __half g_yh[(long long)M_ * E_];          // attention out, fp16
__device__ __half g_wTh[(long long)3 * E_ * E_ + (long long)E_ * E_]; // W^T fp16

__device__ __forceinline__ float ex2f(float x) {
    float r; asm("ex2.approx.f32 %0, %1;" : "=f"(r) : "f"(x)); return r;
}
__device__ __forceinline__ uint32_t pack_half2(float lo, float hi) {
    uint32_t r;
    asm("cvt.rn.f16x2.f32 %0, %1, %2;" : "=r"(r) : "f"(hi), "f"(lo));
    return r;
}
__device__ __forceinline__ uint32_t smem_u32(const void* p) {
    uint32_t a;
    asm("{ .reg .u64 t; cvta.to.shared.u64 t, %1; cvt.u32.u64 %0, t; }"
        : "=r"(a) : "l"(p));
    return a;
}

#define CP_ASYNC16(dst, src) \
    asm volatile("cp.async.cg.shared.global [%0], [%1], 16;" \
        :: "r"(dst), "l"(src))
#define CP_COMMIT() asm volatile("cp.async.commit_group;" ::: "memory")
#define CP_WAIT0()  asm volatile("cp.async.wait_group 0;" ::: "memory")
#define CP_WAIT1()  asm volatile("cp.async.wait_group 1;" ::: "memory")

#define LDSM_X4(r0, r1, r2, r3, addr) \
    asm volatile("ldmatrix.sync.aligned.m8n8.x4.shared.b16 {%0,%1,%2,%3}, [%4];" \
        : "=r"(r0), "=r"(r1), "=r"(r2), "=r"(r3) : "r"(addr))

// m16n8k16 fp16 MMA, fp32 accumulate (sm_80+; Blackwell tensor pipe)
__device__ __forceinline__ void mma_f16(float d[4], const uint32_t a[4],
                                        const uint32_t b[2]) {
    asm volatile(
        "mma.sync.aligned.m16n8k16.row.col.f32.f16.f16.f32 "
        "{%0,%1,%2,%3}, {%4,%5,%6,%7}, {%8,%9}, {%0,%1,%2,%3};\n"
        : "+f"(d[0]), "+f"(d[1]), "+f"(d[2]), "+f"(d[3])
        : "r"(a[0]), "r"(a[1]), "r"(a[2]), "r"(a[3]), "r"(b[0]), "r"(b[1]));
}

// ===========================================================================
// x -> fp16
// ===========================================================================
__global__ void __launch_bounds__(256) cvt_kernel(
    const float* __restrict__ X, __half* __restrict__ XH, long long n4) {
    long long i = blockIdx.x * 256 + threadIdx.x;
    long long stride = (long long)gridDim.x * 256;
    for (; i < n4; i += stride) {
        float4 v = ((const float4*)X)[i];
        ((uint2*)XH)[i] = make_uint2(pack_half2(v.x, v.y), pack_half2(v.z, v.w));
    }
}

// ===========================================================================
// Fused weight transpose + fp16 for BOTH weights in one launch.
// blocks x in [0,96): w_att (N=3072); [96,128): w_proj (N=1024). K=1024.
// ===========================================================================
__global__ void __launch_bounds__(256) transpose2_kernel(
    const float* __restrict__ Wa, __half* __restrict__ WaT,
    const float* __restrict__ Wp, __half* __restrict__ WpT) {
    __shared__ float t[32][33];
    const bool isA = (blockIdx.x < 96);
    const float* W = isA ? Wa : Wp;
    __half* WT     = isA ? WaT : WpT;
    const int N    = isA ? 3 * E_ : E_;
    const int n0   = (isA ? blockIdx.x : blockIdx.x - 96) * 32;
    const int k0   = blockIdx.y * 32;
    const int tx = threadIdx.x & 31, ty = threadIdx.x >> 5;
    for (int r = ty; r < 32; r += 8)
        t[r][tx] = W[(long long)(k0 + r) * N + n0 + tx];
    __syncthreads();
    for (int r = ty; r < 32; r += 8)
        WT[(long long)(n0 + r) * E_ + k0 + tx] = __float2half_rn(t[tx][r]);
}

// ===========================================================================
// fp16 mma.sync GEMM, 3-stage cp.async pipeline, ldmatrix fragment loads.
// C = A[M,K] @ BT[N,K]^T, fp16 operands, fp32 accum.
// 128x128x64 tile (BK=64 halves = 128B rows), 8 warps (2x4), warp 64x32.
// mode 0: fp32 out to Cf.
// mode 1 (QKV): n0<1024 -> Q (scale by QSCALE, half -> Ch);
//               n0<2048 -> K (half -> Ch); else V -> VT transposed.
// ===========================================================================
constexpr int BK = 64;                          // halves per chunk (128B)
constexpr int GSTAGE_B = 2 * 128 * 128;         // A + B tile bytes = 32768
constexpr int GEMM_SMEM_BYTES = 3 * GSTAGE_B;   // 98304

__device__ __forceinline__ void gemm_issue(
    const __half* __restrict__ A, const __half* __restrict__ BT,
    uint32_t sbase, int stage, int m0, int n0, int k0, int K, int tid) {
    uint32_t st = sbase + stage * GSTAGE_B;
#pragma unroll
    for (int it = 0; it < 4; it++) {
        int idx = tid + it * 256;          // 0..1023
        int row = idx >> 3;                // 0..127
        int c   = idx & 7;                 // 16B chunk
        uint32_t off = (uint32_t)(row * 8 + (c ^ (row & 7))) * 16;
        CP_ASYNC16(st + off, A + (long long)(m0 + row) * K + k0 + c * 8);
        CP_ASYNC16(st + 16384 + off, BT + (long long)(n0 + row) * K + k0 + c * 8);
    }
    CP_COMMIT();
}

__global__ void __launch_bounds__(256, 2) gemm_h_kernel(
    const __half* __restrict__ A, const __half* __restrict__ BT,
    float* __restrict__ Cf, __half* __restrict__ Ch, __half* __restrict__ VT,
    int M, int N, int K, int mode) {
    extern __shared__ char smc[];
    const uint32_t sbase = smem_u32(smc);

    const int tid  = threadIdx.x;
    const int wid  = tid >> 5;
    const int lane = tid & 31;
    const int gid  = lane >> 2;
    const int tig  = lane & 3;
    const int wm   = (wid & 1) * 64;
    const int wn   = (wid >> 1) * 32;
    const int m0   = blockIdx.y * 128;
    const int n0   = blockIdx.x * 128;

    const int rl = lane & 7;
    const uint32_t a_lane = (uint32_t)((wm + ((lane >> 3) & 1) * 8 + rl) * 128);
    const int a_cb = lane >> 4;
    const uint32_t b_lane = 16384u + (uint32_t)((wn + ((lane >> 4) & 1) * 8 + rl) * 128);
    const int b_cb = (lane >> 3) & 1;

    float acc[4][4][4] = {};

    const int NIT = K / BK;
    gemm_issue(A, BT, sbase, 0, m0, n0, 0, K, tid);
    gemm_issue(A, BT, sbase, 1, m0, n0, BK, K, tid);

    for (int i = 0; i < NIT; i++) {
        if (i + 1 < NIT) { CP_WAIT1(); } else { CP_WAIT0(); }
        __syncthreads();
        if (i + 2 < NIT)
            gemm_issue(A, BT, sbase, (i + 2) % 3, m0, n0, (i + 2) * BK, K, tid);

        const uint32_t stb = sbase + (uint32_t)(i % 3) * GSTAGE_B;
#pragma unroll
        for (int ks = 0; ks < 4; ks++) {       // 4 k16 steps per BK=64
            uint32_t af[4][4], bf[4][2];
#pragma unroll
            for (int mf = 0; mf < 4; mf++) {
                uint32_t ad = stb + a_lane + mf * 2048 +
                              ((uint32_t)((2 * ks + a_cb) ^ rl) << 4);
                LDSM_X4(af[mf][0], af[mf][1], af[mf][2], af[mf][3], ad);
            }
#pragma unroll
            for (int j = 0; j < 2; j++) {
                uint32_t bd = stb + b_lane + j * 2048 +
                              ((uint32_t)((2 * ks + b_cb) ^ rl) << 4);
                LDSM_X4(bf[2 * j][0], bf[2 * j][1], bf[2 * j + 1][0], bf[2 * j + 1][1], bd);
            }
#pragma unroll
            for (int mf = 0; mf < 4; mf++)
#pragma unroll
                for (int nf = 0; nf < 4; nf++)
                    mma_f16(acc[mf][nf], af[mf], bf[nf]);
        }
    }

    // epilogue
    if (mode == 0) {
#pragma unroll
        for (int mf = 0; mf < 4; mf++) {
            const int r0 = m0 + wm + mf * 16 + gid;
#pragma unroll
            for (int nf = 0; nf < 4; nf++) {
                const int c = n0 + wn + nf * 8 + 2 * tig;
                *(float2*)&Cf[(long long)r0 * N + c] =
                    make_float2(acc[mf][nf][0], acc[mf][nf][1]);
                *(float2*)&Cf[(long long)(r0 + 8) * N + c] =
                    make_float2(acc[mf][nf][2], acc[mf][nf][3]);
            }
        }
    } else {
        const int region = n0 >> 10;   // 0:Q 1:K 2:V
        if (region < 2) {
            const float s = (region == 0) ? QSCALE : 1.0f;
#pragma unroll
            for (int mf = 0; mf < 4; mf++) {
                const int r0 = m0 + wm + mf * 16 + gid;
#pragma unroll
                for (int nf = 0; nf < 4; nf++) {
                    const int c = n0 + wn + nf * 8 + 2 * tig;
                    *(uint32_t*)&Ch[(long long)r0 * 2048 + c] =
                        pack_half2(acc[mf][nf][0] * s, acc[mf][nf][1] * s);
                    *(uint32_t*)&Ch[(long long)(r0 + 8) * 2048 + c] =
                        pack_half2(acc[mf][nf][2] * s, acc[mf][nf][3] * s);
                }
            }
        } else {
#pragma unroll
            for (int mf = 0; mf < 4; mf++) {
                const int r0 = m0 + wm + mf * 16 + gid;
#pragma unroll
                for (int nf = 0; nf < 4; nf++) {
                    const long long cv = n0 + wn + nf * 8 + 2 * tig - 2048;
                    VT[cv * M_ + r0]           = __float2half_rn(acc[mf][nf][0]);
                    VT[(cv + 1) * M_ + r0]     = __float2half_rn(acc[mf][nf][1]);
                    VT[cv * M_ + r0 + 8]       = __float2half_rn(acc[mf][nf][2]);
                    VT[(cv + 1) * M_ + r0 + 8] = __float2half_rn(acc[mf][nf][3]);
                }
            }
        }
    }
}

// ===========================================================================
// Causal flash attention, fp16 m16n8k16.
// R11: 3-stage KV ring -> ONE barrier per tile (GEMM pattern): after the
// top-of-loop barrier, issuing kv_{t+2} into stage (t+2)%3 == (t-1)%3 is
// safe because all warps finished reading stage t-1 before this barrier.
// Q pre-scaled by QSCALE (base-2 softmax). P C-frags pack into A-frags.
// Heavy q-tiles first; per-warp future-tile skip; deferred l reduction.
// Block 256 (8 warps), Q 128 rows, K tiles 64. Grid (S/128, H, B).
// ===========================================================================
constexpr int ATT_Q_B  = 128 * 128;             // 16384
constexpr int ATT_KV_B = 2 * 64 * 128;          // K + V one stage = 16384
constexpr int ATT_SMEM_BYTES = ATT_Q_B + 3 * ATT_KV_B;  // 65536

__device__ __forceinline__ void attn_issue_kv(
    const __half* __restrict__ qkvh, const __half* __restrict__ vth,
    uint32_t sbase, int stage, int k0, int h, int b, int tid) {
    uint32_t kst = sbase + ATT_Q_B + stage * ATT_KV_B;
    uint32_t vst = kst + 64 * 128;
    const long long bS = (long long)b * S_;
#pragma unroll
    for (int it = 0; it < 4; it++) {
        int idx = tid + (it & 1) * 256;    // 0..511
        int row = idx >> 3;                // 0..63
        int c   = idx & 7;
        uint32_t off = (uint32_t)(row * 8 + (c ^ (row & 7))) * 16;
        if (it < 2) {
            CP_ASYNC16(kst + off,
                       qkvh + (bS + k0 + row) * 2048 + 1024 + h * 64 + c * 8);
        } else {
            CP_ASYNC16(vst + off,
                       vth + (long long)(h * 64 + row) * M_ + bS + k0 + c * 8);
        }
    }
    CP_COMMIT();
}

__global__ void __launch_bounds__(256, 2) attn_h_kernel(
    const __half* __restrict__ qkvh, const __half* __restrict__ vth,
    __half* __restrict__ yh) {
    extern __shared__ char smc[];
    const uint32_t sbase = smem_u32(smc);

    const int tid  = threadIdx.x;
    const int w    = tid >> 5;
    const int lane = tid & 31;
    const int gid  = lane >> 2;
    const int tig  = lane & 3;
    const int qt   = gridDim.x - 1 - blockIdx.x;     // heavy tiles first
    const int h    = blockIdx.y;
    const int b    = blockIdx.z;
    const int q0   = qt * 128;
    const int nt   = 2 * qt + 2;
    const long long bS = (long long)b * S_;

    const int rl = lane & 7;
    const uint32_t q_lane  = (uint32_t)((w * 16 + ((lane >> 3) & 1) * 8 + rl) * 128);
    const int      q_cb    = lane >> 4;
    const uint32_t kv_lane = (uint32_t)((((lane >> 4) & 1) * 8 + rl) * 128);
    const int      kv_cb   = (lane >> 3) & 1;

    // prologue: groups [kv0][Q][kv1] — WAIT1 at t=0 covers kv0 AND Q.
    attn_issue_kv(qkvh, vth, sbase, 0, 0, h, b, tid);
#pragma unroll
    for (int it = 0; it < 4; it++) {
        int idx = tid + it * 256;          // 0..1023
        int row = idx >> 3;                // 0..127
        int c   = idx & 7;
        uint32_t off = (uint32_t)(row * 8 + (c ^ (row & 7))) * 16;
        CP_ASYNC16(sbase + off,
                   qkvh + (bS + q0 + row) * 2048 + h * 64 + c * 8);
    }
    CP_COMMIT();
    attn_issue_kv(qkvh, vth, sbase, 1, 64, h, b, tid);

    float m0r = -INFINITY, m1r = -INFINITY, l0 = 0.0f, l1 = 0.0f;
    float ofr[8][4] = {};

    const int r0g = q0 + w * 16 + gid;
    const int r1g = r0g + 8;
    const int rfirst = q0 + w * 16;
    const int rmax   = rfirst + 15;

    for (int t = 0; t < nt; t++) {
        const int k0 = t * 64;
        if (t + 1 < nt) { CP_WAIT1(); } else { CP_WAIT0(); }
        __syncthreads();   // single barrier: stage t ready AND stage (t-1)%3 free
        if (t + 2 < nt)
            attn_issue_kv(qkvh, vth, sbase, (t + 2) % 3, (t + 2) * 64, h, b, tid);

        if (k0 <= rmax) {   // skip tiles entirely in this warp's future
            const uint32_t ksb = sbase + ATT_Q_B + (uint32_t)(t % 3) * ATT_KV_B;
            const uint32_t vsb = ksb + 64 * 128;

            // S = Q K^T  (Q pre-scaled; 4 k16 steps over d=64)
            float sfr[8][4] = {};
#pragma unroll
            for (int ks = 0; ks < 4; ks++) {
                uint32_t a[4];
                LDSM_X4(a[0], a[1], a[2], a[3],
                        sbase + q_lane + ((uint32_t)((2 * ks + q_cb) ^ rl) << 4));
                uint32_t bf[8][2];
#pragma unroll
                for (int j = 0; j < 4; j++) {
                    uint32_t bd = ksb + kv_lane + j * 2048 +
                                  ((uint32_t)((2 * ks + kv_cb) ^ rl) << 4);
                    LDSM_X4(bf[2 * j][0], bf[2 * j][1],
                            bf[2 * j + 1][0], bf[2 * j + 1][1], bd);
                }
#pragma unroll
                for (int nf = 0; nf < 8; nf++)
                    mma_f16(sfr[nf], a, bf[nf]);
            }

            // causal mask (keys natural: c0,c1 -> 2tig, 2tig+1); gate on
            // the FIRST row of the warp strip.
            if (k0 + 63 > rfirst) {
#pragma unroll
                for (int nf = 0; nf < 8; nf++) {
                    const int ca = k0 + nf * 8 + 2 * tig;
                    if (ca     > r0g) sfr[nf][0] = -INFINITY;
                    if (ca + 1 > r0g) sfr[nf][1] = -INFINITY;
                    if (ca     > r1g) sfr[nf][2] = -INFINITY;
                    if (ca + 1 > r1g) sfr[nf][3] = -INFINITY;
                }
            }

            // online softmax (base-2), deferred l reduction
            float mx0 = -INFINITY, mx1 = -INFINITY;
#pragma unroll
            for (int nf = 0; nf < 8; nf++) {
                mx0 = fmaxf(mx0, fmaxf(sfr[nf][0], sfr[nf][1]));
                mx1 = fmaxf(mx1, fmaxf(sfr[nf][2], sfr[nf][3]));
            }
#pragma unroll
            for (int off = 1; off <= 2; off <<= 1) {
                mx0 = fmaxf(mx0, __shfl_xor_sync(0xffffffffu, mx0, off));
                mx1 = fmaxf(mx1, __shfl_xor_sync(0xffffffffu, mx1, off));
            }
            const float mn0 = fmaxf(m0r, mx0);
            const float mn1 = fmaxf(m1r, mx1);
            const float cr0 = ex2f(m0r - mn0);
            const float cr1 = ex2f(m1r - mn1);
            m0r = mn0; m1r = mn1;
            l0 *= cr0;  l1 *= cr1;
#pragma unroll
            for (int nf = 0; nf < 8; nf++) {
                ofr[nf][0] *= cr0; ofr[nf][1] *= cr0;
                ofr[nf][2] *= cr1; ofr[nf][3] *= cr1;
            }
            uint32_t pa[4][4];   // P A-frags for the 4 k16 steps
#pragma unroll
            for (int j = 0; j < 4; j++) {
                float p00 = ex2f(sfr[2 * j][0] - mn0);
                float p01 = ex2f(sfr[2 * j][1] - mn0);
                float p02 = ex2f(sfr[2 * j][2] - mn1);
                float p03 = ex2f(sfr[2 * j][3] - mn1);
                float p10 = ex2f(sfr[2 * j + 1][0] - mn0);
                float p11 = ex2f(sfr[2 * j + 1][1] - mn0);
                float p12 = ex2f(sfr[2 * j + 1][2] - mn1);
                float p13 = ex2f(sfr[2 * j + 1][3] - mn1);
                l0 += p00 + p01 + p10 + p11;
                l1 += p02 + p03 + p12 + p13;
                pa[j][0] = pack_half2(p00, p01);
                pa[j][1] = pack_half2(p02, p03);
                pa[j][2] = pack_half2(p10, p11);
                pa[j][3] = pack_half2(p12, p13);
            }

            // O += P @ V  (V B-frags from Vt[d][key] tile)
#pragma unroll
            for (int j = 0; j < 4; j++) {
                uint32_t bf[8][2];
#pragma unroll
                for (int jb = 0; jb < 4; jb++) {
                    uint32_t bd = vsb + kv_lane + jb * 2048 +
                                  ((uint32_t)((2 * j + kv_cb) ^ rl) << 4);
                    LDSM_X4(bf[2 * jb][0], bf[2 * jb][1],
                            bf[2 * jb + 1][0], bf[2 * jb + 1][1], bd);
                }
#pragma unroll
                for (int nf = 0; nf < 8; nf++)
                    mma_f16(ofr[nf], pa[j], bf[nf]);
            }
        }
    }

    // deferred l reduction + epilogue (fp16 y)
#pragma unroll
    for (int off = 1; off <= 2; off <<= 1) {
        l0 += __shfl_xor_sync(0xffffffffu, l0, off);
        l1 += __shfl_xor_sync(0xffffffffu, l1, off);
    }
    const float inv0 = 1.0f / l0;
    const float inv1 = 1.0f / l1;
#pragma unroll
    for (int nf = 0; nf < 8; nf++) {
        const int c = h * 64 + nf * 8 + 2 * tig;
        *(uint32_t*)&yh[(bS + r0g) * E_ + c] =
            pack_half2(ofr[nf][0] * inv0, ofr[nf][1] * inv0);
        *(uint32_t*)&yh[(bS + r1g) * E_ + c] =
            pack_half2(ofr[nf][2] * inv1, ofr[nf][3] * inv1);
    }
}

// ===========================================================================
extern "C" void kernel_launch(void* const* d_in, const int* in_sizes, int n_in,
                              void* d_out, int out_size) {
    const float* x      = (const float*)d_in[0];   // [B, S, E]
    const float* w_att  = (const float*)d_in[1];   // [E, 3E]
    const float* w_proj = (const float*)d_in[2];   // [E, E]
    float* out = (float*)d_out;                    // [B, S, E]

    __half *xh, *qkvh, *vth, *yh, *wTh;
    cudaGetSymbolAddress((void**)&xh, g_xh);
    cudaGetSymbolAddress((void**)&qkvh, g_qkvh);
    cudaGetSymbolAddress((void**)&vth, g_vth);
    cudaGetSymbolAddress((void**)&yh, g_yh);
    cudaGetSymbolAddress((void**)&wTh, g_wTh);
    __half* wattTh  = wTh;                          // [3E, E]
    __half* wprojTh = wTh + (long long)3 * E_ * E_; // [E, E]

    cudaFuncSetAttribute(gemm_h_kernel,
                         cudaFuncAttributeMaxDynamicSharedMemorySize,
                         GEMM_SMEM_BYTES);
    cudaFuncSetAttribute(attn_h_kernel,
                         cudaFuncAttributeMaxDynamicSharedMemorySize,
                         ATT_SMEM_BYTES);

    // 0) Convert x; transpose+convert both weights (single launch)
    cvt_kernel<<<2048, 256>>>(x, xh, (long long)M_ * E_ / 4);
    {
        dim3 g(128, E_ / 32);
        transpose2_kernel<<<g, 256>>>(w_att, wattTh, w_proj, wprojTh);
    }
    // 1) QKV projection: Q (scaled) + K -> qkvh; V -> vth transposed
    {
        dim3 grid(3 * E_ / 128, M_ / 128);
        gemm_h_kernel<<<grid, 256, GEMM_SMEM_BYTES>>>(
            xh, wattTh, nullptr, qkvh, vth, M_, 3 * E_, E_, 1);
    }
    // 2) Causal flash attention -> yh (fp16)
    {
        dim3 grid(S_ / 128, H_, B_);
        attn_h_kernel<<<grid, 256, ATT_SMEM_BYTES>>>(qkvh, vth, yh);
    }
    // 3) Output projection -> fp32 out
    {
        dim3 grid(E_ / 128, M_ / 128);
        gemm_h_kernel<<<grid, 256, GEMM_SMEM_BYTES>>>(
            yh, wprojTh, out, nullptr, nullptr, M_, E_, E_, 0);
    }
}

// round 12
// speedup vs baseline: 9.3846x; 1.0310x over previous
#include <cuda_runtime.h>
#include <cuda_fp16.h>
#include <math.h>
#include <stdint.h>

// Problem constants
constexpr int B_ = 4;
constexpr int S_ = 2048;
constexpr int E_ = 1024;
constexpr int H_ = 16;
constexpr int D_ = 64;
constexpr int M_ = B_ * S_;   // 8192 tokens

// Q pre-scale: 1/sqrt(64) * log2(e)  (softmax runs in base-2)
#define QSCALE 0.180336880f

// Scratch (allocation-free rule: __device__ globals)
__device__ __half g_xh[(long long)M_ * E_];          // x in fp16
__device__ __half g_qkvh[(long long)M_ * 2 * E_];    // Q(pre-scaled)|K, fp16
__device__ __half g_vth[(long long)E_ * M_];         // V transposed [h*64+d][token]
__device__ __half g_yh[(long long)M_ * E_];          // attention out, fp16
__device__ __half g_wTh[(long long)3 * E_ * E_ + (long long)E_ * E_]; // W^T fp16

__device__ __forceinline__ float ex2f(float x) {
    float r; asm("ex2.approx.f32 %0, %1;" : "=f"(r) : "f"(x)); return r;
}
__device__ __forceinline__ uint32_t h2ex2(uint32_t x) {   // ex2 on packed half2
    uint32_t r; asm("ex2.approx.f16x2 %0, %1;" : "=r"(r) : "r"(x)); return r;
}
__device__ __forceinline__ uint32_t pack_half2(float lo, float hi) {
    uint32_t r;
    asm("cvt.rn.f16x2.f32 %0, %1, %2;" : "=r"(r) : "f"(hi), "f"(lo));
    return r;
}
__device__ __forceinline__ uint32_t smem_u32(const void* p) {
    uint32_t a;
    asm("{ .reg .u64 t; cvta.to.shared.u64 t, %1; cvt.u32.u64 %0, t; }"
        : "=r"(a) : "l"(p));
    return a;
}

#define CP_ASYNC16(dst, src) \
    asm volatile("cp.async.cg.shared.global [%0], [%1], 16;" \
        :: "r"(dst), "l"(src))
#define CP_COMMIT() asm volatile("cp.async.commit_group;" ::: "memory")
#define CP_WAIT0()  asm volatile("cp.async.wait_group 0;" ::: "memory")
#define CP_WAIT1()  asm volatile("cp.async.wait_group 1;" ::: "memory")

#define LDSM_X4(r0, r1, r2, r3, addr) \
    asm volatile("ldmatrix.sync.aligned.m8n8.x4.shared.b16 {%0,%1,%2,%3}, [%4];" \
        : "=r"(r0), "=r"(r1), "=r"(r2), "=r"(r3) : "r"(addr))

// m16n8k16 fp16 MMA, fp32 accumulate (sm_80+; Blackwell tensor pipe)
__device__ __forceinline__ void mma_f16(float d[4], const uint32_t a[4],
                                        const uint32_t b[2]) {
    asm volatile(
        "mma.sync.aligned.m16n8k16.row.col.f32.f16.f16.f32 "
        "{%0,%1,%2,%3}, {%4,%5,%6,%7}, {%8,%9}, {%0,%1,%2,%3};\n"
        : "+f"(d[0]), "+f"(d[1]), "+f"(d[2]), "+f"(d[3])
        : "r"(a[0]), "r"(a[1]), "r"(a[2]), "r"(a[3]), "r"(b[0]), "r"(b[1]));
}

// ===========================================================================
// x -> fp16
// ===========================================================================
__global__ void __launch_bounds__(256) cvt_kernel(
    const float* __restrict__ X, __half* __restrict__ XH, long long n4) {
    long long i = blockIdx.x * 256 + threadIdx.x;
    long long stride = (long long)gridDim.x * 256;
    for (; i < n4; i += stride) {
        float4 v = ((const float4*)X)[i];
        ((uint2*)XH)[i] = make_uint2(pack_half2(v.x, v.y), pack_half2(v.z, v.w));
    }
}

// ===========================================================================
// Fused weight transpose + fp16 for BOTH weights in one launch.
// blocks x in [0,96): w_att (N=3072); [96,128): w_proj (N=1024). K=1024.
// ===========================================================================
__global__ void __launch_bounds__(256) transpose2_kernel(
    const float* __restrict__ Wa, __half* __restrict__ WaT,
    const float* __restrict__ Wp, __half* __restrict__ WpT) {
    __shared__ float t[32][33];
    const bool isA = (blockIdx.x < 96);
    const float* W = isA ? Wa : Wp;
    __half* WT     = isA ? WaT : WpT;
    const int N    = isA ? 3 * E_ : E_;
    const int n0   = (isA ? blockIdx.x : blockIdx.x - 96) * 32;
    const int k0   = blockIdx.y * 32;
    const int tx = threadIdx.x & 31, ty = threadIdx.x >> 5;
    for (int r = ty; r < 32; r += 8)
        t[r][tx] = W[(long long)(k0 + r) * N + n0 + tx];
    __syncthreads();
    for (int r = ty; r < 32; r += 8)
        WT[(long long)(n0 + r) * E_ + k0 + tx] = __float2half_rn(t[tx][r]);
}

// ===========================================================================
// fp16 mma.sync GEMM, 3-stage cp.async pipeline, ldmatrix fragment loads.
// C = A[M,K] @ BT[N,K]^T, fp16 operands, fp32 accum.
// 128x128x64 tile (BK=64 halves = 128B rows), 8 warps (2x4), warp 64x32.
// mode 0: fp32 out to Cf.
// mode 1 (QKV): n0<1024 -> Q (scale by QSCALE, half -> Ch);
//               n0<2048 -> K (half -> Ch); else V -> VT transposed.
// ===========================================================================
constexpr int BK = 64;                          // halves per chunk (128B)
constexpr int GSTAGE_B = 2 * 128 * 128;         // A + B tile bytes = 32768
constexpr int GEMM_SMEM_BYTES = 3 * GSTAGE_B;   // 98304

__device__ __forceinline__ void gemm_issue(
    const __half* __restrict__ A, const __half* __restrict__ BT,
    uint32_t sbase, int stage, int m0, int n0, int k0, int K, int tid) {
    uint32_t st = sbase + stage * GSTAGE_B;
#pragma unroll
    for (int it = 0; it < 4; it++) {
        int idx = tid + it * 256;          // 0..1023
        int row = idx >> 3;                // 0..127
        int c   = idx & 7;                 // 16B chunk
        uint32_t off = (uint32_t)(row * 8 + (c ^ (row & 7))) * 16;
        CP_ASYNC16(st + off, A + (long long)(m0 + row) * K + k0 + c * 8);
        CP_ASYNC16(st + 16384 + off, BT + (long long)(n0 + row) * K + k0 + c * 8);
    }
    CP_COMMIT();
}

__global__ void __launch_bounds__(256, 2) gemm_h_kernel(
    const __half* __restrict__ A, const __half* __restrict__ BT,
    float* __restrict__ Cf, __half* __restrict__ Ch, __half* __restrict__ VT,
    int M, int N, int K, int mode) {
    extern __shared__ char smc[];
    const uint32_t sbase = smem_u32(smc);

    const int tid  = threadIdx.x;
    const int wid  = tid >> 5;
    const int lane = tid & 31;
    const int gid  = lane >> 2;
    const int tig  = lane & 3;
    const int wm   = (wid & 1) * 64;
    const int wn   = (wid >> 1) * 32;
    const int m0   = blockIdx.y * 128;
    const int n0   = blockIdx.x * 128;

    const int rl = lane & 7;
    const uint32_t a_lane = (uint32_t)((wm + ((lane >> 3) & 1) * 8 + rl) * 128);
    const int a_cb = lane >> 4;
    const uint32_t b_lane = 16384u + (uint32_t)((wn + ((lane >> 4) & 1) * 8 + rl) * 128);
    const int b_cb = (lane >> 3) & 1;

    float acc[4][4][4] = {};

    const int NIT = K / BK;
    gemm_issue(A, BT, sbase, 0, m0, n0, 0, K, tid);
    gemm_issue(A, BT, sbase, 1, m0, n0, BK, K, tid);

    for (int i = 0; i < NIT; i++) {
        if (i + 1 < NIT) { CP_WAIT1(); } else { CP_WAIT0(); }
        __syncthreads();
        if (i + 2 < NIT)
            gemm_issue(A, BT, sbase, (i + 2) % 3, m0, n0, (i + 2) * BK, K, tid);

        const uint32_t stb = sbase + (uint32_t)(i % 3) * GSTAGE_B;
#pragma unroll
        for (int ks = 0; ks < 4; ks++) {       // 4 k16 steps per BK=64
            uint32_t af[4][4], bf[4][2];
#pragma unroll
            for (int mf = 0; mf < 4; mf++) {
                uint32_t ad = stb + a_lane + mf * 2048 +
                              ((uint32_t)((2 * ks + a_cb) ^ rl) << 4);
                LDSM_X4(af[mf][0], af[mf][1], af[mf][2], af[mf][3], ad);
            }
#pragma unroll
            for (int j = 0; j < 2; j++) {
                uint32_t bd = stb + b_lane + j * 2048 +
                              ((uint32_t)((2 * ks + b_cb) ^ rl) << 4);
                LDSM_X4(bf[2 * j][0], bf[2 * j][1], bf[2 * j + 1][0], bf[2 * j + 1][1], bd);
            }
#pragma unroll
            for (int mf = 0; mf < 4; mf++)
#pragma unroll
                for (int nf = 0; nf < 4; nf++)
                    mma_f16(acc[mf][nf], af[mf], bf[nf]);
        }
    }

    // epilogue
    if (mode == 0) {
#pragma unroll
        for (int mf = 0; mf < 4; mf++) {
            const int r0 = m0 + wm + mf * 16 + gid;
#pragma unroll
            for (int nf = 0; nf < 4; nf++) {
                const int c = n0 + wn + nf * 8 + 2 * tig;
                *(float2*)&Cf[(long long)r0 * N + c] =
                    make_float2(acc[mf][nf][0], acc[mf][nf][1]);
                *(float2*)&Cf[(long long)(r0 + 8) * N + c] =
                    make_float2(acc[mf][nf][2], acc[mf][nf][3]);
            }
        }
    } else {
        const int region = n0 >> 10;   // 0:Q 1:K 2:V
        if (region < 2) {
            const float s = (region == 0) ? QSCALE : 1.0f;
#pragma unroll
            for (int mf = 0; mf < 4; mf++) {
                const int r0 = m0 + wm + mf * 16 + gid;
#pragma unroll
                for (int nf = 0; nf < 4; nf++) {
                    const int c = n0 + wn + nf * 8 + 2 * tig;
                    *(uint32_t*)&Ch[(long long)r0 * 2048 + c] =
                        pack_half2(acc[mf][nf][0] * s, acc[mf][nf][1] * s);
                    *(uint32_t*)&Ch[(long long)(r0 + 8) * 2048 + c] =
                        pack_half2(acc[mf][nf][2] * s, acc[mf][nf][3] * s);
                }
            }
        } else {
#pragma unroll
            for (int mf = 0; mf < 4; mf++) {
                const int r0 = m0 + wm + mf * 16 + gid;
#pragma unroll
                for (int nf = 0; nf < 4; nf++) {
                    const long long cv = n0 + wn + nf * 8 + 2 * tig - 2048;
                    VT[cv * M_ + r0]           = __float2half_rn(acc[mf][nf][0]);
                    VT[(cv + 1) * M_ + r0]     = __float2half_rn(acc[mf][nf][1]);
                    VT[cv * M_ + r0 + 8]       = __float2half_rn(acc[mf][nf][2]);
                    VT[(cv + 1) * M_ + r0 + 8] = __float2half_rn(acc[mf][nf][3]);
                }
            }
        }
    }
}

// ===========================================================================
// Causal flash attention, fp16 m16n8k16.
// R12: softmax scalar-stream reduction —
//  (a) exp via ex2.approx.f16x2 on packed (s-m): halves MUFU ops and emits
//      P directly in A-frag format; num & denom use the SAME quantized P.
//  (b) l accumulated as an extra MMA column group with a CONSTANT all-ones
//      B-frag (l = P @ 1): no scalar l adds, no end shfl reduce; per-tile
//      rescale multiplies apply to lfr exactly like ofr.
// 3-stage KV ring, one barrier/tile. Q pre-scaled (base-2 softmax).
// Heavy q-tiles first; per-warp future-tile skip.
// Block 256 (8 warps), Q 128 rows, K tiles 64. Grid (S/128, H, B).
// ===========================================================================
constexpr int ATT_Q_B  = 128 * 128;             // 16384
constexpr int ATT_KV_B = 2 * 64 * 128;          // K + V one stage = 16384
constexpr int ATT_SMEM_BYTES = ATT_Q_B + 3 * ATT_KV_B;  // 65536

__device__ __forceinline__ void attn_issue_kv(
    const __half* __restrict__ qkvh, const __half* __restrict__ vth,
    uint32_t sbase, int stage, int k0, int h, int b, int tid) {
    uint32_t kst = sbase + ATT_Q_B + stage * ATT_KV_B;
    uint32_t vst = kst + 64 * 128;
    const long long bS = (long long)b * S_;
#pragma unroll
    for (int it = 0; it < 4; it++) {
        int idx = tid + (it & 1) * 256;    // 0..511
        int row = idx >> 3;                // 0..63
        int c   = idx & 7;
        uint32_t off = (uint32_t)(row * 8 + (c ^ (row & 7))) * 16;
        if (it < 2) {
            CP_ASYNC16(kst + off,
                       qkvh + (bS + k0 + row) * 2048 + 1024 + h * 64 + c * 8);
        } else {
            CP_ASYNC16(vst + off,
                       vth + (long long)(h * 64 + row) * M_ + bS + k0 + c * 8);
        }
    }
    CP_COMMIT();
}

__global__ void __launch_bounds__(256, 2) attn_h_kernel(
    const __half* __restrict__ qkvh, const __half* __restrict__ vth,
    __half* __restrict__ yh) {
    extern __shared__ char smc[];
    const uint32_t sbase = smem_u32(smc);

    const int tid  = threadIdx.x;
    const int w    = tid >> 5;
    const int lane = tid & 31;
    const int gid  = lane >> 2;
    const int tig  = lane & 3;
    const int qt   = gridDim.x - 1 - blockIdx.x;     // heavy tiles first
    const int h    = blockIdx.y;
    const int b    = blockIdx.z;
    const int q0   = qt * 128;
    const int nt   = 2 * qt + 2;
    const long long bS = (long long)b * S_;

    const int rl = lane & 7;
    const uint32_t q_lane  = (uint32_t)((w * 16 + ((lane >> 3) & 1) * 8 + rl) * 128);
    const int      q_cb    = lane >> 4;
    const uint32_t kv_lane = (uint32_t)((((lane >> 4) & 1) * 8 + rl) * 128);
    const int      kv_cb   = (lane >> 3) & 1;

    // prologue: groups [kv0][Q][kv1] — WAIT1 at t=0 covers kv0 AND Q.
    attn_issue_kv(qkvh, vth, sbase, 0, 0, h, b, tid);
#pragma unroll
    for (int it = 0; it < 4; it++) {
        int idx = tid + it * 256;          // 0..1023
        int row = idx >> 3;                // 0..127
        int c   = idx & 7;
        uint32_t off = (uint32_t)(row * 8 + (c ^ (row & 7))) * 16;
        CP_ASYNC16(sbase + off,
                   qkvh + (bS + q0 + row) * 2048 + h * 64 + c * 8);
    }
    CP_COMMIT();
    attn_issue_kv(qkvh, vth, sbase, 1, 64, h, b, tid);

    float m0r = -INFINITY, m1r = -INFINITY;
    float ofr[8][4] = {};
    float lfr[4] = {};                      // l via MMA (all cols equal l)
    const uint32_t ONES2[2] = {0x3C003C00u, 0x3C003C00u};  // half2(1,1)

    const int r0g = q0 + w * 16 + gid;
    const int r1g = r0g + 8;
    const int rfirst = q0 + w * 16;
    const int rmax   = rfirst + 15;

    for (int t = 0; t < nt; t++) {
        const int k0 = t * 64;
        if (t + 1 < nt) { CP_WAIT1(); } else { CP_WAIT0(); }
        __syncthreads();   // single barrier: stage t ready AND stage (t-1)%3 free
        if (t + 2 < nt)
            attn_issue_kv(qkvh, vth, sbase, (t + 2) % 3, (t + 2) * 64, h, b, tid);

        if (k0 <= rmax) {   // skip tiles entirely in this warp's future
            const uint32_t ksb = sbase + ATT_Q_B + (uint32_t)(t % 3) * ATT_KV_B;
            const uint32_t vsb = ksb + 64 * 128;

            // S = Q K^T  (Q pre-scaled; 4 k16 steps over d=64)
            float sfr[8][4] = {};
#pragma unroll
            for (int ks = 0; ks < 4; ks++) {
                uint32_t a[4];
                LDSM_X4(a[0], a[1], a[2], a[3],
                        sbase + q_lane + ((uint32_t)((2 * ks + q_cb) ^ rl) << 4));
                uint32_t bf[8][2];
#pragma unroll
                for (int j = 0; j < 4; j++) {
                    uint32_t bd = ksb + kv_lane + j * 2048 +
                                  ((uint32_t)((2 * ks + kv_cb) ^ rl) << 4);
                    LDSM_X4(bf[2 * j][0], bf[2 * j][1],
                            bf[2 * j + 1][0], bf[2 * j + 1][1], bd);
                }
#pragma unroll
                for (int nf = 0; nf < 8; nf++)
                    mma_f16(sfr[nf], a, bf[nf]);
            }

            // causal mask (keys natural: c0,c1 -> 2tig, 2tig+1); gate on
            // the FIRST row of the warp strip.
            if (k0 + 63 > rfirst) {
#pragma unroll
                for (int nf = 0; nf < 8; nf++) {
                    const int ca = k0 + nf * 8 + 2 * tig;
                    if (ca     > r0g) sfr[nf][0] = -INFINITY;
                    if (ca + 1 > r0g) sfr[nf][1] = -INFINITY;
                    if (ca     > r1g) sfr[nf][2] = -INFINITY;
                    if (ca + 1 > r1g) sfr[nf][3] = -INFINITY;
                }
            }

            // online softmax (base-2)
            float mx0 = -INFINITY, mx1 = -INFINITY;
#pragma unroll
            for (int nf = 0; nf < 8; nf++) {
                mx0 = fmaxf(mx0, fmaxf(sfr[nf][0], sfr[nf][1]));
                mx1 = fmaxf(mx1, fmaxf(sfr[nf][2], sfr[nf][3]));
            }
#pragma unroll
            for (int off = 1; off <= 2; off <<= 1) {
                mx0 = fmaxf(mx0, __shfl_xor_sync(0xffffffffu, mx0, off));
                mx1 = fmaxf(mx1, __shfl_xor_sync(0xffffffffu, mx1, off));
            }
            const float mn0 = fmaxf(m0r, mx0);
            const float mn1 = fmaxf(m1r, mx1);
            const float cr0 = ex2f(m0r - mn0);
            const float cr1 = ex2f(m1r - mn1);
            m0r = mn0; m1r = mn1;
#pragma unroll
            for (int nf = 0; nf < 8; nf++) {
                ofr[nf][0] *= cr0; ofr[nf][1] *= cr0;
                ofr[nf][2] *= cr1; ofr[nf][3] *= cr1;
            }
            lfr[0] *= cr0; lfr[1] *= cr0;
            lfr[2] *= cr1; lfr[3] *= cr1;

            // P = 2^(s-m) via f16x2 ex2 -> A-frags directly; l via ones-MMA
            uint32_t pa[4][4];
#pragma unroll
            for (int j = 0; j < 4; j++) {
                pa[j][0] = h2ex2(pack_half2(sfr[2 * j][0] - mn0,
                                            sfr[2 * j][1] - mn0));
                pa[j][1] = h2ex2(pack_half2(sfr[2 * j][2] - mn1,
                                            sfr[2 * j][3] - mn1));
                pa[j][2] = h2ex2(pack_half2(sfr[2 * j + 1][0] - mn0,
                                            sfr[2 * j + 1][1] - mn0));
                pa[j][3] = h2ex2(pack_half2(sfr[2 * j + 1][2] - mn1,
                                            sfr[2 * j + 1][3] - mn1));
                mma_f16(lfr, pa[j], ONES2);
            }

            // O += P @ V  (V B-frags from Vt[d][key] tile)
#pragma unroll
            for (int j = 0; j < 4; j++) {
                uint32_t bf[8][2];
#pragma unroll
                for (int jb = 0; jb < 4; jb++) {
                    uint32_t bd = vsb + kv_lane + jb * 2048 +
                                  ((uint32_t)((2 * j + kv_cb) ^ rl) << 4);
                    LDSM_X4(bf[2 * jb][0], bf[2 * jb][1],
                            bf[2 * jb + 1][0], bf[2 * jb + 1][1], bd);
                }
#pragma unroll
                for (int nf = 0; nf < 8; nf++)
                    mma_f16(ofr[nf], pa[j], bf[nf]);
            }
        }
    }

    // epilogue: every lane's lfr[0]/lfr[2] IS l for its two rows (fp16 y)
    const float inv0 = 1.0f / lfr[0];
    const float inv1 = 1.0f / lfr[2];
#pragma unroll
    for (int nf = 0; nf < 8; nf++) {
        const int c = h * 64 + nf * 8 + 2 * tig;
        *(uint32_t*)&yh[(bS + r0g) * E_ + c] =
            pack_half2(ofr[nf][0] * inv0, ofr[nf][1] * inv0);
        *(uint32_t*)&yh[(bS + r1g) * E_ + c] =
            pack_half2(ofr[nf][2] * inv1, ofr[nf][3] * inv1);
    }
}

// ===========================================================================
extern "C" void kernel_launch(void* const* d_in, const int* in_sizes, int n_in,
                              void* d_out, int out_size) {
    const float* x      = (const float*)d_in[0];   // [B, S, E]
    const float* w_att  = (const float*)d_in[1];   // [E, 3E]
    const float* w_proj = (const float*)d_in[2];   // [E, E]
    float* out = (float*)d_out;                    // [B, S, E]

    __half *xh, *qkvh, *vth, *yh, *wTh;
    cudaGetSymbolAddress((void**)&xh, g_xh);
    cudaGetSymbolAddress((void**)&qkvh, g_qkvh);
    cudaGetSymbolAddress((void**)&vth, g_vth);
    cudaGetSymbolAddress((void**)&yh, g_yh);
    cudaGetSymbolAddress((void**)&wTh, g_wTh);
    __half* wattTh  = wTh;                          // [3E, E]
    __half* wprojTh = wTh + (long long)3 * E_ * E_; // [E, E]

    cudaFuncSetAttribute(gemm_h_kernel,
                         cudaFuncAttributeMaxDynamicSharedMemorySize,
                         GEMM_SMEM_BYTES);
    cudaFuncSetAttribute(attn_h_kernel,
                         cudaFuncAttributeMaxDynamicSharedMemorySize,
                         ATT_SMEM_BYTES);

    // 0) Convert x; transpose+convert both weights (single launch)
    cvt_kernel<<<2048, 256>>>(x, xh, (long long)M_ * E_ / 4);
    {
        dim3 g(128, E_ / 32);
        transpose2_kernel<<<g, 256>>>(w_att, wattTh, w_proj, wprojTh);
    }
    // 1) QKV projection: Q (scaled) + K -> qkvh; V -> vth transposed
    {
        dim3 grid(3 * E_ / 128, M_ / 128);
        gemm_h_kernel<<<grid, 256, GEMM_SMEM_BYTES>>>(
            xh, wattTh, nullptr, qkvh, vth, M_, 3 * E_, E_, 1);
    }
    // 2) Causal flash attention -> yh (fp16)
    {
        dim3 grid(S_ / 128, H_, B_);
        attn_h_kernel<<<grid, 256, ATT_SMEM_BYTES>>>(qkvh, vth, yh);
    }
    // 3) Output projection -> fp32 out
    {
        dim3 grid(E_ / 128, M_ / 128);
        gemm_h_kernel<<<grid, 256, GEMM_SMEM_BYTES>>>(
            yh, wprojTh, out, nullptr, nullptr, M_, E_, E_, 0);
    }
}

// round 13
// speedup vs baseline: 9.4159x; 1.0033x over previous
#include <cuda_runtime.h>
#include <cuda_fp16.h>
#include <math.h>
#include <stdint.h>

// Problem constants
constexpr int B_ = 4;
constexpr int S_ = 2048;
constexpr int E_ = 1024;
constexpr int H_ = 16;
constexpr int D_ = 64;
constexpr int M_ = B_ * S_;   // 8192 tokens

// Q pre-scale: 1/sqrt(64) * log2(e)  (softmax runs in base-2)
#define QSCALE 0.180336880f

// Scratch (allocation-free rule: __device__ globals)
__device__ __half g_xh[(long long)M_ * E_];          // x in fp16
__device__ __half g_qkvh[(long long)M_ * 2 * E_];    // Q(pre-scaled)|K, fp16
__device__ __half g_vth[(long long)E_ * M_];         // V transposed [h*64+d][token]
__device__ __half g_yh[(long long)M_ * E_];          // attention out, fp16
__device__ __half g_wTh[(long long)3 * E_ * E_ + (long long)E_ * E_]; // W^T fp16

__device__ __forceinline__ float ex2f(float x) {
    float r; asm("ex2.approx.f32 %0, %1;" : "=f"(r) : "f"(x)); return r;
}
__device__ __forceinline__ uint32_t h2ex2(uint32_t x) {   // ex2 on packed half2
    uint32_t r; asm("ex2.approx.f16x2 %0, %1;" : "=r"(r) : "r"(x)); return r;
}
__device__ __forceinline__ uint32_t pack_half2(float lo, float hi) {
    uint32_t r;
    asm("cvt.rn.f16x2.f32 %0, %1, %2;" : "=r"(r) : "f"(hi), "f"(lo));
    return r;
}
__device__ __forceinline__ uint32_t smem_u32(const void* p) {
    uint32_t a;
    asm("{ .reg .u64 t; cvta.to.shared.u64 t, %1; cvt.u32.u64 %0, t; }"
        : "=r"(a) : "l"(p));
    return a;
}

#define CP_ASYNC16(dst, src) \
    asm volatile("cp.async.cg.shared.global [%0], [%1], 16;" \
        :: "r"(dst), "l"(src))
#define CP_COMMIT() asm volatile("cp.async.commit_group;" ::: "memory")
#define CP_WAIT0()  asm volatile("cp.async.wait_group 0;" ::: "memory")
#define CP_WAIT1()  asm volatile("cp.async.wait_group 1;" ::: "memory")

#define LDSM_X4(r0, r1, r2, r3, addr) \
    asm volatile("ldmatrix.sync.aligned.m8n8.x4.shared.b16 {%0,%1,%2,%3}, [%4];" \
        : "=r"(r0), "=r"(r1), "=r"(r2), "=r"(r3) : "r"(addr))

// m16n8k16 fp16 MMA, fp32 accumulate (sm_80+; Blackwell tensor pipe)
__device__ __forceinline__ void mma_f16(float d[4], const uint32_t a[4],
                                        const uint32_t b[2]) {
    asm volatile(
        "mma.sync.aligned.m16n8k16.row.col.f32.f16.f16.f32 "
        "{%0,%1,%2,%3}, {%4,%5,%6,%7}, {%8,%9}, {%0,%1,%2,%3};\n"
        : "+f"(d[0]), "+f"(d[1]), "+f"(d[2]), "+f"(d[3])
        : "r"(a[0]), "r"(a[1]), "r"(a[2]), "r"(a[3]), "r"(b[0]), "r"(b[1]));
}

// ===========================================================================
// x -> fp16
// ===========================================================================
__global__ void __launch_bounds__(256) cvt_kernel(
    const float* __restrict__ X, __half* __restrict__ XH, long long n4) {
    long long i = blockIdx.x * 256 + threadIdx.x;
    long long stride = (long long)gridDim.x * 256;
    for (; i < n4; i += stride) {
        float4 v = ((const float4*)X)[i];
        ((uint2*)XH)[i] = make_uint2(pack_half2(v.x, v.y), pack_half2(v.z, v.w));
    }
}

// ===========================================================================
// Fused weight transpose + fp16 for BOTH weights in one launch.
// blocks x in [0,96): w_att (N=3072); [96,128): w_proj (N=1024). K=1024.
// ===========================================================================
__global__ void __launch_bounds__(256) transpose2_kernel(
    const float* __restrict__ Wa, __half* __restrict__ WaT,
    const float* __restrict__ Wp, __half* __restrict__ WpT) {
    __shared__ float t[32][33];
    const bool isA = (blockIdx.x < 96);
    const float* W = isA ? Wa : Wp;
    __half* WT     = isA ? WaT : WpT;
    const int N    = isA ? 3 * E_ : E_;
    const int n0   = (isA ? blockIdx.x : blockIdx.x - 96) * 32;
    const int k0   = blockIdx.y * 32;
    const int tx = threadIdx.x & 31, ty = threadIdx.x >> 5;
    for (int r = ty; r < 32; r += 8)
        t[r][tx] = W[(long long)(k0 + r) * N + n0 + tx];
    __syncthreads();
    for (int r = ty; r < 32; r += 8)
        WT[(long long)(n0 + r) * E_ + k0 + tx] = __float2half_rn(t[tx][r]);
}

// ===========================================================================
// fp16 mma.sync GEMM, 3-stage cp.async pipeline, ldmatrix fragment loads.
// C = A[M,K] @ BT[N,K]^T, fp16 operands, fp32 accum.
// 128x128x64 tile (BK=64 halves = 128B rows), 8 warps (2x4), warp 64x32.
// mode 0: fp32 out to Cf.
// mode 1 (QKV): n0<1024 -> Q (scale by QSCALE, half -> Ch);
//               n0<2048 -> K (half -> Ch); else V -> VT transposed.
// ===========================================================================
constexpr int BK = 64;                          // halves per chunk (128B)
constexpr int GSTAGE_B = 2 * 128 * 128;         // A + B tile bytes = 32768
constexpr int GEMM_SMEM_BYTES = 3 * GSTAGE_B;   // 98304

__device__ __forceinline__ void gemm_issue(
    const __half* __restrict__ A, const __half* __restrict__ BT,
    uint32_t sbase, int stage, int m0, int n0, int k0, int K, int tid) {
    uint32_t st = sbase + stage * GSTAGE_B;
#pragma unroll
    for (int it = 0; it < 4; it++) {
        int idx = tid + it * 256;          // 0..1023
        int row = idx >> 3;                // 0..127
        int c   = idx & 7;                 // 16B chunk
        uint32_t off = (uint32_t)(row * 8 + (c ^ (row & 7))) * 16;
        CP_ASYNC16(st + off, A + (long long)(m0 + row) * K + k0 + c * 8);
        CP_ASYNC16(st + 16384 + off, BT + (long long)(n0 + row) * K + k0 + c * 8);
    }
    CP_COMMIT();
}

__global__ void __launch_bounds__(256, 2) gemm_h_kernel(
    const __half* __restrict__ A, const __half* __restrict__ BT,
    float* __restrict__ Cf, __half* __restrict__ Ch, __half* __restrict__ VT,
    int M, int N, int K, int mode) {
    extern __shared__ char smc[];
    const uint32_t sbase = smem_u32(smc);

    const int tid  = threadIdx.x;
    const int wid  = tid >> 5;
    const int lane = tid & 31;
    const int gid  = lane >> 2;
    const int tig  = lane & 3;
    const int wm   = (wid & 1) * 64;
    const int wn   = (wid >> 1) * 32;
    const int m0   = blockIdx.y * 128;
    const int n0   = blockIdx.x * 128;

    const int rl = lane & 7;
    const uint32_t a_lane = (uint32_t)((wm + ((lane >> 3) & 1) * 8 + rl) * 128);
    const int a_cb = lane >> 4;
    const uint32_t b_lane = 16384u + (uint32_t)((wn + ((lane >> 4) & 1) * 8 + rl) * 128);
    const int b_cb = (lane >> 3) & 1;

    float acc[4][4][4] = {};

    const int NIT = K / BK;
    gemm_issue(A, BT, sbase, 0, m0, n0, 0, K, tid);
    gemm_issue(A, BT, sbase, 1, m0, n0, BK, K, tid);

    for (int i = 0; i < NIT; i++) {
        if (i + 1 < NIT) { CP_WAIT1(); } else { CP_WAIT0(); }
        __syncthreads();
        if (i + 2 < NIT)
            gemm_issue(A, BT, sbase, (i + 2) % 3, m0, n0, (i + 2) * BK, K, tid);

        const uint32_t stb = sbase + (uint32_t)(i % 3) * GSTAGE_B;
#pragma unroll
        for (int ks = 0; ks < 4; ks++) {       // 4 k16 steps per BK=64
            uint32_t af[4][4], bf[4][2];
#pragma unroll
            for (int mf = 0; mf < 4; mf++) {
                uint32_t ad = stb + a_lane + mf * 2048 +
                              ((uint32_t)((2 * ks + a_cb) ^ rl) << 4);
                LDSM_X4(af[mf][0], af[mf][1], af[mf][2], af[mf][3], ad);
            }
#pragma unroll
            for (int j = 0; j < 2; j++) {
                uint32_t bd = stb + b_lane + j * 2048 +
                              ((uint32_t)((2 * ks + b_cb) ^ rl) << 4);
                LDSM_X4(bf[2 * j][0], bf[2 * j][1], bf[2 * j + 1][0], bf[2 * j + 1][1], bd);
            }
#pragma unroll
            for (int mf = 0; mf < 4; mf++)
#pragma unroll
                for (int nf = 0; nf < 4; nf++)
                    mma_f16(acc[mf][nf], af[mf], bf[nf]);
        }
    }

    // epilogue
    if (mode == 0) {
#pragma unroll
        for (int mf = 0; mf < 4; mf++) {
            const int r0 = m0 + wm + mf * 16 + gid;
#pragma unroll
            for (int nf = 0; nf < 4; nf++) {
                const int c = n0 + wn + nf * 8 + 2 * tig;
                *(float2*)&Cf[(long long)r0 * N + c] =
                    make_float2(acc[mf][nf][0], acc[mf][nf][1]);
                *(float2*)&Cf[(long long)(r0 + 8) * N + c] =
                    make_float2(acc[mf][nf][2], acc[mf][nf][3]);
            }
        }
    } else {
        const int region = n0 >> 10;   // 0:Q 1:K 2:V
        if (region < 2) {
            const float s = (region == 0) ? QSCALE : 1.0f;
#pragma unroll
            for (int mf = 0; mf < 4; mf++) {
                const int r0 = m0 + wm + mf * 16 + gid;
#pragma unroll
                for (int nf = 0; nf < 4; nf++) {
                    const int c = n0 + wn + nf * 8 + 2 * tig;
                    *(uint32_t*)&Ch[(long long)r0 * 2048 + c] =
                        pack_half2(acc[mf][nf][0] * s, acc[mf][nf][1] * s);
                    *(uint32_t*)&Ch[(long long)(r0 + 8) * 2048 + c] =
                        pack_half2(acc[mf][nf][2] * s, acc[mf][nf][3] * s);
                }
            }
        } else {
#pragma unroll
            for (int mf = 0; mf < 4; mf++) {
                const int r0 = m0 + wm + mf * 16 + gid;
#pragma unroll
                for (int nf = 0; nf < 4; nf++) {
                    const long long cv = n0 + wn + nf * 8 + 2 * tig - 2048;
                    VT[cv * M_ + r0]           = __float2half_rn(acc[mf][nf][0]);
                    VT[(cv + 1) * M_ + r0]     = __float2half_rn(acc[mf][nf][1]);
                    VT[cv * M_ + r0 + 8]       = __float2half_rn(acc[mf][nf][2]);
                    VT[(cv + 1) * M_ + r0 + 8] = __float2half_rn(acc[mf][nf][3]);
                }
            }
        }
    }
}

// ===========================================================================
// Causal flash attention, fp16 m16n8k16.
// R13: LAZY softmax-max updates, period 4 (exact reformulation):
//  - per tile: only local-max accumulation into candidates (mc0/mc1);
//  - at t % 4 == 0: quad shfl-reduce, ex2 corrections, O/l rescale;
//  - between updates P = 2^(s - m_stale); O and l carry the same scale,
//    which cancels in O/l. fp16 range safe: s - m_stale <= ~6 whp << 16.
//  - t=0 is an update tile (valid m from the start; ex2(-inf)=0 zeroes
//    the empty accumulators). Warp tile-skip is monotone in t, so the
//    update schedule never desyncs.
// exp via ex2.approx.f16x2 -> P directly in A-frag form; l via ones-MMA.
// 3-stage KV ring, one barrier/tile. Q pre-scaled (base-2 softmax).
// Heavy q-tiles first. Block 256 (8 warps), Q 128 rows, K tiles 64.
// Grid (S/128, H, B).
// ===========================================================================
constexpr int ATT_Q_B  = 128 * 128;             // 16384
constexpr int ATT_KV_B = 2 * 64 * 128;          // K + V one stage = 16384
constexpr int ATT_SMEM_BYTES = ATT_Q_B + 3 * ATT_KV_B;  // 65536

__device__ __forceinline__ void attn_issue_kv(
    const __half* __restrict__ qkvh, const __half* __restrict__ vth,
    uint32_t sbase, int stage, int k0, int h, int b, int tid) {
    uint32_t kst = sbase + ATT_Q_B + stage * ATT_KV_B;
    uint32_t vst = kst + 64 * 128;
    const long long bS = (long long)b * S_;
#pragma unroll
    for (int it = 0; it < 4; it++) {
        int idx = tid + (it & 1) * 256;    // 0..511
        int row = idx >> 3;                // 0..63
        int c   = idx & 7;
        uint32_t off = (uint32_t)(row * 8 + (c ^ (row & 7))) * 16;
        if (it < 2) {
            CP_ASYNC16(kst + off,
                       qkvh + (bS + k0 + row) * 2048 + 1024 + h * 64 + c * 8);
        } else {
            CP_ASYNC16(vst + off,
                       vth + (long long)(h * 64 + row) * M_ + bS + k0 + c * 8);
        }
    }
    CP_COMMIT();
}

__global__ void __launch_bounds__(256, 2) attn_h_kernel(
    const __half* __restrict__ qkvh, const __half* __restrict__ vth,
    __half* __restrict__ yh) {
    extern __shared__ char smc[];
    const uint32_t sbase = smem_u32(smc);

    const int tid  = threadIdx.x;
    const int w    = tid >> 5;
    const int lane = tid & 31;
    const int gid  = lane >> 2;
    const int tig  = lane & 3;
    const int qt   = gridDim.x - 1 - blockIdx.x;     // heavy tiles first
    const int h    = blockIdx.y;
    const int b    = blockIdx.z;
    const int q0   = qt * 128;
    const int nt   = 2 * qt + 2;
    const long long bS = (long long)b * S_;

    const int rl = lane & 7;
    const uint32_t q_lane  = (uint32_t)((w * 16 + ((lane >> 3) & 1) * 8 + rl) * 128);
    const int      q_cb    = lane >> 4;
    const uint32_t kv_lane = (uint32_t)((((lane >> 4) & 1) * 8 + rl) * 128);
    const int      kv_cb   = (lane >> 3) & 1;

    // prologue: groups [kv0][Q][kv1] — WAIT1 at t=0 covers kv0 AND Q.
    attn_issue_kv(qkvh, vth, sbase, 0, 0, h, b, tid);
#pragma unroll
    for (int it = 0; it < 4; it++) {
        int idx = tid + it * 256;          // 0..1023
        int row = idx >> 3;                // 0..127
        int c   = idx & 7;
        uint32_t off = (uint32_t)(row * 8 + (c ^ (row & 7))) * 16;
        CP_ASYNC16(sbase + off,
                   qkvh + (bS + q0 + row) * 2048 + h * 64 + c * 8);
    }
    CP_COMMIT();
    attn_issue_kv(qkvh, vth, sbase, 1, 64, h, b, tid);

    float m0r = -INFINITY, m1r = -INFINITY;        // running max (stale ok)
    float mc0 = -INFINITY, mc1 = -INFINITY;        // candidates since update
    float ofr[8][4] = {};
    float lfr[4] = {};                             // l via MMA
    const uint32_t ONES2[2] = {0x3C003C00u, 0x3C003C00u};  // half2(1,1)

    const int r0g = q0 + w * 16 + gid;
    const int r1g = r0g + 8;
    const int rfirst = q0 + w * 16;
    const int rmax   = rfirst + 15;

    for (int t = 0; t < nt; t++) {
        const int k0 = t * 64;
        if (t + 1 < nt) { CP_WAIT1(); } else { CP_WAIT0(); }
        __syncthreads();   // single barrier: stage t ready AND stage (t-1)%3 free
        if (t + 2 < nt)
            attn_issue_kv(qkvh, vth, sbase, (t + 2) % 3, (t + 2) * 64, h, b, tid);

        if (k0 <= rmax) {   // skip tiles entirely in this warp's future
            const uint32_t ksb = sbase + ATT_Q_B + (uint32_t)(t % 3) * ATT_KV_B;
            const uint32_t vsb = ksb + 64 * 128;

            // S = Q K^T  (Q pre-scaled; 4 k16 steps over d=64)
            float sfr[8][4] = {};
#pragma unroll
            for (int ks = 0; ks < 4; ks++) {
                uint32_t a[4];
                LDSM_X4(a[0], a[1], a[2], a[3],
                        sbase + q_lane + ((uint32_t)((2 * ks + q_cb) ^ rl) << 4));
                uint32_t bf[8][2];
#pragma unroll
                for (int j = 0; j < 4; j++) {
                    uint32_t bd = ksb + kv_lane + j * 2048 +
                                  ((uint32_t)((2 * ks + kv_cb) ^ rl) << 4);
                    LDSM_X4(bf[2 * j][0], bf[2 * j][1],
                            bf[2 * j + 1][0], bf[2 * j + 1][1], bd);
                }
#pragma unroll
                for (int nf = 0; nf < 8; nf++)
                    mma_f16(sfr[nf], a, bf[nf]);
            }

            // causal mask (keys natural: c0,c1 -> 2tig, 2tig+1); gate on
            // the FIRST row of the warp strip.
            if (k0 + 63 > rfirst) {
#pragma unroll
                for (int nf = 0; nf < 8; nf++) {
                    const int ca = k0 + nf * 8 + 2 * tig;
                    if (ca     > r0g) sfr[nf][0] = -INFINITY;
                    if (ca + 1 > r0g) sfr[nf][1] = -INFINITY;
                    if (ca     > r1g) sfr[nf][2] = -INFINITY;
                    if (ca + 1 > r1g) sfr[nf][3] = -INFINITY;
                }
            }

            // accumulate local max candidates (cheap, per tile)
#pragma unroll
            for (int nf = 0; nf < 8; nf++) {
                mc0 = fmaxf(mc0, fmaxf(sfr[nf][0], sfr[nf][1]));
                mc1 = fmaxf(mc1, fmaxf(sfr[nf][2], sfr[nf][3]));
            }

            // lazy update: shfl-reduce + rescale only every 4th tile
            if ((t & 3) == 0) {
#pragma unroll
                for (int off = 1; off <= 2; off <<= 1) {
                    mc0 = fmaxf(mc0, __shfl_xor_sync(0xffffffffu, mc0, off));
                    mc1 = fmaxf(mc1, __shfl_xor_sync(0xffffffffu, mc1, off));
                }
                const float mn0 = fmaxf(m0r, mc0);
                const float mn1 = fmaxf(m1r, mc1);
                const float cr0 = ex2f(m0r - mn0);   // t=0: ex2(-inf)=0, O/l are 0
                const float cr1 = ex2f(m1r - mn1);
                m0r = mn0; m1r = mn1;
                mc0 = -INFINITY; mc1 = -INFINITY;
#pragma unroll
                for (int nf = 0; nf < 8; nf++) {
                    ofr[nf][0] *= cr0; ofr[nf][1] *= cr0;
                    ofr[nf][2] *= cr1; ofr[nf][3] *= cr1;
                }
                lfr[0] *= cr0; lfr[1] *= cr0;
                lfr[2] *= cr1; lfr[3] *= cr1;
            }

            // P = 2^(s-m) via f16x2 ex2 -> A-frags directly; l via ones-MMA.
            // Between updates m is stale: P may exceed 1 (bounded ~2^6),
            // safely inside fp16 range; O/l scale cancels exactly.
            uint32_t pa[4][4];
#pragma unroll
            for (int j = 0; j < 4; j++) {
                pa[j][0] = h2ex2(pack_half2(sfr[2 * j][0] - m0r,
                                            sfr[2 * j][1] - m0r));
                pa[j][1] = h2ex2(pack_half2(sfr[2 * j][2] - m1r,
                                            sfr[2 * j][3] - m1r));
                pa[j][2] = h2ex2(pack_half2(sfr[2 * j + 1][0] - m0r,
                                            sfr[2 * j + 1][1] - m0r));
                pa[j][3] = h2ex2(pack_half2(sfr[2 * j + 1][2] - m1r,
                                            sfr[2 * j + 1][3] - m1r));
                mma_f16(lfr, pa[j], ONES2);
            }

            // O += P @ V  (V B-frags from Vt[d][key] tile)
#pragma unroll
            for (int j = 0; j < 4; j++) {
                uint32_t bf[8][2];
#pragma unroll
                for (int jb = 0; jb < 4; jb++) {
                    uint32_t bd = vsb + kv_lane + jb * 2048 +
                                  ((uint32_t)((2 * j + kv_cb) ^ rl) << 4);
                    LDSM_X4(bf[2 * jb][0], bf[2 * jb][1],
                            bf[2 * jb + 1][0], bf[2 * jb + 1][1], bd);
                }
#pragma unroll
                for (int nf = 0; nf < 8; nf++)
                    mma_f16(ofr[nf], pa[j], bf[nf]);
            }
        }
    }

    // epilogue: every lane's lfr[0]/lfr[2] IS l for its two rows (scale
    // 2^(-m_last_update) cancels in O/l). fp16 y.
    const float inv0 = 1.0f / lfr[0];
    const float inv1 = 1.0f / lfr[2];
#pragma unroll
    for (int nf = 0; nf < 8; nf++) {
        const int c = h * 64 + nf * 8 + 2 * tig;
        *(uint32_t*)&yh[(bS + r0g) * E_ + c] =
            pack_half2(ofr[nf][0] * inv0, ofr[nf][1] * inv0);
        *(uint32_t*)&yh[(bS + r1g) * E_ + c] =
            pack_half2(ofr[nf][2] * inv1, ofr[nf][3] * inv1);
    }
}

// ===========================================================================
extern "C" void kernel_launch(void* const* d_in, const int* in_sizes, int n_in,
                              void* d_out, int out_size) {
    const float* x      = (const float*)d_in[0];   // [B, S, E]
    const float* w_att  = (const float*)d_in[1];   // [E, 3E]
    const float* w_proj = (const float*)d_in[2];   // [E, E]
    float* out = (float*)d_out;                    // [B, S, E]

    __half *xh, *qkvh, *vth, *yh, *wTh;
    cudaGetSymbolAddress((void**)&xh, g_xh);
    cudaGetSymbolAddress((void**)&qkvh, g_qkvh);
    cudaGetSymbolAddress((void**)&vth, g_vth);
    cudaGetSymbolAddress((void**)&yh, g_yh);
    cudaGetSymbolAddress((void**)&wTh, g_wTh);
    __half* wattTh  = wTh;                          // [3E, E]
    __half* wprojTh = wTh + (long long)3 * E_ * E_; // [E, E]

    cudaFuncSetAttribute(gemm_h_kernel,
                         cudaFuncAttributeMaxDynamicSharedMemorySize,
                         GEMM_SMEM_BYTES);
    cudaFuncSetAttribute(attn_h_kernel,
                         cudaFuncAttributeMaxDynamicSharedMemorySize,
                         ATT_SMEM_BYTES);

    // 0) Convert x; transpose+convert both weights (single launch)
    cvt_kernel<<<2048, 256>>>(x, xh, (long long)M_ * E_ / 4);
    {
        dim3 g(128, E_ / 32);
        transpose2_kernel<<<g, 256>>>(w_att, wattTh, w_proj, wprojTh);
    }
    // 1) QKV projection: Q (scaled) + K -> qkvh; V -> vth transposed
    {
        dim3 grid(3 * E_ / 128, M_ / 128);
        gemm_h_kernel<<<grid, 256, GEMM_SMEM_BYTES>>>(
            xh, wattTh, nullptr, qkvh, vth, M_, 3 * E_, E_, 1);
    }
    // 2) Causal flash attention -> yh (fp16)
    {
        dim3 grid(S_ / 128, H_, B_);
        attn_h_kernel<<<grid, 256, ATT_SMEM_BYTES>>>(qkvh, vth, yh);
    }
    // 3) Output projection -> fp32 out
    {
        dim3 grid(E_ / 128, M_ / 128);
        gemm_h_kernel<<<grid, 256, GEMM_SMEM_BYTES>>>(
            yh, wprojTh, out, nullptr, nullptr, M_, E_, E_, 0);
    }
}

// round 14
// speedup vs baseline: 9.5458x; 1.0138x over previous
#include <cuda_runtime.h>
#include <cuda_fp16.h>
#include <math.h>
#include <stdint.h>

// Problem constants
constexpr int B_ = 4;
constexpr int S_ = 2048;
constexpr int E_ = 1024;
constexpr int H_ = 16;
constexpr int D_ = 64;
constexpr int M_ = B_ * S_;   // 8192 tokens

// Q pre-scale: 1/sqrt(64) * log2(e)  (softmax runs in base-2)
#define QSCALE 0.180336880f

// Scratch (allocation-free rule: __device__ globals)
__device__ __half g_xh[(long long)M_ * E_];          // x in fp16
__device__ __half g_qkvh[(long long)M_ * 2 * E_];    // Q(pre-scaled)|K, fp16
__device__ __half g_vth[(long long)E_ * M_];         // V transposed [h*64+d][token]
__device__ __half g_yh[(long long)M_ * E_];          // attention out, fp16
__device__ __half g_wTh[(long long)3 * E_ * E_ + (long long)E_ * E_]; // W^T fp16

__device__ __forceinline__ float ex2f(float x) {
    float r; asm("ex2.approx.f32 %0, %1;" : "=f"(r) : "f"(x)); return r;
}
__device__ __forceinline__ uint32_t h2ex2(uint32_t x) {   // ex2 on packed half2
    uint32_t r; asm("ex2.approx.f16x2 %0, %1;" : "=r"(r) : "r"(x)); return r;
}
__device__ __forceinline__ uint32_t pack_half2(float lo, float hi) {
    uint32_t r;
    asm("cvt.rn.f16x2.f32 %0, %1, %2;" : "=r"(r) : "f"(hi), "f"(lo));
    return r;
}
__device__ __forceinline__ uint32_t smem_u32(const void* p) {
    uint32_t a;
    asm("{ .reg .u64 t; cvta.to.shared.u64 t, %1; cvt.u32.u64 %0, t; }"
        : "=r"(a) : "l"(p));
    return a;
}

#define CP_ASYNC16(dst, src) \
    asm volatile("cp.async.cg.shared.global [%0], [%1], 16;" \
        :: "r"(dst), "l"(src))
#define CP_COMMIT() asm volatile("cp.async.commit_group;" ::: "memory")
#define CP_WAIT0()  asm volatile("cp.async.wait_group 0;" ::: "memory")
#define CP_WAIT1()  asm volatile("cp.async.wait_group 1;" ::: "memory")

#define LDSM_X4(r0, r1, r2, r3, addr) \
    asm volatile("ldmatrix.sync.aligned.m8n8.x4.shared.b16 {%0,%1,%2,%3}, [%4];" \
        : "=r"(r0), "=r"(r1), "=r"(r2), "=r"(r3) : "r"(addr))

// m16n8k16 fp16 MMA, fp32 accumulate (sm_80+; Blackwell tensor pipe)
__device__ __forceinline__ void mma_f16(float d[4], const uint32_t a[4],
                                        const uint32_t b[2]) {
    asm volatile(
        "mma.sync.aligned.m16n8k16.row.col.f32.f16.f16.f32 "
        "{%0,%1,%2,%3}, {%4,%5,%6,%7}, {%8,%9}, {%0,%1,%2,%3};\n"
        : "+f"(d[0]), "+f"(d[1]), "+f"(d[2]), "+f"(d[3])
        : "r"(a[0]), "r"(a[1]), "r"(a[2]), "r"(a[3]), "r"(b[0]), "r"(b[1]));
}

// ===========================================================================
// x -> fp16
// ===========================================================================
__global__ void __launch_bounds__(256) cvt_kernel(
    const float* __restrict__ X, __half* __restrict__ XH, long long n4) {
    long long i = blockIdx.x * 256 + threadIdx.x;
    long long stride = (long long)gridDim.x * 256;
    for (; i < n4; i += stride) {
        float4 v = ((const float4*)X)[i];
        ((uint2*)XH)[i] = make_uint2(pack_half2(v.x, v.y), pack_half2(v.z, v.w));
    }
}

// ===========================================================================
// Fused weight transpose + fp16 for BOTH weights in one launch.
// blocks x in [0,96): w_att (N=3072); [96,128): w_proj (N=1024). K=1024.
// ===========================================================================
__global__ void __launch_bounds__(256) transpose2_kernel(
    const float* __restrict__ Wa, __half* __restrict__ WaT,
    const float* __restrict__ Wp, __half* __restrict__ WpT) {
    __shared__ float t[32][33];
    const bool isA = (blockIdx.x < 96);
    const float* W = isA ? Wa : Wp;
    __half* WT     = isA ? WaT : WpT;
    const int N    = isA ? 3 * E_ : E_;
    const int n0   = (isA ? blockIdx.x : blockIdx.x - 96) * 32;
    const int k0   = blockIdx.y * 32;
    const int tx = threadIdx.x & 31, ty = threadIdx.x >> 5;
    for (int r = ty; r < 32; r += 8)
        t[r][tx] = W[(long long)(k0 + r) * N + n0 + tx];
    __syncthreads();
    for (int r = ty; r < 32; r += 8)
        WT[(long long)(n0 + r) * E_ + k0 + tx] = __float2half_rn(t[tx][r]);
}

// ===========================================================================
// fp16 mma.sync GEMM, 3-stage cp.async pipeline, ldmatrix fragment loads.
// C = A[M,K] @ BT[N,K]^T, fp16 operands, fp32 accum.
// 128x128x64 tile (BK=64 halves = 128B rows), 8 warps (2x4), warp 64x32.
// mode 0: fp32 out to Cf.
// mode 1 (QKV): n0<1024 -> Q (scale by QSCALE, half -> Ch);
//               n0<2048 -> K (half -> Ch); else V -> VT transposed.
// ===========================================================================
constexpr int BK = 64;                          // halves per chunk (128B)
constexpr int GSTAGE_B = 2 * 128 * 128;         // A + B tile bytes = 32768
constexpr int GEMM_SMEM_BYTES = 3 * GSTAGE_B;   // 98304

__device__ __forceinline__ void gemm_issue(
    const __half* __restrict__ A, const __half* __restrict__ BT,
    uint32_t sbase, int stage, int m0, int n0, int k0, int K, int tid) {
    uint32_t st = sbase + stage * GSTAGE_B;
#pragma unroll
    for (int it = 0; it < 4; it++) {
        int idx = tid + it * 256;          // 0..1023
        int row = idx >> 3;                // 0..127
        int c   = idx & 7;                 // 16B chunk
        uint32_t off = (uint32_t)(row * 8 + (c ^ (row & 7))) * 16;
        CP_ASYNC16(st + off, A + (long long)(m0 + row) * K + k0 + c * 8);
        CP_ASYNC16(st + 16384 + off, BT + (long long)(n0 + row) * K + k0 + c * 8);
    }
    CP_COMMIT();
}

__global__ void __launch_bounds__(256, 2) gemm_h_kernel(
    const __half* __restrict__ A, const __half* __restrict__ BT,
    float* __restrict__ Cf, __half* __restrict__ Ch, __half* __restrict__ VT,
    int M, int N, int K, int mode) {
    extern __shared__ char smc[];
    const uint32_t sbase = smem_u32(smc);

    const int tid  = threadIdx.x;
    const int wid  = tid >> 5;
    const int lane = tid & 31;
    const int gid  = lane >> 2;
    const int tig  = lane & 3;
    const int wm   = (wid & 1) * 64;
    const int wn   = (wid >> 1) * 32;
    const int m0   = blockIdx.y * 128;
    const int n0   = blockIdx.x * 128;

    const int rl = lane & 7;
    const uint32_t a_lane = (uint32_t)((wm + ((lane >> 3) & 1) * 8 + rl) * 128);
    const int a_cb = lane >> 4;
    const uint32_t b_lane = 16384u + (uint32_t)((wn + ((lane >> 4) & 1) * 8 + rl) * 128);
    const int b_cb = (lane >> 3) & 1;

    float acc[4][4][4] = {};

    const int NIT = K / BK;
    gemm_issue(A, BT, sbase, 0, m0, n0, 0, K, tid);
    gemm_issue(A, BT, sbase, 1, m0, n0, BK, K, tid);

    for (int i = 0; i < NIT; i++) {
        if (i + 1 < NIT) { CP_WAIT1(); } else { CP_WAIT0(); }
        __syncthreads();
        if (i + 2 < NIT)
            gemm_issue(A, BT, sbase, (i + 2) % 3, m0, n0, (i + 2) * BK, K, tid);

        const uint32_t stb = sbase + (uint32_t)(i % 3) * GSTAGE_B;
#pragma unroll
        for (int ks = 0; ks < 4; ks++) {       // 4 k16 steps per BK=64
            uint32_t af[4][4], bf[4][2];
#pragma unroll
            for (int mf = 0; mf < 4; mf++) {
                uint32_t ad = stb + a_lane + mf * 2048 +
                              ((uint32_t)((2 * ks + a_cb) ^ rl) << 4);
                LDSM_X4(af[mf][0], af[mf][1], af[mf][2], af[mf][3], ad);
            }
#pragma unroll
            for (int j = 0; j < 2; j++) {
                uint32_t bd = stb + b_lane + j * 2048 +
                              ((uint32_t)((2 * ks + b_cb) ^ rl) << 4);
                LDSM_X4(bf[2 * j][0], bf[2 * j][1], bf[2 * j + 1][0], bf[2 * j + 1][1], bd);
            }
#pragma unroll
            for (int mf = 0; mf < 4; mf++)
#pragma unroll
                for (int nf = 0; nf < 4; nf++)
                    mma_f16(acc[mf][nf], af[mf], bf[nf]);
        }
    }

    // epilogue
    if (mode == 0) {
#pragma unroll
        for (int mf = 0; mf < 4; mf++) {
            const int r0 = m0 + wm + mf * 16 + gid;
#pragma unroll
            for (int nf = 0; nf < 4; nf++) {
                const int c = n0 + wn + nf * 8 + 2 * tig;
                *(float2*)&Cf[(long long)r0 * N + c] =
                    make_float2(acc[mf][nf][0], acc[mf][nf][1]);
                *(float2*)&Cf[(long long)(r0 + 8) * N + c] =
                    make_float2(acc[mf][nf][2], acc[mf][nf][3]);
            }
        }
    } else {
        const int region = n0 >> 10;   // 0:Q 1:K 2:V
        if (region < 2) {
            const float s = (region == 0) ? QSCALE : 1.0f;
#pragma unroll
            for (int mf = 0; mf < 4; mf++) {
                const int r0 = m0 + wm + mf * 16 + gid;
#pragma unroll
                for (int nf = 0; nf < 4; nf++) {
                    const int c = n0 + wn + nf * 8 + 2 * tig;
                    *(uint32_t*)&Ch[(long long)r0 * 2048 + c] =
                        pack_half2(acc[mf][nf][0] * s, acc[mf][nf][1] * s);
                    *(uint32_t*)&Ch[(long long)(r0 + 8) * 2048 + c] =
                        pack_half2(acc[mf][nf][2] * s, acc[mf][nf][3] * s);
                }
            }
        } else {
#pragma unroll
            for (int mf = 0; mf < 4; mf++) {
                const int r0 = m0 + wm + mf * 16 + gid;
#pragma unroll
                for (int nf = 0; nf < 4; nf++) {
                    const long long cv = n0 + wn + nf * 8 + 2 * tig - 2048;
                    VT[cv * M_ + r0]           = __float2half_rn(acc[mf][nf][0]);
                    VT[(cv + 1) * M_ + r0]     = __float2half_rn(acc[mf][nf][1]);
                    VT[cv * M_ + r0 + 8]       = __float2half_rn(acc[mf][nf][2]);
                    VT[(cv + 1) * M_ + r0 + 8] = __float2half_rn(acc[mf][nf][3]);
                }
            }
        }
    }
}

// ===========================================================================
// Causal flash attention, fp16 m16n8k16.
// R14: KT=128 keys per pipeline stage (two 16KB [K|V] subtile blocks),
// 3-stage ring, ONE barrier per 128 keys (half the barrier density of R13).
// smem = 16KB Q + 3*32KB = 112KB/CTA -> still 2 CTAs/SM (226 <= 228KB).
// Lazy softmax-max (period 4 subtiles), exp via f16x2 ex2 -> P A-frags,
// l via ones-MMA. Heavy q-tiles first; per-warp monotone subtile skip.
// Block 256 (8 warps), Q 128 rows. Grid (S/128, H, B).
// ===========================================================================
constexpr int ATT_Q_B     = 128 * 128;            // 16384
constexpr int ATT_STAGE_B = 2 * (8192 + 8192);    // [K0|V0|K1|V1] = 32768
constexpr int ATT_SMEM_BYTES = ATT_Q_B + 3 * ATT_STAGE_B;  // 114688 (112KB)

__device__ __forceinline__ void attn_issue_kv128(
    const __half* __restrict__ qkvh, const __half* __restrict__ vth,
    uint32_t sbase, int stage, int k0, int h, int b, int tid) {
    uint32_t st = sbase + ATT_Q_B + stage * ATT_STAGE_B;
    const long long bS = (long long)b * S_;
#pragma unroll
    for (int it = 0; it < 8; it++) {
        int idx = tid + (it & 1) * 256;    // 0..511
        int row = idx >> 3;                // 0..63
        int c   = idx & 7;
        uint32_t off = (uint32_t)(row * 8 + (c ^ (row & 7))) * 16;
        const int half = (it >> 1) & 1;    // subtile within stage
        if (it < 4) {                      // K: [half*16384 + 0 .. 8192)
            CP_ASYNC16(st + half * 16384 + off,
                       qkvh + (bS + k0 + half * 64 + row) * 2048 + 1024 + h * 64 + c * 8);
        } else {                           // V: [half*16384 + 8192 ..)
            CP_ASYNC16(st + half * 16384 + 8192 + off,
                       vth + (long long)(h * 64 + row) * M_ + bS + k0 + half * 64 + c * 8);
        }
    }
    CP_COMMIT();
}

__global__ void __launch_bounds__(256, 2) attn_h_kernel(
    const __half* __restrict__ qkvh, const __half* __restrict__ vth,
    __half* __restrict__ yh) {
    extern __shared__ char smc[];
    const uint32_t sbase = smem_u32(smc);

    const int tid  = threadIdx.x;
    const int w    = tid >> 5;
    const int lane = tid & 31;
    const int gid  = lane >> 2;
    const int tig  = lane & 3;
    const int qt   = gridDim.x - 1 - blockIdx.x;     // heavy tiles first
    const int h    = blockIdx.y;
    const int b    = blockIdx.z;
    const int q0   = qt * 128;
    const int niter = qt + 1;                        // 128-key iterations
    const long long bS = (long long)b * S_;

    const int rl = lane & 7;
    const uint32_t q_lane  = (uint32_t)((w * 16 + ((lane >> 3) & 1) * 8 + rl) * 128);
    const int      q_cb    = lane >> 4;
    const uint32_t kv_lane = (uint32_t)((((lane >> 4) & 1) * 8 + rl) * 128);
    const int      kv_cb   = (lane >> 3) & 1;

    // prologue: groups [kv0][Q][kv1] — WAIT1 at t=0 covers kv0 AND Q.
    attn_issue_kv128(qkvh, vth, sbase, 0, 0, h, b, tid);
#pragma unroll
    for (int it = 0; it < 4; it++) {
        int idx = tid + it * 256;          // 0..1023
        int row = idx >> 3;                // 0..127
        int c   = idx & 7;
        uint32_t off = (uint32_t)(row * 8 + (c ^ (row & 7))) * 16;
        CP_ASYNC16(sbase + off,
                   qkvh + (bS + q0 + row) * 2048 + h * 64 + c * 8);
    }
    CP_COMMIT();
    if (niter > 1) attn_issue_kv128(qkvh, vth, sbase, 1, 128, h, b, tid);

    float m0r = -INFINITY, m1r = -INFINITY;        // running max (stale ok)
    float mc0 = -INFINITY, mc1 = -INFINITY;        // candidates since update
    float ofr[8][4] = {};
    float lfr[4] = {};                             // l via MMA
    const uint32_t ONES2[2] = {0x3C003C00u, 0x3C003C00u};  // half2(1,1)

    const int r0g = q0 + w * 16 + gid;
    const int r1g = r0g + 8;
    const int rfirst = q0 + w * 16;
    const int rmax   = rfirst + 15;

    for (int t = 0; t < niter; t++) {
        if (t + 1 < niter) { CP_WAIT1(); } else { CP_WAIT0(); }
        __syncthreads();   // stage t ready AND stage (t-1)%3 readers done
        if (t + 2 < niter)
            attn_issue_kv128(qkvh, vth, sbase, (t + 2) % 3, (t + 2) * 128, h, b, tid);

        const uint32_t stg = sbase + ATT_Q_B + (uint32_t)(t % 3) * ATT_STAGE_B;

#pragma unroll
        for (int half = 0; half < 2; half++) {
            const int k0 = t * 128 + half * 64;
            if (k0 > rmax) break;          // monotone per-warp skip
            const int u = 2 * t + half;    // global subtile index
            const uint32_t ksb = stg + (uint32_t)half * 16384;
            const uint32_t vsb = ksb + 8192;

            // S = Q K^T  (Q pre-scaled; 4 k16 steps over d=64)
            float sfr[8][4] = {};
#pragma unroll
            for (int ks = 0; ks < 4; ks++) {
                uint32_t a[4];
                LDSM_X4(a[0], a[1], a[2], a[3],
                        sbase + q_lane + ((uint32_t)((2 * ks + q_cb) ^ rl) << 4));
                uint32_t bf[8][2];
#pragma unroll
                for (int j = 0; j < 4; j++) {
                    uint32_t bd = ksb + kv_lane + j * 2048 +
                                  ((uint32_t)((2 * ks + kv_cb) ^ rl) << 4);
                    LDSM_X4(bf[2 * j][0], bf[2 * j][1],
                            bf[2 * j + 1][0], bf[2 * j + 1][1], bd);
                }
#pragma unroll
                for (int nf = 0; nf < 8; nf++)
                    mma_f16(sfr[nf], a, bf[nf]);
            }

            // causal mask (keys natural: c0,c1 -> 2tig, 2tig+1); gate on
            // the FIRST row of the warp strip.
            if (k0 + 63 > rfirst) {
#pragma unroll
                for (int nf = 0; nf < 8; nf++) {
                    const int ca = k0 + nf * 8 + 2 * tig;
                    if (ca     > r0g) sfr[nf][0] = -INFINITY;
                    if (ca + 1 > r0g) sfr[nf][1] = -INFINITY;
                    if (ca     > r1g) sfr[nf][2] = -INFINITY;
                    if (ca + 1 > r1g) sfr[nf][3] = -INFINITY;
                }
            }

            // accumulate local max candidates
#pragma unroll
            for (int nf = 0; nf < 8; nf++) {
                mc0 = fmaxf(mc0, fmaxf(sfr[nf][0], sfr[nf][1]));
                mc1 = fmaxf(mc1, fmaxf(sfr[nf][2], sfr[nf][3]));
            }

            // lazy update: shfl-reduce + rescale every 4th subtile
            if ((u & 3) == 0) {
#pragma unroll
                for (int off = 1; off <= 2; off <<= 1) {
                    mc0 = fmaxf(mc0, __shfl_xor_sync(0xffffffffu, mc0, off));
                    mc1 = fmaxf(mc1, __shfl_xor_sync(0xffffffffu, mc1, off));
                }
                const float mn0 = fmaxf(m0r, mc0);
                const float mn1 = fmaxf(m1r, mc1);
                const float cr0 = ex2f(m0r - mn0);   // u=0: ex2(-inf)=0, O/l are 0
                const float cr1 = ex2f(m1r - mn1);
                m0r = mn0; m1r = mn1;
                mc0 = -INFINITY; mc1 = -INFINITY;
#pragma unroll
                for (int nf = 0; nf < 8; nf++) {
                    ofr[nf][0] *= cr0; ofr[nf][1] *= cr0;
                    ofr[nf][2] *= cr1; ofr[nf][3] *= cr1;
                }
                lfr[0] *= cr0; lfr[1] *= cr0;
                lfr[2] *= cr1; lfr[3] *= cr1;
            }

            // P = 2^(s-m) via f16x2 ex2 -> A-frags; l via ones-MMA.
            // Stale m bounded (~2^6) -> safe in fp16; scale cancels in O/l.
            uint32_t pa[4][4];
#pragma unroll
            for (int j = 0; j < 4; j++) {
                pa[j][0] = h2ex2(pack_half2(sfr[2 * j][0] - m0r,
                                            sfr[2 * j][1] - m0r));
                pa[j][1] = h2ex2(pack_half2(sfr[2 * j][2] - m1r,
                                            sfr[2 * j][3] - m1r));
                pa[j][2] = h2ex2(pack_half2(sfr[2 * j + 1][0] - m0r,
                                            sfr[2 * j + 1][1] - m0r));
                pa[j][3] = h2ex2(pack_half2(sfr[2 * j + 1][2] - m1r,
                                            sfr[2 * j + 1][3] - m1r));
                mma_f16(lfr, pa[j], ONES2);
            }

            // O += P @ V  (V B-frags from Vt[d][key] subtile)
#pragma unroll
            for (int j = 0; j < 4; j++) {
                uint32_t bf[8][2];
#pragma unroll
                for (int jb = 0; jb < 4; jb++) {
                    uint32_t bd = vsb + kv_lane + jb * 2048 +
                                  ((uint32_t)((2 * j + kv_cb) ^ rl) << 4);
                    LDSM_X4(bf[2 * jb][0], bf[2 * jb][1],
                            bf[2 * jb + 1][0], bf[2 * jb + 1][1], bd);
                }
#pragma unroll
                for (int nf = 0; nf < 8; nf++)
                    mma_f16(ofr[nf], pa[j], bf[nf]);
            }
        }
    }

    // epilogue: lane's lfr[0]/lfr[2] IS l for its two rows (2^-m cancels)
    const float inv0 = 1.0f / lfr[0];
    const float inv1 = 1.0f / lfr[2];
#pragma unroll
    for (int nf = 0; nf < 8; nf++) {
        const int c = h * 64 + nf * 8 + 2 * tig;
        *(uint32_t*)&yh[(bS + r0g) * E_ + c] =
            pack_half2(ofr[nf][0] * inv0, ofr[nf][1] * inv0);
        *(uint32_t*)&yh[(bS + r1g) * E_ + c] =
            pack_half2(ofr[nf][2] * inv1, ofr[nf][3] * inv1);
    }
}

// ===========================================================================
extern "C" void kernel_launch(void* const* d_in, const int* in_sizes, int n_in,
                              void* d_out, int out_size) {
    const float* x      = (const float*)d_in[0];   // [B, S, E]
    const float* w_att  = (const float*)d_in[1];   // [E, 3E]
    const float* w_proj = (const float*)d_in[2];   // [E, E]
    float* out = (float*)d_out;                    // [B, S, E]

    __half *xh, *qkvh, *vth, *yh, *wTh;
    cudaGetSymbolAddress((void**)&xh, g_xh);
    cudaGetSymbolAddress((void**)&qkvh, g_qkvh);
    cudaGetSymbolAddress((void**)&vth, g_vth);
    cudaGetSymbolAddress((void**)&yh, g_yh);
    cudaGetSymbolAddress((void**)&wTh, g_wTh);
    __half* wattTh  = wTh;                          // [3E, E]
    __half* wprojTh = wTh + (long long)3 * E_ * E_; // [E, E]

    cudaFuncSetAttribute(gemm_h_kernel,
                         cudaFuncAttributeMaxDynamicSharedMemorySize,
                         GEMM_SMEM_BYTES);
    cudaFuncSetAttribute(attn_h_kernel,
                         cudaFuncAttributeMaxDynamicSharedMemorySize,
                         ATT_SMEM_BYTES);

    // 0) Convert x; transpose+convert both weights (single launch)
    cvt_kernel<<<2048, 256>>>(x, xh, (long long)M_ * E_ / 4);
    {
        dim3 g(128, E_ / 32);
        transpose2_kernel<<<g, 256>>>(w_att, wattTh, w_proj, wprojTh);
    }
    // 1) QKV projection: Q (scaled) + K -> qkvh; V -> vth transposed
    {
        dim3 grid(3 * E_ / 128, M_ / 128);
        gemm_h_kernel<<<grid, 256, GEMM_SMEM_BYTES>>>(
            xh, wattTh, nullptr, qkvh, vth, M_, 3 * E_, E_, 1);
    }
    // 2) Causal flash attention -> yh (fp16)
    {
        dim3 grid(S_ / 128, H_, B_);
        attn_h_kernel<<<grid, 256, ATT_SMEM_BYTES>>>(qkvh, vth, yh);
    }
    // 3) Output projection -> fp32 out
    {
        dim3 grid(E_ / 128, M_ / 128);
        gemm_h_kernel<<<grid, 256, GEMM_SMEM_BYTES>>>(
            yh, wprojTh, out, nullptr, nullptr, M_, E_, E_, 0);
    }
}

// round 15
// speedup vs baseline: 9.6474x; 1.0106x over previous
#include <cuda_runtime.h>
#include <cuda_fp16.h>
#include <math.h>
#include <stdint.h>

// Problem constants
constexpr int B_ = 4;
constexpr int S_ = 2048;
constexpr int E_ = 1024;
constexpr int H_ = 16;
constexpr int D_ = 64;
constexpr int M_ = B_ * S_;   // 8192 tokens

// Q pre-scale: 1/sqrt(64) * log2(e)  (softmax runs in base-2)
#define QSCALE 0.180336880f

// Scratch (allocation-free rule: __device__ globals)
__device__ __half g_xh[(long long)M_ * E_];          // x in fp16
__device__ __half g_qkvh[(long long)M_ * 2 * E_];    // Q(pre-scaled)|K, fp16
__device__ __half g_vth[(long long)E_ * M_];         // V transposed [h*64+d][token]
__device__ __half g_yh[(long long)M_ * E_];          // attention out, fp16
__device__ __half g_wTh[(long long)3 * E_ * E_ + (long long)E_ * E_]; // W^T fp16

__device__ __forceinline__ float ex2f(float x) {
    float r; asm("ex2.approx.f32 %0, %1;" : "=f"(r) : "f"(x)); return r;
}
__device__ __forceinline__ uint32_t h2ex2(uint32_t x) {   // ex2 on packed half2
    uint32_t r; asm("ex2.approx.f16x2 %0, %1;" : "=r"(r) : "r"(x)); return r;
}
__device__ __forceinline__ uint32_t pack_half2(float lo, float hi) {
    uint32_t r;
    asm("cvt.rn.f16x2.f32 %0, %1, %2;" : "=r"(r) : "f"(hi), "f"(lo));
    return r;
}
__device__ __forceinline__ uint32_t smem_u32(const void* p) {
    uint32_t a;
    asm("{ .reg .u64 t; cvta.to.shared.u64 t, %1; cvt.u32.u64 %0, t; }"
        : "=r"(a) : "l"(p));
    return a;
}

#define CP_ASYNC16(dst, src) \
    asm volatile("cp.async.cg.shared.global [%0], [%1], 16;" \
        :: "r"(dst), "l"(src))
#define CP_COMMIT() asm volatile("cp.async.commit_group;" ::: "memory")
#define CP_WAIT0()  asm volatile("cp.async.wait_group 0;" ::: "memory")
#define CP_WAIT1()  asm volatile("cp.async.wait_group 1;" ::: "memory")

#define LDSM_X4(r0, r1, r2, r3, addr) \
    asm volatile("ldmatrix.sync.aligned.m8n8.x4.shared.b16 {%0,%1,%2,%3}, [%4];" \
        : "=r"(r0), "=r"(r1), "=r"(r2), "=r"(r3) : "r"(addr))

// m16n8k16 fp16 MMA, fp32 accumulate (sm_80+; Blackwell tensor pipe)
__device__ __forceinline__ void mma_f16(float d[4], const uint32_t a[4],
                                        const uint32_t b[2]) {
    asm volatile(
        "mma.sync.aligned.m16n8k16.row.col.f32.f16.f16.f32 "
        "{%0,%1,%2,%3}, {%4,%5,%6,%7}, {%8,%9}, {%0,%1,%2,%3};\n"
        : "+f"(d[0]), "+f"(d[1]), "+f"(d[2]), "+f"(d[3])
        : "r"(a[0]), "r"(a[1]), "r"(a[2]), "r"(a[3]), "r"(b[0]), "r"(b[1]));
}

// ===========================================================================
// x -> fp16
// ===========================================================================
__global__ void __launch_bounds__(256) cvt_kernel(
    const float* __restrict__ X, __half* __restrict__ XH, long long n4) {
    long long i = blockIdx.x * 256 + threadIdx.x;
    long long stride = (long long)gridDim.x * 256;
    for (; i < n4; i += stride) {
        float4 v = ((const float4*)X)[i];
        ((uint2*)XH)[i] = make_uint2(pack_half2(v.x, v.y), pack_half2(v.z, v.w));
    }
}

// ===========================================================================
// Fused weight transpose + fp16 for BOTH weights in one launch.
// blocks x in [0,96): w_att (N=3072); [96,128): w_proj (N=1024). K=1024.
// ===========================================================================
__global__ void __launch_bounds__(256) transpose2_kernel(
    const float* __restrict__ Wa, __half* __restrict__ WaT,
    const float* __restrict__ Wp, __half* __restrict__ WpT) {
    __shared__ float t[32][33];
    const bool isA = (blockIdx.x < 96);
    const float* W = isA ? Wa : Wp;
    __half* WT     = isA ? WaT : WpT;
    const int N    = isA ? 3 * E_ : E_;
    const int n0   = (isA ? blockIdx.x : blockIdx.x - 96) * 32;
    const int k0   = blockIdx.y * 32;
    const int tx = threadIdx.x & 31, ty = threadIdx.x >> 5;
    for (int r = ty; r < 32; r += 8)
        t[r][tx] = W[(long long)(k0 + r) * N + n0 + tx];
    __syncthreads();
    for (int r = ty; r < 32; r += 8)
        WT[(long long)(n0 + r) * E_ + k0 + tx] = __float2half_rn(t[tx][r]);
}

// ===========================================================================
// fp16 mma.sync GEMM, 3-stage cp.async pipeline, ldmatrix fragment loads.
// C = A[M,K] @ BT[N,K]^T, fp16 operands, fp32 accum.
// 128x128x64 tile (BK=64 halves = 128B rows), 8 warps (2x4), warp 64x32.
// mode 0: fp32 out to Cf.
// mode 1 (QKV): n0<1024 -> Q (scale by QSCALE, half -> Ch);
//               n0<2048 -> K (half -> Ch); else V -> VT transposed.
// ===========================================================================
constexpr int BK = 64;                          // halves per chunk (128B)
constexpr int GSTAGE_B = 2 * 128 * 128;         // A + B tile bytes = 32768
constexpr int GEMM_SMEM_BYTES = 3 * GSTAGE_B;   // 98304

__device__ __forceinline__ void gemm_issue(
    const __half* __restrict__ A, const __half* __restrict__ BT,
    uint32_t sbase, int stage, int m0, int n0, int k0, int K, int tid) {
    uint32_t st = sbase + stage * GSTAGE_B;
#pragma unroll
    for (int it = 0; it < 4; it++) {
        int idx = tid + it * 256;          // 0..1023
        int row = idx >> 3;                // 0..127
        int c   = idx & 7;                 // 16B chunk
        uint32_t off = (uint32_t)(row * 8 + (c ^ (row & 7))) * 16;
        CP_ASYNC16(st + off, A + (long long)(m0 + row) * K + k0 + c * 8);
        CP_ASYNC16(st + 16384 + off, BT + (long long)(n0 + row) * K + k0 + c * 8);
    }
    CP_COMMIT();
}

__global__ void __launch_bounds__(256, 2) gemm_h_kernel(
    const __half* __restrict__ A, const __half* __restrict__ BT,
    float* __restrict__ Cf, __half* __restrict__ Ch, __half* __restrict__ VT,
    int M, int N, int K, int mode) {
    extern __shared__ char smc[];
    const uint32_t sbase = smem_u32(smc);

    const int tid  = threadIdx.x;
    const int wid  = tid >> 5;
    const int lane = tid & 31;
    const int gid  = lane >> 2;
    const int tig  = lane & 3;
    const int wm   = (wid & 1) * 64;
    const int wn   = (wid >> 1) * 32;
    const int m0   = blockIdx.y * 128;
    const int n0   = blockIdx.x * 128;

    const int rl = lane & 7;
    const uint32_t a_lane = (uint32_t)((wm + ((lane >> 3) & 1) * 8 + rl) * 128);
    const int a_cb = lane >> 4;
    const uint32_t b_lane = 16384u + (uint32_t)((wn + ((lane >> 4) & 1) * 8 + rl) * 128);
    const int b_cb = (lane >> 3) & 1;

    float acc[4][4][4] = {};

    const int NIT = K / BK;
    gemm_issue(A, BT, sbase, 0, m0, n0, 0, K, tid);
    gemm_issue(A, BT, sbase, 1, m0, n0, BK, K, tid);

    for (int i = 0; i < NIT; i++) {
        if (i + 1 < NIT) { CP_WAIT1(); } else { CP_WAIT0(); }
        __syncthreads();
        if (i + 2 < NIT)
            gemm_issue(A, BT, sbase, (i + 2) % 3, m0, n0, (i + 2) * BK, K, tid);

        const uint32_t stb = sbase + (uint32_t)(i % 3) * GSTAGE_B;
#pragma unroll
        for (int ks = 0; ks < 4; ks++) {       // 4 k16 steps per BK=64
            uint32_t af[4][4], bf[4][2];
#pragma unroll
            for (int mf = 0; mf < 4; mf++) {
                uint32_t ad = stb + a_lane + mf * 2048 +
                              ((uint32_t)((2 * ks + a_cb) ^ rl) << 4);
                LDSM_X4(af[mf][0], af[mf][1], af[mf][2], af[mf][3], ad);
            }
#pragma unroll
            for (int j = 0; j < 2; j++) {
                uint32_t bd = stb + b_lane + j * 2048 +
                              ((uint32_t)((2 * ks + b_cb) ^ rl) << 4);
                LDSM_X4(bf[2 * j][0], bf[2 * j][1], bf[2 * j + 1][0], bf[2 * j + 1][1], bd);
            }
#pragma unroll
            for (int mf = 0; mf < 4; mf++)
#pragma unroll
                for (int nf = 0; nf < 4; nf++)
                    mma_f16(acc[mf][nf], af[mf], bf[nf]);
        }
    }

    // epilogue
    if (mode == 0) {
#pragma unroll
        for (int mf = 0; mf < 4; mf++) {
            const int r0 = m0 + wm + mf * 16 + gid;
#pragma unroll
            for (int nf = 0; nf < 4; nf++) {
                const int c = n0 + wn + nf * 8 + 2 * tig;
                *(float2*)&Cf[(long long)r0 * N + c] =
                    make_float2(acc[mf][nf][0], acc[mf][nf][1]);
                *(float2*)&Cf[(long long)(r0 + 8) * N + c] =
                    make_float2(acc[mf][nf][2], acc[mf][nf][3]);
            }
        }
    } else {
        const int region = n0 >> 10;   // 0:Q 1:K 2:V
        if (region < 2) {
            const float s = (region == 0) ? QSCALE : 1.0f;
#pragma unroll
            for (int mf = 0; mf < 4; mf++) {
                const int r0 = m0 + wm + mf * 16 + gid;
#pragma unroll
                for (int nf = 0; nf < 4; nf++) {
                    const int c = n0 + wn + nf * 8 + 2 * tig;
                    *(uint32_t*)&Ch[(long long)r0 * 2048 + c] =
                        pack_half2(acc[mf][nf][0] * s, acc[mf][nf][1] * s);
                    *(uint32_t*)&Ch[(long long)(r0 + 8) * 2048 + c] =
                        pack_half2(acc[mf][nf][2] * s, acc[mf][nf][3] * s);
                }
            }
        } else {
#pragma unroll
            for (int mf = 0; mf < 4; mf++) {
                const int r0 = m0 + wm + mf * 16 + gid;
#pragma unroll
                for (int nf = 0; nf < 4; nf++) {
                    const long long cv = n0 + wn + nf * 8 + 2 * tig - 2048;
                    VT[cv * M_ + r0]           = __float2half_rn(acc[mf][nf][0]);
                    VT[(cv + 1) * M_ + r0]     = __float2half_rn(acc[mf][nf][1]);
                    VT[cv * M_ + r0 + 8]       = __float2half_rn(acc[mf][nf][2]);
                    VT[(cv + 1) * M_ + r0 + 8] = __float2half_rn(acc[mf][nf][3]);
                }
            }
        }
    }
}

// ===========================================================================
// Causal flash attention, fp16 m16n8k16.
// R15: 128-thread CTAs (4 warps, 64 q-rows), KT=64, 3-stage ring ->
//   smem 8KB Q + 48KB = 56KB/CTA -> 4 CTAs/SM (was 2): same 16 warps/SM
//   but 4 independent barrier domains, phase-offset CTAs fill the tensor
//   pipe during each other's softmax/sync.
// Lazy softmax-max (period 4 tiles) with explicit fmax tree; exp via
// f16x2 ex2 -> P A-frags; l via ones-MMA. Heavy q-tiles first.
// Grid (S/64, H, B).
// ===========================================================================
constexpr int ATT_Q_B     = 64 * 128;             // 8192
constexpr int ATT_KV_B    = 2 * 64 * 128;         // K + V one stage = 16384
constexpr int ATT_SMEM_BYTES = ATT_Q_B + 3 * ATT_KV_B;  // 57344 (56KB)

__device__ __forceinline__ void attn_issue_kv(
    const __half* __restrict__ qkvh, const __half* __restrict__ vth,
    uint32_t sbase, int stage, int k0, int h, int b, int tid) {
    uint32_t kst = sbase + ATT_Q_B + stage * ATT_KV_B;
    uint32_t vst = kst + 64 * 128;
    const long long bS = (long long)b * S_;
#pragma unroll
    for (int it = 0; it < 8; it++) {
        int idx = tid + (it & 3) * 128;    // 0..511
        int row = idx >> 3;                // 0..63
        int c   = idx & 7;
        uint32_t off = (uint32_t)(row * 8 + (c ^ (row & 7))) * 16;
        if (it < 4) {
            CP_ASYNC16(kst + off,
                       qkvh + (bS + k0 + row) * 2048 + 1024 + h * 64 + c * 8);
        } else {
            CP_ASYNC16(vst + off,
                       vth + (long long)(h * 64 + row) * M_ + bS + k0 + c * 8);
        }
    }
    CP_COMMIT();
}

__global__ void __launch_bounds__(128, 4) attn_h_kernel(
    const __half* __restrict__ qkvh, const __half* __restrict__ vth,
    __half* __restrict__ yh) {
    extern __shared__ char smc[];
    const uint32_t sbase = smem_u32(smc);

    const int tid  = threadIdx.x;
    const int w    = tid >> 5;                       // 0..3
    const int lane = tid & 31;
    const int gid  = lane >> 2;
    const int tig  = lane & 3;
    const int qt   = gridDim.x - 1 - blockIdx.x;     // heavy tiles first
    const int h    = blockIdx.y;
    const int b    = blockIdx.z;
    const int q0   = qt * 64;
    const int nt   = qt + 1;                         // 64-key tiles
    const long long bS = (long long)b * S_;

    const int rl = lane & 7;
    const uint32_t q_lane  = (uint32_t)((w * 16 + ((lane >> 3) & 1) * 8 + rl) * 128);
    const int      q_cb    = lane >> 4;
    const uint32_t kv_lane = (uint32_t)((((lane >> 4) & 1) * 8 + rl) * 128);
    const int      kv_cb   = (lane >> 3) & 1;

    // prologue: groups [kv0][Q][kv1] — WAIT1 at t=0 covers kv0 AND Q.
    attn_issue_kv(qkvh, vth, sbase, 0, 0, h, b, tid);
#pragma unroll
    for (int it = 0; it < 4; it++) {
        int idx = tid + it * 128;          // 0..511
        int row = idx >> 3;                // 0..63
        int c   = idx & 7;
        uint32_t off = (uint32_t)(row * 8 + (c ^ (row & 7))) * 16;
        CP_ASYNC16(sbase + off,
                   qkvh + (bS + q0 + row) * 2048 + h * 64 + c * 8);
    }
    CP_COMMIT();
    if (nt > 1) attn_issue_kv(qkvh, vth, sbase, 1, 64, h, b, tid);

    float m0r = -INFINITY, m1r = -INFINITY;        // running max (stale ok)
    float mc0 = -INFINITY, mc1 = -INFINITY;        // candidates since update
    float ofr[8][4] = {};
    float lfr[4] = {};                             // l via MMA
    const uint32_t ONES2[2] = {0x3C003C00u, 0x3C003C00u};  // half2(1,1)

    const int r0g = q0 + w * 16 + gid;
    const int r1g = r0g + 8;
    const int rfirst = q0 + w * 16;

    for (int t = 0; t < nt; t++) {
        const int k0 = t * 64;
        if (t + 1 < nt) { CP_WAIT1(); } else { CP_WAIT0(); }
        __syncthreads();   // stage t ready AND stage (t-1)%3 readers done
        if (t + 2 < nt)
            attn_issue_kv(qkvh, vth, sbase, (t + 2) % 3, (t + 2) * 64, h, b, tid);

        const uint32_t ksb = sbase + ATT_Q_B + (uint32_t)(t % 3) * ATT_KV_B;
        const uint32_t vsb = ksb + 64 * 128;

        // S = Q K^T  (Q pre-scaled; 4 k16 steps over d=64)
        float sfr[8][4] = {};
#pragma unroll
        for (int ks = 0; ks < 4; ks++) {
            uint32_t a[4];
            LDSM_X4(a[0], a[1], a[2], a[3],
                    sbase + q_lane + ((uint32_t)((2 * ks + q_cb) ^ rl) << 4));
            uint32_t bf[8][2];
#pragma unroll
            for (int j = 0; j < 4; j++) {
                uint32_t bd = ksb + kv_lane + j * 2048 +
                              ((uint32_t)((2 * ks + kv_cb) ^ rl) << 4);
                LDSM_X4(bf[2 * j][0], bf[2 * j][1],
                        bf[2 * j + 1][0], bf[2 * j + 1][1], bd);
            }
#pragma unroll
            for (int nf = 0; nf < 8; nf++)
                mma_f16(sfr[nf], a, bf[nf]);
        }

        // causal mask (keys natural: c0,c1 -> 2tig, 2tig+1); gate on
        // the FIRST row of the warp strip (only diagonal tile masks).
        if (k0 + 63 > rfirst) {
#pragma unroll
            for (int nf = 0; nf < 8; nf++) {
                const int ca = k0 + nf * 8 + 2 * tig;
                if (ca     > r0g) sfr[nf][0] = -INFINITY;
                if (ca + 1 > r0g) sfr[nf][1] = -INFINITY;
                if (ca     > r1g) sfr[nf][2] = -INFINITY;
                if (ca + 1 > r1g) sfr[nf][3] = -INFINITY;
            }
        }

        // accumulate local max candidates (explicit tree, depth ~5)
        {
            float a0[8], a1[8];
#pragma unroll
            for (int nf = 0; nf < 8; nf++) {
                a0[nf] = fmaxf(sfr[nf][0], sfr[nf][1]);
                a1[nf] = fmaxf(sfr[nf][2], sfr[nf][3]);
            }
#pragma unroll
            for (int srd = 4; srd; srd >>= 1)
#pragma unroll
                for (int k = 0; k < srd; k++) {
                    a0[k] = fmaxf(a0[k], a0[k + srd]);
                    a1[k] = fmaxf(a1[k], a1[k + srd]);
                }
            mc0 = fmaxf(mc0, a0[0]);
            mc1 = fmaxf(mc1, a1[0]);
        }

        // lazy update: shfl-reduce + rescale every 4th tile
        if ((t & 3) == 0) {
#pragma unroll
            for (int off = 1; off <= 2; off <<= 1) {
                mc0 = fmaxf(mc0, __shfl_xor_sync(0xffffffffu, mc0, off));
                mc1 = fmaxf(mc1, __shfl_xor_sync(0xffffffffu, mc1, off));
            }
            const float mn0 = fmaxf(m0r, mc0);
            const float mn1 = fmaxf(m1r, mc1);
            const float cr0 = ex2f(m0r - mn0);   // t=0: ex2(-inf)=0, O/l are 0
            const float cr1 = ex2f(m1r - mn1);
            m0r = mn0; m1r = mn1;
            mc0 = -INFINITY; mc1 = -INFINITY;
#pragma unroll
            for (int nf = 0; nf < 8; nf++) {
                ofr[nf][0] *= cr0; ofr[nf][1] *= cr0;
                ofr[nf][2] *= cr1; ofr[nf][3] *= cr1;
            }
            lfr[0] *= cr0; lfr[1] *= cr0;
            lfr[2] *= cr1; lfr[3] *= cr1;
        }

        // P = 2^(s-m) via f16x2 ex2 -> A-frags; l via ones-MMA.
        // Stale m bounded (~2^6) -> safe in fp16; scale cancels in O/l.
        uint32_t pa[4][4];
#pragma unroll
        for (int j = 0; j < 4; j++) {
            pa[j][0] = h2ex2(pack_half2(sfr[2 * j][0] - m0r,
                                        sfr[2 * j][1] - m0r));
            pa[j][1] = h2ex2(pack_half2(sfr[2 * j][2] - m1r,
                                        sfr[2 * j][3] - m1r));
            pa[j][2] = h2ex2(pack_half2(sfr[2 * j + 1][0] - m0r,
                                        sfr[2 * j + 1][1] - m0r));
            pa[j][3] = h2ex2(pack_half2(sfr[2 * j + 1][2] - m1r,
                                        sfr[2 * j + 1][3] - m1r));
            mma_f16(lfr, pa[j], ONES2);
        }

        // O += P @ V  (V B-frags from Vt[d][key] tile)
#pragma unroll
        for (int j = 0; j < 4; j++) {
            uint32_t bf[8][2];
#pragma unroll
            for (int jb = 0; jb < 4; jb++) {
                uint32_t bd = vsb + kv_lane + jb * 2048 +
                              ((uint32_t)((2 * j + kv_cb) ^ rl) << 4);
                LDSM_X4(bf[2 * jb][0], bf[2 * jb][1],
                        bf[2 * jb + 1][0], bf[2 * jb + 1][1], bd);
            }
#pragma unroll
            for (int nf = 0; nf < 8; nf++)
                mma_f16(ofr[nf], pa[j], bf[nf]);
        }
    }

    // epilogue: lane's lfr[0]/lfr[2] IS l for its two rows (2^-m cancels)
    const float inv0 = 1.0f / lfr[0];
    const float inv1 = 1.0f / lfr[2];
#pragma unroll
    for (int nf = 0; nf < 8; nf++) {
        const int c = h * 64 + nf * 8 + 2 * tig;
        *(uint32_t*)&yh[(bS + r0g) * E_ + c] =
            pack_half2(ofr[nf][0] * inv0, ofr[nf][1] * inv0);
        *(uint32_t*)&yh[(bS + r1g) * E_ + c] =
            pack_half2(ofr[nf][2] * inv1, ofr[nf][3] * inv1);
    }
}

// ===========================================================================
extern "C" void kernel_launch(void* const* d_in, const int* in_sizes, int n_in,
                              void* d_out, int out_size) {
    const float* x      = (const float*)d_in[0];   // [B, S, E]
    const float* w_att  = (const float*)d_in[1];   // [E, 3E]
    const float* w_proj = (const float*)d_in[2];   // [E, E]
    float* out = (float*)d_out;                    // [B, S, E]

    __half *xh, *qkvh, *vth, *yh, *wTh;
    cudaGetSymbolAddress((void**)&xh, g_xh);
    cudaGetSymbolAddress((void**)&qkvh, g_qkvh);
    cudaGetSymbolAddress((void**)&vth, g_vth);
    cudaGetSymbolAddress((void**)&yh, g_yh);
    cudaGetSymbolAddress((void**)&wTh, g_wTh);
    __half* wattTh  = wTh;                          // [3E, E]
    __half* wprojTh = wTh + (long long)3 * E_ * E_; // [E, E]

    cudaFuncSetAttribute(gemm_h_kernel,
                         cudaFuncAttributeMaxDynamicSharedMemorySize,
                         GEMM_SMEM_BYTES);
    cudaFuncSetAttribute(attn_h_kernel,
                         cudaFuncAttributeMaxDynamicSharedMemorySize,
                         ATT_SMEM_BYTES);

    // 0) Convert x; transpose+convert both weights (single launch)
    cvt_kernel<<<2048, 256>>>(x, xh, (long long)M_ * E_ / 4);
    {
        dim3 g(128, E_ / 32);
        transpose2_kernel<<<g, 256>>>(w_att, wattTh, w_proj, wprojTh);
    }
    // 1) QKV projection: Q (scaled) + K -> qkvh; V -> vth transposed
    {
        dim3 grid(3 * E_ / 128, M_ / 128);
        gemm_h_kernel<<<grid, 256, GEMM_SMEM_BYTES>>>(
            xh, wattTh, nullptr, qkvh, vth, M_, 3 * E_, E_, 1);
    }
    // 2) Causal flash attention -> yh (fp16), 64-q-row CTAs
    {
        dim3 grid(S_ / 64, H_, B_);
        attn_h_kernel<<<grid, 128, ATT_SMEM_BYTES>>>(qkvh, vth, yh);
    }
    // 3) Output projection -> fp32 out
    {
        dim3 grid(E_ / 128, M_ / 128);
        gemm_h_kernel<<<grid, 256, GEMM_SMEM_BYTES>>>(
            yh, wprojTh, out, nullptr, nullptr, M_, E_, E_, 0);
    }
}